// round 1
// baseline (speedup 1.0000x reference)
#include <cuda_runtime.h>

// ---------------------------------------------------------------------------
// Problem constants
// ---------------------------------------------------------------------------
#define BATCH   4
#define SEQ     2048
#define DMODEL  1024
#define NHEAD   16
#define HDIM    64
#define MROWS   (BATCH * SEQ)          // 8192

// ---------------------------------------------------------------------------
// Scratch (device globals: allocation-free, graph-capture safe)
// ---------------------------------------------------------------------------
__device__ float g_q[MROWS * DMODEL];
__device__ float g_k[MROWS * DMODEL];
__device__ float g_v[MROWS * DMODEL];
__device__ float g_ctx[MROWS * DMODEL];

// ---------------------------------------------------------------------------
// GEMM body: C[M=8192, N=1024] = A[M, K=1024] @ W[K, N] + bias[N]
// 128x128 block tile, BK=16, 256 threads, 8x8 per thread.
// ---------------------------------------------------------------------------
__device__ __forceinline__ void gemm_body(const float* __restrict__ A,
                                          const float* __restrict__ W,
                                          const float* __restrict__ bias,
                                          float* __restrict__ C)
{
    constexpr int BM = 128, BN = 128, BK = 16;
    constexpr int K = DMODEL, N = DMODEL;

    __shared__ float As[BK][BM + 4];   // A tile, transposed ([k][m])
    __shared__ float Ws[BK][BN + 4];   // W tile, natural ([k][n])

    const int tid = threadIdx.x;
    const int tx  = tid & 15;          // 0..15 -> n block of 8
    const int ty  = tid >> 4;          // 0..15 -> m block of 8
    const int m0  = blockIdx.y * BM;
    const int n0  = blockIdx.x * BN;

    float acc[8][8];
#pragma unroll
    for (int i = 0; i < 8; i++)
#pragma unroll
        for (int j = 0; j < 8; j++) acc[i][j] = 0.f;

    for (int k0 = 0; k0 < K; k0 += BK) {
        // Load A tile (128x16) -> transposed into As. 512 float4, 2/thread.
#pragma unroll
        for (int i = 0; i < 2; i++) {
            int f  = tid + i * 256;          // 0..511
            int m  = f >> 2;                 // 0..127
            int kk = (f & 3) * 4;            // 0,4,8,12
            float4 v = *(const float4*)&A[(size_t)(m0 + m) * K + k0 + kk];
            As[kk + 0][m] = v.x;
            As[kk + 1][m] = v.y;
            As[kk + 2][m] = v.z;
            As[kk + 3][m] = v.w;
        }
        // Load W tile (16x128). 512 float4, 2/thread, direct copy.
#pragma unroll
        for (int i = 0; i < 2; i++) {
            int f  = tid + i * 256;
            int kk = f >> 5;                 // 0..15
            int n  = (f & 31) * 4;           // 0..124
            *(float4*)&Ws[kk][n] = *(const float4*)&W[(size_t)(k0 + kk) * N + n0 + n];
        }
        __syncthreads();

#pragma unroll
        for (int kk = 0; kk < BK; kk++) {
            float a[8], b[8];
            *(float4*)&a[0] = *(float4*)&As[kk][ty * 8];
            *(float4*)&a[4] = *(float4*)&As[kk][ty * 8 + 4];
            *(float4*)&b[0] = *(float4*)&Ws[kk][tx * 8];
            *(float4*)&b[4] = *(float4*)&Ws[kk][tx * 8 + 4];
#pragma unroll
            for (int i = 0; i < 8; i++)
#pragma unroll
                for (int j = 0; j < 8; j++)
                    acc[i][j] = fmaf(a[i], b[j], acc[i][j]);
        }
        __syncthreads();
    }

    // Epilogue: + bias, vectorized store.
#pragma unroll
    for (int i = 0; i < 8; i++) {
        int m = m0 + ty * 8 + i;
#pragma unroll
        for (int j = 0; j < 8; j += 4) {
            int n = n0 + tx * 8 + j;
            float4 o;
            o.x = acc[i][j + 0] + bias[n + 0];
            o.y = acc[i][j + 1] + bias[n + 1];
            o.z = acc[i][j + 2] + bias[n + 2];
            o.w = acc[i][j + 3] + bias[n + 3];
            *(float4*)&C[(size_t)m * N + n] = o;
        }
    }
}

__global__ __launch_bounds__(256, 2) void qkv_kernel(
    const float* __restrict__ x,
    const float* __restrict__ wq, const float* __restrict__ bq,
    const float* __restrict__ wk, const float* __restrict__ bk,
    const float* __restrict__ wv, const float* __restrict__ bv)
{
    const float* W; const float* bias; float* C;
    if (blockIdx.z == 0)      { W = wq; bias = bq; C = g_q; }
    else if (blockIdx.z == 1) { W = wk; bias = bk; C = g_k; }
    else                      { W = wv; bias = bv; C = g_v; }
    gemm_body(x, W, bias, C);
}

__global__ __launch_bounds__(256, 2) void out_kernel(
    const float* __restrict__ wo, const float* __restrict__ bo,
    float* __restrict__ out)
{
    gemm_body(g_ctx, wo, bo, out);
}

// ---------------------------------------------------------------------------
// Causal flash attention, fp32.
// Block = 128 threads, q-tile 64 rows, k-tile 32 rows, Dh = 64.
// Thread (rg = tid/8, cg = tid%8):
//   scores s[i][j]: q rows rg*4+i (i<4), k cols cg*4+j (j<4)
//   output acc[i][j]: q rows rg*4+i, dv cols cg*8+j (j<8)
// Row-statistics reductions are __shfl_xor over the 8-lane cg group.
// Smem: Qt (d-major), Kt (d-major), Vs (k-major), Pt (k-major) = 44 KB.
// ---------------------------------------------------------------------------
__global__ __launch_bounds__(128) void attn_kernel()
{
    __shared__ float Qt[64][68];   // [d][q]
    __shared__ float Kt[64][36];   // [d][k]
    __shared__ float Vs[32][68];   // [k][dv]
    __shared__ float Pt[32][68];   // [k][q]

    const int b   = blockIdx.z;
    const int h   = blockIdx.y;
    const int qt  = blockIdx.x;
    const int tid = threadIdx.x;
    const int rg  = tid >> 3;      // 0..15
    const int cg  = tid & 7;       // 0..7
    const int q0  = qt * 64;

    const float* qptr = g_q + (size_t)b * SEQ * DMODEL + h * HDIM;
    const float* kptr = g_k + (size_t)b * SEQ * DMODEL + h * HDIM;
    const float* vptr = g_v + (size_t)b * SEQ * DMODEL + h * HDIM;

    // Load Q tile (64 x 64), pre-scaled by 1/sqrt(Dh), transposed to [d][q].
#pragma unroll
    for (int i = 0; i < 8; i++) {
        int f = tid + i * 128;               // 0..1023
        int r = f >> 4;                      // 0..63
        int d = (f & 15) * 4;
        float4 v = *(const float4*)&qptr[(size_t)(q0 + r) * DMODEL + d];
        Qt[d + 0][r] = v.x * 0.125f;
        Qt[d + 1][r] = v.y * 0.125f;
        Qt[d + 2][r] = v.z * 0.125f;
        Qt[d + 3][r] = v.w * 0.125f;
    }

    float m_[4], l_[4], acc[4][8];
#pragma unroll
    for (int i = 0; i < 4; i++) {
        m_[i] = -1e30f; l_[i] = 0.f;
#pragma unroll
        for (int j = 0; j < 8; j++) acc[i][j] = 0.f;
    }

    const int nkt = 2 * qt + 2;   // k tiles of 32 covering [0, q0+64)
    for (int kt = 0; kt < nkt; kt++) {
        const int k0 = kt * 32;
        __syncthreads();   // previous iteration's Pt/Vs readers done

        // Load K tile (32x64) transposed -> Kt[d][k]; V tile direct -> Vs[k][d].
#pragma unroll
        for (int i = 0; i < 4; i++) {
            int f = tid + i * 128;           // 0..511
            int r = f >> 4;                  // 0..31
            int d = (f & 15) * 4;
            float4 kv = *(const float4*)&kptr[(size_t)(k0 + r) * DMODEL + d];
            Kt[d + 0][r] = kv.x;
            Kt[d + 1][r] = kv.y;
            Kt[d + 2][r] = kv.z;
            Kt[d + 3][r] = kv.w;
            float4 vv = *(const float4*)&vptr[(size_t)(k0 + r) * DMODEL + d];
            *(float4*)&Vs[r][d] = vv;
        }
        __syncthreads();

        // S = Q @ K^T  (64x32 tile; 4x4 per thread)
        float s[4][4];
#pragma unroll
        for (int i = 0; i < 4; i++)
#pragma unroll
            for (int j = 0; j < 4; j++) s[i][j] = 0.f;

#pragma unroll 8
        for (int d = 0; d < 64; d++) {
            float4 qv = *(float4*)&Qt[d][rg * 4];
            float4 kv = *(float4*)&Kt[d][cg * 4];
            float qa[4] = {qv.x, qv.y, qv.z, qv.w};
            float ka[4] = {kv.x, kv.y, kv.z, kv.w};
#pragma unroll
            for (int i = 0; i < 4; i++)
#pragma unroll
                for (int j = 0; j < 4; j++)
                    s[i][j] = fmaf(qa[i], ka[j], s[i][j]);
        }

        // Causal mask (only the last two tiles can cross the diagonal)
        if (k0 + 31 > q0) {
#pragma unroll
            for (int i = 0; i < 4; i++)
#pragma unroll
                for (int j = 0; j < 4; j++)
                    if (k0 + cg * 4 + j > q0 + rg * 4 + i) s[i][j] = -1e30f;
        }

        // Online softmax update
#pragma unroll
        for (int i = 0; i < 4; i++) {
            float mrow = s[i][0];
#pragma unroll
            for (int j = 1; j < 4; j++) mrow = fmaxf(mrow, s[i][j]);
            mrow = fmaxf(mrow, __shfl_xor_sync(0xffffffffu, mrow, 1));
            mrow = fmaxf(mrow, __shfl_xor_sync(0xffffffffu, mrow, 2));
            mrow = fmaxf(mrow, __shfl_xor_sync(0xffffffffu, mrow, 4));

            float mnew = fmaxf(m_[i], mrow);
            float corr = __expf(m_[i] - mnew);
            float rsum = 0.f;
#pragma unroll
            for (int j = 0; j < 4; j++) {
                float p = __expf(s[i][j] - mnew);
                s[i][j] = p;
                rsum += p;
            }
            rsum += __shfl_xor_sync(0xffffffffu, rsum, 1);
            rsum += __shfl_xor_sync(0xffffffffu, rsum, 2);
            rsum += __shfl_xor_sync(0xffffffffu, rsum, 4);

            l_[i] = l_[i] * corr + rsum;
            m_[i] = mnew;
#pragma unroll
            for (int j = 0; j < 8; j++) acc[i][j] *= corr;
        }

        // Stage P transposed -> Pt[k][q]
#pragma unroll
        for (int j = 0; j < 4; j++)
#pragma unroll
            for (int i = 0; i < 4; i++)
                Pt[cg * 4 + j][rg * 4 + i] = s[i][j];
        __syncthreads();

        // acc += P @ V   (32-deep inner product)
#pragma unroll 4
        for (int k = 0; k < 32; k++) {
            float4 pv = *(float4*)&Pt[k][rg * 4];
            float4 v0 = *(float4*)&Vs[k][cg * 8];
            float4 v1 = *(float4*)&Vs[k][cg * 8 + 4];
            float pa[4] = {pv.x, pv.y, pv.z, pv.w};
            float va[8] = {v0.x, v0.y, v0.z, v0.w, v1.x, v1.y, v1.z, v1.w};
#pragma unroll
            for (int i = 0; i < 4; i++)
#pragma unroll
                for (int j = 0; j < 8; j++)
                    acc[i][j] = fmaf(pa[i], va[j], acc[i][j]);
        }
    }

    // Normalize and write ctx in [B, S, D] layout
    float* cptr = g_ctx + (size_t)b * SEQ * DMODEL + h * HDIM;
#pragma unroll
    for (int i = 0; i < 4; i++) {
        float rinv = 1.f / l_[i];
        int r = q0 + rg * 4 + i;
        float4 o0, o1;
        o0.x = acc[i][0] * rinv; o0.y = acc[i][1] * rinv;
        o0.z = acc[i][2] * rinv; o0.w = acc[i][3] * rinv;
        o1.x = acc[i][4] * rinv; o1.y = acc[i][5] * rinv;
        o1.z = acc[i][6] * rinv; o1.w = acc[i][7] * rinv;
        *(float4*)&cptr[(size_t)r * DMODEL + cg * 8]     = o0;
        *(float4*)&cptr[(size_t)r * DMODEL + cg * 8 + 4] = o1;
    }
}

// ---------------------------------------------------------------------------
// Launch
// ---------------------------------------------------------------------------
extern "C" void kernel_launch(void* const* d_in, const int* in_sizes, int n_in,
                              void* d_out, int out_size)
{
    const float* x  = (const float*)d_in[0];
    const float* wq = (const float*)d_in[1];
    const float* bq = (const float*)d_in[2];
    const float* wk = (const float*)d_in[3];
    const float* bk = (const float*)d_in[4];
    const float* wv = (const float*)d_in[5];
    const float* bv = (const float*)d_in[6];
    const float* wo = (const float*)d_in[7];
    const float* bo = (const float*)d_in[8];
    float* out = (float*)d_out;

    (void)in_sizes; (void)n_in; (void)out_size;

    // Q/K/V projections: grid.z selects which of the three GEMMs.
    qkv_kernel<<<dim3(DMODEL / 128, MROWS / 128, 3), 256>>>(x, wq, bq, wk, bk, wv, bv);

    // Causal flash attention per (q-tile, head, batch).
    attn_kernel<<<dim3(SEQ / 64, NHEAD, BATCH), 128>>>();

    // Output projection.
    out_kernel<<<dim3(DMODEL / 128, MROWS / 128), 256>>>(wo, bo, out);
}

// round 4
// speedup vs baseline: 1.4447x; 1.4447x over previous
#include <cuda_runtime.h>
#include <cuda_bf16.h>
#include <cstdint>

// ---------------------------------------------------------------------------
// Problem constants
// ---------------------------------------------------------------------------
#define BATCH   4
#define SEQ     2048
#define DMODEL  1024
#define NHEAD   16
#define HDIM    64
#define MROWS   (BATCH * SEQ)          // 8192
#define KEXP    (3 * DMODEL)           // 3072: [hi | hi | lo] x [hi | lo | hi]
#define NCHUNK  (KEXP / 64)            // 48 K-chunks of 64

// ---------------------------------------------------------------------------
// Scratch (device globals: allocation-free, graph-capture safe)
// ---------------------------------------------------------------------------
__device__ float g_q[MROWS * DMODEL];
__device__ float g_k[MROWS * DMODEL];
__device__ float g_v[MROWS * DMODEL];
__device__ float g_ctx[MROWS * DMODEL];
__device__ __nv_bfloat16 g_ax[(size_t)MROWS * KEXP];      // x split      [M, 3K]
__device__ __nv_bfloat16 g_actx[(size_t)MROWS * KEXP];    // ctx split    [M, 3K]
__device__ __nv_bfloat16 g_bw[(size_t)4 * DMODEL * KEXP]; // weights^T    [4][N, 3K]

// ---------------------------------------------------------------------------
// PTX helpers — ONLY arch-agnostic instructions (sm_80-class): the harness
// compiles via .target sm_103 (no 'a'), so tcgen05/cta_group are unavailable.
// ---------------------------------------------------------------------------
__device__ __forceinline__ uint32_t smem_u32(const void* p) {
    uint32_t a;
    asm("{ .reg .u64 t; cvta.to.shared.u64 t, %1; cvt.u32.u64 %0, t; }" : "=r"(a) : "l"(p));
    return a;
}
__device__ __forceinline__ void cp_async16(uint32_t dst, const void* src) {
    size_t g = __cvta_generic_to_global(src);
    asm volatile("cp.async.cg.shared.global [%0], [%1], 16;" :: "r"(dst), "l"(g) : "memory");
}
__device__ __forceinline__ void cp_commit() {
    asm volatile("cp.async.commit_group;" ::: "memory");
}
template <int N>
__device__ __forceinline__ void cp_wait() {
    asm volatile("cp.async.wait_group %0;" :: "n"(N) : "memory");
}
__device__ __forceinline__ uint32_t swz(uint32_t b) {   // Swizzle<3,4,3> on 128B rows
    return b ^ ((b >> 3) & 0x70);
}

// ---------------------------------------------------------------------------
// Split conversion: fp32 -> [hi | hi | lo] bf16, K-expanded rows
// ---------------------------------------------------------------------------
__device__ __forceinline__ void split2(float x, __nv_bfloat16& h, __nv_bfloat16& l) {
    h = __float2bfloat16(x);
    l = __float2bfloat16(x - __bfloat162float(h));
}

// which==0: in -> g_ax ; which==1: g_ctx -> g_actx (g_ctx resolved on DEVICE —
// passing a __device__ symbol as a host-side kernel arg was the round-3 bug).
__global__ void split_kernel(const float* __restrict__ in, int which)
{
    const float* src   = which ? (const float*)g_ctx : in;
    __nv_bfloat16* out = which ? g_actx : g_ax;
    int idx = blockIdx.x * 256 + threadIdx.x;        // one float4 per thread
    int m   = idx >> 8;                              // 256 float4 per row
    int k4  = (idx & 255) * 4;
    float4 v = *(const float4*)&src[(size_t)m * DMODEL + k4];
    __nv_bfloat16 h[4], l[4];
    split2(v.x, h[0], l[0]); split2(v.y, h[1], l[1]);
    split2(v.z, h[2], l[2]); split2(v.w, h[3], l[3]);
    size_t ro = (size_t)m * KEXP;
    uint2 hp, lp;
    hp.x = ((uint32_t)*(uint16_t*)&h[1] << 16) | *(uint16_t*)&h[0];
    hp.y = ((uint32_t)*(uint16_t*)&h[3] << 16) | *(uint16_t*)&h[2];
    lp.x = ((uint32_t)*(uint16_t*)&l[1] << 16) | *(uint16_t*)&l[0];
    lp.y = ((uint32_t)*(uint16_t*)&l[3] << 16) | *(uint16_t*)&l[2];
    *(uint2*)&out[ro + k4]              = hp;   // seg0: hi
    *(uint2*)&out[ro + DMODEL + k4]     = hp;   // seg1: hi
    *(uint2*)&out[ro + 2 * DMODEL + k4] = lp;   // seg2: lo
}

// Weight split + transpose: W[K,N] fp32 -> out[N, 3K] bf16 = [hi | lo | hi]
__global__ void wsplit_kernel(const float* __restrict__ wq, const float* __restrict__ wk,
                              const float* __restrict__ wv, const float* __restrict__ wo)
{
    const float* W;
    switch (blockIdx.z) {
        case 0: W = wq; break; case 1: W = wk; break;
        case 2: W = wv; break; default: W = wo; break;
    }
    __nv_bfloat16* out = g_bw + (size_t)blockIdx.z * DMODEL * KEXP;

    __shared__ float t[32][33];
    int k0 = blockIdx.x * 32, n0 = blockIdx.y * 32;
    int tx = threadIdx.x & 31, ty = threadIdx.x >> 5;   // 256 threads: 32x8
#pragma unroll
    for (int i = 0; i < 4; i++)
        t[ty + i * 8][tx] = W[(size_t)(k0 + ty + i * 8) * DMODEL + n0 + tx];
    __syncthreads();
#pragma unroll
    for (int i = 0; i < 4; i++) {
        int nl = ty + i * 8;
        float v = t[tx][nl];
        __nv_bfloat16 h, l;
        split2(v, h, l);
        size_t ro = (size_t)(n0 + nl) * KEXP + k0 + tx;
        out[ro]              = h;   // seg0: hi
        out[ro + DMODEL]     = l;   // seg1: lo
        out[ro + 2 * DMODEL] = h;   // seg2: hi
    }
}

// ---------------------------------------------------------------------------
// mma.sync bf16 GEMM: C[M=8192, N=1024] = A'[M,3072] @ B'[N,3072]^T + bias
// 128x128 CTA tile, BK=64, 3-stage cp.async pipeline, 8 warps (2M x 4N),
// warp tile 64x32, m16n8k16 fragments via ldmatrix from swizzled smem.
// ---------------------------------------------------------------------------
#define STAGES 3
#define CHUNK_BYTES 32768                 // A tile 16KB + B tile 16KB
#define GEMM_SMEM (STAGES * CHUNK_BYTES)  // 96KB

__device__ __forceinline__ void gemm_mma_body(const __nv_bfloat16* __restrict__ A,
                                              const __nv_bfloat16* __restrict__ B,
                                              const float* __restrict__ bias,
                                              float* __restrict__ C)
{
    extern __shared__ char smem[];
    const uint32_t sbase = smem_u32(smem);
    const int tid  = threadIdx.x;
    const int lane = tid & 31;
    const int w    = tid >> 5;
    const int wm   = w & 1;               // 0..1  (M)
    const int wn   = w >> 1;              // 0..3  (N)
    const int m0   = blockIdx.y * 128;
    const int n0   = blockIdx.x * 128;

    const __nv_bfloat16* Abase = A + (size_t)m0 * KEXP;
    const __nv_bfloat16* Bbase = B + (size_t)n0 * KEXP;

    // cp.async thread mapping: per tile 1024x16B; thread covers rows r0+32i, unit u.
    const int r0 = tid >> 3;
    const int u  = tid & 7;

    auto load_chunk = [&](int c) {
        uint32_t so = sbase + (uint32_t)(c % STAGES) * CHUNK_BYTES;
        const __nv_bfloat16* as = Abase + (size_t)r0 * KEXP + c * 64 + u * 8;
        const __nv_bfloat16* bs = Bbase + (size_t)r0 * KEXP + c * 64 + u * 8;
#pragma unroll
        for (int i = 0; i < 4; i++) {
            uint32_t d = swz((uint32_t)(i * 32 + r0) * 128 + u * 16);
            cp_async16(so + d,         as + (size_t)i * 32 * KEXP);
            cp_async16(so + 16384 + d, bs + (size_t)i * 32 * KEXP);
        }
        cp_commit();
    };

    float acc[4][4][4];
#pragma unroll
    for (int mi = 0; mi < 4; mi++)
#pragma unroll
        for (int ni = 0; ni < 4; ni++)
#pragma unroll
            for (int r = 0; r < 4; r++) acc[mi][ni][r] = 0.f;

    load_chunk(0);
    load_chunk(1);

    for (int c = 0; c < NCHUNK; c++) {
        cp_wait<1>();            // chunk c resident
        __syncthreads();         // all warps done with buffer (c-1)%STAGES
        if (c + 2 < NCHUNK) load_chunk(c + 2);

        uint32_t sa = sbase + (uint32_t)(c % STAGES) * CHUNK_BYTES;
        uint32_t sb = sa + 16384;

#pragma unroll
        for (int ks = 0; ks < 4; ks++) {   // four k16 slices within BK=64
            uint32_t a[4][4], b[4][2];
#pragma unroll
            for (int mi = 0; mi < 4; mi++) {
                int r = wm * 64 + mi * 16 + (lane & 15);
                uint32_t addr = sa + swz((uint32_t)r * 128 + ks * 32 + (lane >> 4) * 16);
                asm volatile("ldmatrix.sync.aligned.m8n8.x4.shared.b16 {%0,%1,%2,%3}, [%4];"
                             : "=r"(a[mi][0]), "=r"(a[mi][1]), "=r"(a[mi][2]), "=r"(a[mi][3])
                             : "r"(addr));
            }
#pragma unroll
            for (int nj = 0; nj < 2; nj++) {
                int n = wn * 32 + nj * 16 + (lane >> 4) * 8 + (lane & 7);
                uint32_t addr = sb + swz((uint32_t)n * 128 + ks * 32 + ((lane >> 3) & 1) * 16);
                asm volatile("ldmatrix.sync.aligned.m8n8.x4.shared.b16 {%0,%1,%2,%3}, [%4];"
                             : "=r"(b[nj * 2][0]), "=r"(b[nj * 2][1]),
                               "=r"(b[nj * 2 + 1][0]), "=r"(b[nj * 2 + 1][1])
                             : "r"(addr));
            }
#pragma unroll
            for (int mi = 0; mi < 4; mi++)
#pragma unroll
                for (int ni = 0; ni < 4; ni++)
                    asm volatile(
                        "mma.sync.aligned.m16n8k16.row.col.f32.bf16.bf16.f32 "
                        "{%0,%1,%2,%3}, {%4,%5,%6,%7}, {%8,%9}, {%0,%1,%2,%3};"
                        : "+f"(acc[mi][ni][0]), "+f"(acc[mi][ni][1]),
                          "+f"(acc[mi][ni][2]), "+f"(acc[mi][ni][3])
                        : "r"(a[mi][0]), "r"(a[mi][1]), "r"(a[mi][2]), "r"(a[mi][3]),
                          "r"(b[ni][0]), "r"(b[ni][1]));
        }
    }

    // Epilogue: regs -> global, + bias. c0,c1 = row g cols 2t,2t+1; c2,c3 = row g+8.
    const int mrow = m0 + wm * 64 + (lane >> 2);
    const int ncol = n0 + wn * 32 + (lane & 3) * 2;
#pragma unroll
    for (int mi = 0; mi < 4; mi++) {
        int r = mrow + mi * 16;
#pragma unroll
        for (int ni = 0; ni < 4; ni++) {
            int cc = ncol + ni * 8;
            float b0 = bias[cc], b1 = bias[cc + 1];
            float2 o0 = make_float2(acc[mi][ni][0] + b0, acc[mi][ni][1] + b1);
            float2 o1 = make_float2(acc[mi][ni][2] + b0, acc[mi][ni][3] + b1);
            *(float2*)&C[(size_t)r * DMODEL + cc]       = o0;
            *(float2*)&C[(size_t)(r + 8) * DMODEL + cc] = o1;
        }
    }
}

__global__ __launch_bounds__(256, 1) void qkv_tc_kernel(
    const float* __restrict__ bq, const float* __restrict__ bk, const float* __restrict__ bv)
{
    const __nv_bfloat16* B; const float* bias; float* C;
    if (blockIdx.z == 0)      { B = g_bw;                             bias = bq; C = g_q; }
    else if (blockIdx.z == 1) { B = g_bw + (size_t)DMODEL * KEXP;     bias = bk; C = g_k; }
    else                      { B = g_bw + (size_t)2 * DMODEL * KEXP; bias = bv; C = g_v; }
    gemm_mma_body(g_ax, B, bias, C);
}

__global__ __launch_bounds__(256, 1) void out_tc_kernel(
    const float* __restrict__ bo, float* __restrict__ out)
{
    gemm_mma_body(g_actx, g_bw + (size_t)3 * DMODEL * KEXP, bo, out);
}

// ---------------------------------------------------------------------------
// Causal flash attention, fp32 SIMT (at FMA roofline; unchanged)
// ---------------------------------------------------------------------------
__global__ __launch_bounds__(128) void attn_kernel()
{
    __shared__ float Qt[64][68];   // [d][q]
    __shared__ float Kt[64][36];   // [d][k]
    __shared__ float Vs[32][68];   // [k][dv]
    __shared__ float Pt[32][68];   // [k][q]

    const int b   = blockIdx.z;
    const int h   = blockIdx.y;
    const int qt  = blockIdx.x;
    const int tid = threadIdx.x;
    const int rg  = tid >> 3;      // 0..15
    const int cg  = tid & 7;       // 0..7
    const int q0  = qt * 64;

    const float* qptr = g_q + (size_t)b * SEQ * DMODEL + h * HDIM;
    const float* kptr = g_k + (size_t)b * SEQ * DMODEL + h * HDIM;
    const float* vptr = g_v + (size_t)b * SEQ * DMODEL + h * HDIM;

#pragma unroll
    for (int i = 0; i < 8; i++) {
        int f = tid + i * 128;
        int r = f >> 4;
        int d = (f & 15) * 4;
        float4 v = *(const float4*)&qptr[(size_t)(q0 + r) * DMODEL + d];
        Qt[d + 0][r] = v.x * 0.125f;
        Qt[d + 1][r] = v.y * 0.125f;
        Qt[d + 2][r] = v.z * 0.125f;
        Qt[d + 3][r] = v.w * 0.125f;
    }

    float m_[4], l_[4], acc[4][8];
#pragma unroll
    for (int i = 0; i < 4; i++) {
        m_[i] = -1e30f; l_[i] = 0.f;
#pragma unroll
        for (int j = 0; j < 8; j++) acc[i][j] = 0.f;
    }

    const int nkt = 2 * qt + 2;
    for (int kt = 0; kt < nkt; kt++) {
        const int k0 = kt * 32;
        __syncthreads();

#pragma unroll
        for (int i = 0; i < 4; i++) {
            int f = tid + i * 128;
            int r = f >> 4;
            int d = (f & 15) * 4;
            float4 kv = *(const float4*)&kptr[(size_t)(k0 + r) * DMODEL + d];
            Kt[d + 0][r] = kv.x;
            Kt[d + 1][r] = kv.y;
            Kt[d + 2][r] = kv.z;
            Kt[d + 3][r] = kv.w;
            float4 vv = *(const float4*)&vptr[(size_t)(k0 + r) * DMODEL + d];
            *(float4*)&Vs[r][d] = vv;
        }
        __syncthreads();

        float s[4][4];
#pragma unroll
        for (int i = 0; i < 4; i++)
#pragma unroll
            for (int j = 0; j < 4; j++) s[i][j] = 0.f;

#pragma unroll 8
        for (int d = 0; d < 64; d++) {
            float4 qv = *(float4*)&Qt[d][rg * 4];
            float4 kv = *(float4*)&Kt[d][cg * 4];
            float qa[4] = {qv.x, qv.y, qv.z, qv.w};
            float ka[4] = {kv.x, kv.y, kv.z, kv.w};
#pragma unroll
            for (int i = 0; i < 4; i++)
#pragma unroll
                for (int j = 0; j < 4; j++)
                    s[i][j] = fmaf(qa[i], ka[j], s[i][j]);
        }

        if (k0 + 31 > q0) {
#pragma unroll
            for (int i = 0; i < 4; i++)
#pragma unroll
                for (int j = 0; j < 4; j++)
                    if (k0 + cg * 4 + j > q0 + rg * 4 + i) s[i][j] = -1e30f;
        }

#pragma unroll
        for (int i = 0; i < 4; i++) {
            float mrow = s[i][0];
#pragma unroll
            for (int j = 1; j < 4; j++) mrow = fmaxf(mrow, s[i][j]);
            mrow = fmaxf(mrow, __shfl_xor_sync(0xffffffffu, mrow, 1));
            mrow = fmaxf(mrow, __shfl_xor_sync(0xffffffffu, mrow, 2));
            mrow = fmaxf(mrow, __shfl_xor_sync(0xffffffffu, mrow, 4));

            float mnew = fmaxf(m_[i], mrow);
            float corr = __expf(m_[i] - mnew);
            float rsum = 0.f;
#pragma unroll
            for (int j = 0; j < 4; j++) {
                float p = __expf(s[i][j] - mnew);
                s[i][j] = p;
                rsum += p;
            }
            rsum += __shfl_xor_sync(0xffffffffu, rsum, 1);
            rsum += __shfl_xor_sync(0xffffffffu, rsum, 2);
            rsum += __shfl_xor_sync(0xffffffffu, rsum, 4);

            l_[i] = l_[i] * corr + rsum;
            m_[i] = mnew;
#pragma unroll
            for (int j = 0; j < 8; j++) acc[i][j] *= corr;
        }

#pragma unroll
        for (int j = 0; j < 4; j++)
#pragma unroll
            for (int i = 0; i < 4; i++)
                Pt[cg * 4 + j][rg * 4 + i] = s[i][j];
        __syncthreads();

#pragma unroll 4
        for (int k = 0; k < 32; k++) {
            float4 pv = *(float4*)&Pt[k][rg * 4];
            float4 v0 = *(float4*)&Vs[k][cg * 8];
            float4 v1 = *(float4*)&Vs[k][cg * 8 + 4];
            float pa[4] = {pv.x, pv.y, pv.z, pv.w};
            float va[8] = {v0.x, v0.y, v0.z, v0.w, v1.x, v1.y, v1.z, v1.w};
#pragma unroll
            for (int i = 0; i < 4; i++)
#pragma unroll
                for (int j = 0; j < 8; j++)
                    acc[i][j] = fmaf(pa[i], va[j], acc[i][j]);
        }
    }

    float* cptr = g_ctx + (size_t)b * SEQ * DMODEL + h * HDIM;
#pragma unroll
    for (int i = 0; i < 4; i++) {
        float rinv = 1.f / l_[i];
        int r = q0 + rg * 4 + i;
        float4 o0, o1;
        o0.x = acc[i][0] * rinv; o0.y = acc[i][1] * rinv;
        o0.z = acc[i][2] * rinv; o0.w = acc[i][3] * rinv;
        o1.x = acc[i][4] * rinv; o1.y = acc[i][5] * rinv;
        o1.z = acc[i][6] * rinv; o1.w = acc[i][7] * rinv;
        *(float4*)&cptr[(size_t)r * DMODEL + cg * 8]     = o0;
        *(float4*)&cptr[(size_t)r * DMODEL + cg * 8 + 4] = o1;
    }
}

// ---------------------------------------------------------------------------
// Launch
// ---------------------------------------------------------------------------
extern "C" void kernel_launch(void* const* d_in, const int* in_sizes, int n_in,
                              void* d_out, int out_size)
{
    const float* x  = (const float*)d_in[0];
    const float* wq = (const float*)d_in[1];
    const float* bq = (const float*)d_in[2];
    const float* wk = (const float*)d_in[3];
    const float* bk = (const float*)d_in[4];
    const float* wv = (const float*)d_in[5];
    const float* bv = (const float*)d_in[6];
    const float* wo = (const float*)d_in[7];
    const float* bo = (const float*)d_in[8];
    float* out = (float*)d_out;
    (void)in_sizes; (void)n_in; (void)out_size;

    cudaFuncSetAttribute(qkv_tc_kernel, cudaFuncAttributeMaxDynamicSharedMemorySize, GEMM_SMEM);
    cudaFuncSetAttribute(out_tc_kernel, cudaFuncAttributeMaxDynamicSharedMemorySize, GEMM_SMEM);

    // Weight transpose + bf16 hi/lo split.
    wsplit_kernel<<<dim3(32, 32, 4), 256>>>(wq, wk, wv, wo);
    // x split.
    split_kernel<<<MROWS * (DMODEL / 4) / 256, 256>>>(x, 0);
    // QKV projections on tensor cores (mma.sync path).
    qkv_tc_kernel<<<dim3(DMODEL / 128, MROWS / 128, 3), 256, GEMM_SMEM>>>(bq, bk, bv);
    // Causal flash attention (fp32 SIMT).
    attn_kernel<<<dim3(SEQ / 64, NHEAD, BATCH), 128>>>();
    // ctx split (reads g_ctx on device; 'in' unused for which=1).
    split_kernel<<<MROWS * (DMODEL / 4) / 256, 256>>>(x, 1);
    // Output projection on tensor cores.
    out_tc_kernel<<<dim3(DMODEL / 128, MROWS / 128), 256, GEMM_SMEM>>>(bo, out);
}

// round 5
// speedup vs baseline: 2.7382x; 1.8953x over previous
#include <cuda_runtime.h>
#include <cuda_bf16.h>
#include <cstdint>

// ---------------------------------------------------------------------------
// Problem constants
// ---------------------------------------------------------------------------
#define BATCH   4
#define SEQ     2048
#define DMODEL  1024
#define NHEAD   16
#define HDIM    64
#define MROWS   (BATCH * SEQ)          // 8192
#define KEXP    (3 * DMODEL)           // 3072: [hi | hi | lo] x [hi | lo | hi]
#define NCHUNK  (KEXP / 64)            // 48 K-chunks of 64
#define QSCALE  0.18033688011112042f   // log2(e) / sqrt(HDIM)

// ---------------------------------------------------------------------------
// Scratch (device globals: allocation-free, graph-capture safe)
// ---------------------------------------------------------------------------
__device__ __nv_bfloat16 g_qh[MROWS * DMODEL];            // [b,h,s,d] Q hi (pre-scaled)
__device__ __nv_bfloat16 g_ql[MROWS * DMODEL];            // Q lo
__device__ __nv_bfloat16 g_kh[MROWS * DMODEL];            // K hi
__device__ __nv_bfloat16 g_kl[MROWS * DMODEL];            // K lo
__device__ __nv_bfloat16 g_vh[MROWS * DMODEL];            // V hi
__device__ __nv_bfloat16 g_vl[MROWS * DMODEL];            // V lo
__device__ __nv_bfloat16 g_ax[(size_t)MROWS * KEXP];      // x split      [M, 3K]
__device__ __nv_bfloat16 g_actx[(size_t)MROWS * KEXP];    // ctx split    [M, 3K]
__device__ __nv_bfloat16 g_bw[(size_t)4 * DMODEL * KEXP]; // weights^T    [4][N, 3K]

// ---------------------------------------------------------------------------
// PTX helpers — arch-agnostic (sm_80-class) only: harness targets sm_103.
// ---------------------------------------------------------------------------
__device__ __forceinline__ uint32_t smem_u32(const void* p) {
    uint32_t a;
    asm("{ .reg .u64 t; cvta.to.shared.u64 t, %1; cvt.u32.u64 %0, t; }" : "=r"(a) : "l"(p));
    return a;
}
__device__ __forceinline__ void cp_async16(uint32_t dst, const void* src) {
    size_t g = __cvta_generic_to_global(src);
    asm volatile("cp.async.cg.shared.global [%0], [%1], 16;" :: "r"(dst), "l"(g) : "memory");
}
__device__ __forceinline__ void cp_commit() {
    asm volatile("cp.async.commit_group;" ::: "memory");
}
template <int N>
__device__ __forceinline__ void cp_wait() {
    asm volatile("cp.async.wait_group %0;" :: "n"(N) : "memory");
}
__device__ __forceinline__ uint32_t swz(uint32_t b) {   // Swizzle<3,4,3> on 128B rows
    return b ^ ((b >> 3) & 0x70);
}
__device__ __forceinline__ float ex2(float x) {
    float y;
    asm("ex2.approx.ftz.f32 %0, %1;" : "=f"(y) : "f"(x));
    return y;
}
__device__ __forceinline__ uint32_t pack2(__nv_bfloat16 a, __nv_bfloat16 b) {
    return ((uint32_t)__bfloat16_as_ushort(b) << 16) | __bfloat16_as_ushort(a);
}
// a (low/even) , b (high/odd)  ->  hi-pair, lo-pair
__device__ __forceinline__ void split_pack(float a, float b, uint32_t& hp, uint32_t& lp) {
    __nv_bfloat16 ah = __float2bfloat16(a);
    __nv_bfloat16 bh = __float2bfloat16(b);
    float al = a - __bfloat162float(ah);
    float bl = b - __bfloat162float(bh);
    hp = pack2(ah, bh);
    lp = pack2(__float2bfloat16(al), __float2bfloat16(bl));
}

#define MMA(acc, a, b0, b1)                                                          \
    asm volatile(                                                                    \
        "mma.sync.aligned.m16n8k16.row.col.f32.bf16.bf16.f32 "                       \
        "{%0,%1,%2,%3}, {%4,%5,%6,%7}, {%8,%9}, {%0,%1,%2,%3};"                      \
        : "+f"((acc)[0]), "+f"((acc)[1]), "+f"((acc)[2]), "+f"((acc)[3])             \
        : "r"((a)[0]), "r"((a)[1]), "r"((a)[2]), "r"((a)[3]), "r"(b0), "r"(b1))

#define LDSM4(r, addr)                                                               \
    asm volatile("ldmatrix.sync.aligned.m8n8.x4.shared.b16 {%0,%1,%2,%3}, [%4];"     \
                 : "=r"((r)[0]), "=r"((r)[1]), "=r"((r)[2]), "=r"((r)[3]) : "r"(addr))

#define LDSM4T(r, addr)                                                              \
    asm volatile("ldmatrix.sync.aligned.m8n8.x4.trans.shared.b16 {%0,%1,%2,%3}, [%4];" \
                 : "=r"((r)[0]), "=r"((r)[1]), "=r"((r)[2]), "=r"((r)[3]) : "r"(addr))

// ---------------------------------------------------------------------------
// Split conversions
// ---------------------------------------------------------------------------
__device__ __forceinline__ void split2(float x, __nv_bfloat16& h, __nv_bfloat16& l) {
    h = __float2bfloat16(x);
    l = __float2bfloat16(x - __bfloat162float(h));
}

__global__ void split_kernel(const float* __restrict__ in)   // x -> g_ax
{
    int idx = blockIdx.x * 256 + threadIdx.x;
    int m   = idx >> 8;
    int k4  = (idx & 255) * 4;
    float4 v = *(const float4*)&in[(size_t)m * DMODEL + k4];
    __nv_bfloat16 h[4], l[4];
    split2(v.x, h[0], l[0]); split2(v.y, h[1], l[1]);
    split2(v.z, h[2], l[2]); split2(v.w, h[3], l[3]);
    size_t ro = (size_t)m * KEXP;
    uint2 hp, lp;
    hp.x = pack2(h[0], h[1]); hp.y = pack2(h[2], h[3]);
    lp.x = pack2(l[0], l[1]); lp.y = pack2(l[2], l[3]);
    *(uint2*)&g_ax[ro + k4]              = hp;
    *(uint2*)&g_ax[ro + DMODEL + k4]     = hp;
    *(uint2*)&g_ax[ro + 2 * DMODEL + k4] = lp;
}

__global__ void wsplit_kernel(const float* __restrict__ wq, const float* __restrict__ wk,
                              const float* __restrict__ wv, const float* __restrict__ wo)
{
    const float* W;
    switch (blockIdx.z) {
        case 0: W = wq; break; case 1: W = wk; break;
        case 2: W = wv; break; default: W = wo; break;
    }
    __nv_bfloat16* out = g_bw + (size_t)blockIdx.z * DMODEL * KEXP;

    __shared__ float t[32][33];
    int k0 = blockIdx.x * 32, n0 = blockIdx.y * 32;
    int tx = threadIdx.x & 31, ty = threadIdx.x >> 5;
#pragma unroll
    for (int i = 0; i < 4; i++)
        t[ty + i * 8][tx] = W[(size_t)(k0 + ty + i * 8) * DMODEL + n0 + tx];
    __syncthreads();
#pragma unroll
    for (int i = 0; i < 4; i++) {
        int nl = ty + i * 8;
        float v = t[tx][nl];
        __nv_bfloat16 h, l;
        split2(v, h, l);
        size_t ro = (size_t)(n0 + nl) * KEXP + k0 + tx;
        out[ro]              = h;
        out[ro + DMODEL]     = l;
        out[ro + 2 * DMODEL] = h;
    }
}

// ---------------------------------------------------------------------------
// mma.sync bf16 GEMM, 128x128 CTA tile, BK=64, 3-stage cp.async pipeline.
// MODE 0: C = acc + bias (fp32 out). MODE 1: split bf16 out to Oh/Ol in
// head-major [b,h,s,d] layout, scaled.
// ---------------------------------------------------------------------------
#define STAGES 3
#define CHUNK_BYTES 32768
#define GEMM_SMEM (STAGES * CHUNK_BYTES)

template <int MODE>
__device__ __forceinline__ void gemm_mma_body(const __nv_bfloat16* __restrict__ A,
                                              const __nv_bfloat16* __restrict__ B,
                                              const float* __restrict__ bias,
                                              float* __restrict__ C,
                                              __nv_bfloat16* __restrict__ Oh,
                                              __nv_bfloat16* __restrict__ Ol,
                                              float scale)
{
    extern __shared__ char smem[];
    const uint32_t sbase = smem_u32(smem);
    const int tid  = threadIdx.x;
    const int lane = tid & 31;
    const int w    = tid >> 5;
    const int wm   = w & 1;
    const int wn   = w >> 1;
    const int m0   = blockIdx.y * 128;
    const int n0   = blockIdx.x * 128;

    const __nv_bfloat16* Abase = A + (size_t)m0 * KEXP;
    const __nv_bfloat16* Bbase = B + (size_t)n0 * KEXP;

    const int r0 = tid >> 3;
    const int u  = tid & 7;

    auto load_chunk = [&](int c) {
        uint32_t so = sbase + (uint32_t)(c % STAGES) * CHUNK_BYTES;
        const __nv_bfloat16* as = Abase + (size_t)r0 * KEXP + c * 64 + u * 8;
        const __nv_bfloat16* bs = Bbase + (size_t)r0 * KEXP + c * 64 + u * 8;
#pragma unroll
        for (int i = 0; i < 4; i++) {
            uint32_t d = swz((uint32_t)(i * 32 + r0) * 128 + u * 16);
            cp_async16(so + d,         as + (size_t)i * 32 * KEXP);
            cp_async16(so + 16384 + d, bs + (size_t)i * 32 * KEXP);
        }
        cp_commit();
    };

    float acc[4][4][4];
#pragma unroll
    for (int mi = 0; mi < 4; mi++)
#pragma unroll
        for (int ni = 0; ni < 4; ni++)
#pragma unroll
            for (int r = 0; r < 4; r++) acc[mi][ni][r] = 0.f;

    load_chunk(0);
    load_chunk(1);

    for (int c = 0; c < NCHUNK; c++) {
        cp_wait<1>();
        __syncthreads();
        if (c + 2 < NCHUNK) load_chunk(c + 2);

        uint32_t sa = sbase + (uint32_t)(c % STAGES) * CHUNK_BYTES;
        uint32_t sb = sa + 16384;

#pragma unroll
        for (int ks = 0; ks < 4; ks++) {
            uint32_t a[4][4], b[4][2];
#pragma unroll
            for (int mi = 0; mi < 4; mi++) {
                int r = wm * 64 + mi * 16 + (lane & 15);
                uint32_t addr = sa + swz((uint32_t)r * 128 + ks * 32 + (lane >> 4) * 16);
                LDSM4(a[mi], addr);
            }
#pragma unroll
            for (int nj = 0; nj < 2; nj++) {
                int n = wn * 32 + nj * 16 + (lane >> 4) * 8 + (lane & 7);
                uint32_t addr = sb + swz((uint32_t)n * 128 + ks * 32 + ((lane >> 3) & 1) * 16);
                asm volatile("ldmatrix.sync.aligned.m8n8.x4.shared.b16 {%0,%1,%2,%3}, [%4];"
                             : "=r"(b[nj * 2][0]), "=r"(b[nj * 2][1]),
                               "=r"(b[nj * 2 + 1][0]), "=r"(b[nj * 2 + 1][1])
                             : "r"(addr));
            }
#pragma unroll
            for (int mi = 0; mi < 4; mi++)
#pragma unroll
                for (int ni = 0; ni < 4; ni++)
                    MMA(acc[mi][ni], a[mi], b[ni][0], b[ni][1]);
        }
    }

    const int mrow = m0 + wm * 64 + (lane >> 2);
    const int ncol = n0 + wn * 32 + (lane & 3) * 2;
#pragma unroll
    for (int mi = 0; mi < 4; mi++) {
        int r = mrow + mi * 16;
#pragma unroll
        for (int ni = 0; ni < 4; ni++) {
            int cc = ncol + ni * 8;
            float b0 = bias[cc], b1 = bias[cc + 1];
            float v0 = acc[mi][ni][0] + b0, v1 = acc[mi][ni][1] + b1;
            float v2 = acc[mi][ni][2] + b0, v3 = acc[mi][ni][3] + b1;
            if (MODE == 0) {
                *(float2*)&C[(size_t)r * DMODEL + cc]       = make_float2(v0, v1);
                *(float2*)&C[(size_t)(r + 8) * DMODEL + cc] = make_float2(v2, v3);
            } else {
                v0 *= scale; v1 *= scale; v2 *= scale; v3 *= scale;
                int bb = r >> 11, hh = cc >> 6, dd = cc & 63;
                size_t off0 = (((size_t)bb * NHEAD + hh) * SEQ + (r & 2047)) * HDIM + dd;
                size_t off1 = off0 + 8 * HDIM;   // row r+8, same (b,h)
                uint32_t hp, lp;
                split_pack(v0, v1, hp, lp);
                *(uint32_t*)&Oh[off0] = hp;
                *(uint32_t*)&Ol[off0] = lp;
                split_pack(v2, v3, hp, lp);
                *(uint32_t*)&Oh[off1] = hp;
                *(uint32_t*)&Ol[off1] = lp;
            }
        }
    }
}

__global__ __launch_bounds__(256, 1) void qkv_tc_kernel(
    const float* __restrict__ bq, const float* __restrict__ bk, const float* __restrict__ bv)
{
    if (blockIdx.z == 0)
        gemm_mma_body<1>(g_ax, g_bw, bq, nullptr, g_qh, g_ql, QSCALE);
    else if (blockIdx.z == 1)
        gemm_mma_body<1>(g_ax, g_bw + (size_t)DMODEL * KEXP, bk, nullptr, g_kh, g_kl, 1.f);
    else
        gemm_mma_body<1>(g_ax, g_bw + (size_t)2 * DMODEL * KEXP, bv, nullptr, g_vh, g_vl, 1.f);
}

__global__ __launch_bounds__(256, 1) void out_tc_kernel(
    const float* __restrict__ bo, float* __restrict__ out)
{
    gemm_mma_body<0>(g_actx, g_bw + (size_t)3 * DMODEL * KEXP, bo, out, nullptr, nullptr, 1.f);
}

// ---------------------------------------------------------------------------
// Tensor-core causal flash attention.
// CTA: 256 thr (8 warps), q-tile 128 (16 rows/warp), k-tile 64, Dh=64.
// QK^T: 3-term bf16 split. P·V: 3-term bf16 split. exp2 domain softmax.
// Smem: Qh|Ql (32KB) + 2 x (Kh|Kl|Vh|Vl) (2x32KB) = 96KB.
// ---------------------------------------------------------------------------
#define ATT_SMEM 98304

__global__ __launch_bounds__(256) void attn_tc_kernel()
{
    extern __shared__ char smem[];
    const uint32_t sb = smem_u32(smem);
    const int tid  = threadIdx.x;
    const int lane = tid & 31;
    const int w    = tid >> 5;
    const int qt   = (int)(gridDim.x - 1 - blockIdx.x);   // heavy tiles first
    const int h    = blockIdx.y, b = blockIdx.z;
    const int q0   = qt * 128;
    const int nkt  = 2 * qt + 2;
    const size_t bh = ((size_t)b * NHEAD + h) * SEQ * HDIM;
    const __nv_bfloat16 *Qhp = g_qh + bh, *Qlp = g_ql + bh;
    const __nv_bfloat16 *Khp = g_kh + bh, *Klp = g_kl + bh;
    const __nv_bfloat16 *Vhp = g_vh + bh, *Vlp = g_vl + bh;

    const int u  = tid & 7;         // 16B unit within 128B row
    const int r8 = tid >> 3;        // 0..31

    // ---- stage Q (q0..q0+127, hi+lo)
#pragma unroll
    for (int i = 0; i < 4; i++) {
        int row = r8 + 32 * i;
        uint32_t d = swz((uint32_t)row * 128 + u * 16);
        cp_async16(sb + d,         Qhp + (size_t)(q0 + row) * HDIM + u * 8);
        cp_async16(sb + 16384 + d, Qlp + (size_t)(q0 + row) * HDIM + u * 8);
    }
    cp_commit();

    auto load_kv = [&](int kt) {
        uint32_t so = sb + 32768 + (uint32_t)(kt & 1) * 32768;
        int kbase = kt * 64;
#pragma unroll
        for (int i = 0; i < 2; i++) {
            int row = r8 + 32 * i;
            uint32_t d = swz((uint32_t)row * 128 + u * 16);
            size_t g = (size_t)(kbase + row) * HDIM + u * 8;
            cp_async16(so + d,         Khp + g);
            cp_async16(so + 8192 + d,  Klp + g);
            cp_async16(so + 16384 + d, Vhp + g);
            cp_async16(so + 24576 + d, Vlp + g);
        }
        cp_commit();
    };
    load_kv(0);
    cp_wait<0>();
    __syncthreads();

    // ---- resident Q fragments (4 k16 slices each for hi/lo)
    uint32_t qh[4][4], ql[4][4];
#pragma unroll
    for (int ks = 0; ks < 4; ks++) {
        uint32_t d = swz((uint32_t)(w * 16 + (lane & 15)) * 128 + ks * 32 + (lane >> 4) * 16);
        LDSM4(qh[ks], sb + d);
        LDSM4(ql[ks], sb + 16384 + d);
    }

    float ctx[8][4];
#pragma unroll
    for (int dt = 0; dt < 8; dt++)
#pragma unroll
        for (int r = 0; r < 4; r++) ctx[dt][r] = 0.f;
    float m0 = -1e30f, m1 = -1e30f, l0 = 0.f, l1 = 0.f;

    for (int kt = 0; kt < nkt; kt++) {
        cp_wait<0>();
        __syncthreads();
        if (kt + 1 < nkt) load_kv(kt + 1);
        const uint32_t sk = sb + 32768 + (uint32_t)(kt & 1) * 32768;

        // ---- S = Q K^T  (Qh Kh + Qh Kl + Ql Kh)
        float s[8][4];
#pragma unroll
        for (int nt = 0; nt < 8; nt++) {
            s[nt][0] = s[nt][1] = s[nt][2] = s[nt][3] = 0.f;
            uint32_t kh[4][2], kl[4][2];
#pragma unroll
            for (int hf = 0; hf < 2; hf++) {
                uint32_t d = swz((uint32_t)(nt * 8 + (lane & 7)) * 128 + hf * 64 + (lane >> 3) * 16);
                asm volatile("ldmatrix.sync.aligned.m8n8.x4.shared.b16 {%0,%1,%2,%3}, [%4];"
                             : "=r"(kh[2*hf][0]), "=r"(kh[2*hf][1]),
                               "=r"(kh[2*hf+1][0]), "=r"(kh[2*hf+1][1]) : "r"(sk + d));
                asm volatile("ldmatrix.sync.aligned.m8n8.x4.shared.b16 {%0,%1,%2,%3}, [%4];"
                             : "=r"(kl[2*hf][0]), "=r"(kl[2*hf][1]),
                               "=r"(kl[2*hf+1][0]), "=r"(kl[2*hf+1][1]) : "r"(sk + 8192 + d));
            }
#pragma unroll
            for (int ks = 0; ks < 4; ks++) {
                MMA(s[nt], qh[ks], kh[ks][0], kh[ks][1]);
                MMA(s[nt], qh[ks], kl[ks][0], kl[ks][1]);
                MMA(s[nt], ql[ks], kh[ks][0], kh[ks][1]);
            }
        }

        // ---- causal mask (only the last two k-tiles cross the diagonal)
        if (kt >= nkt - 2) {
            int qr = q0 + w * 16 + (lane >> 2);
#pragma unroll
            for (int nt = 0; nt < 8; nt++) {
                int kc = kt * 64 + nt * 8 + (lane & 3) * 2;
                if (kc     > qr)     s[nt][0] = -1e30f;
                if (kc + 1 > qr)     s[nt][1] = -1e30f;
                if (kc     > qr + 8) s[nt][2] = -1e30f;
                if (kc + 1 > qr + 8) s[nt][3] = -1e30f;
            }
        }

        // ---- online softmax (exp2 domain; Q pre-scaled by log2e/8)
        float mx0 = -1e30f, mx1 = -1e30f;
#pragma unroll
        for (int nt = 0; nt < 8; nt++) {
            mx0 = fmaxf(mx0, fmaxf(s[nt][0], s[nt][1]));
            mx1 = fmaxf(mx1, fmaxf(s[nt][2], s[nt][3]));
        }
        mx0 = fmaxf(mx0, __shfl_xor_sync(0xffffffffu, mx0, 1));
        mx0 = fmaxf(mx0, __shfl_xor_sync(0xffffffffu, mx0, 2));
        mx1 = fmaxf(mx1, __shfl_xor_sync(0xffffffffu, mx1, 1));
        mx1 = fmaxf(mx1, __shfl_xor_sync(0xffffffffu, mx1, 2));
        float mn0 = fmaxf(m0, mx0), mn1 = fmaxf(m1, mx1);
        float c0 = ex2(m0 - mn0), c1 = ex2(m1 - mn1);
        m0 = mn0; m1 = mn1;

        float sum0 = 0.f, sum1 = 0.f;
        uint32_t ph[4][4], pl[4][4];
#pragma unroll
        for (int j = 0; j < 4; j++) {
            float p00 = ex2(s[2*j][0] - mn0),   p01 = ex2(s[2*j][1] - mn0);
            float p02 = ex2(s[2*j][2] - mn1),   p03 = ex2(s[2*j][3] - mn1);
            float p10 = ex2(s[2*j+1][0] - mn0), p11 = ex2(s[2*j+1][1] - mn0);
            float p12 = ex2(s[2*j+1][2] - mn1), p13 = ex2(s[2*j+1][3] - mn1);
            sum0 += (p00 + p01) + (p10 + p11);
            sum1 += (p02 + p03) + (p12 + p13);
            split_pack(p00, p01, ph[j][0], pl[j][0]);
            split_pack(p02, p03, ph[j][1], pl[j][1]);
            split_pack(p10, p11, ph[j][2], pl[j][2]);
            split_pack(p12, p13, ph[j][3], pl[j][3]);
        }
        l0 = l0 * c0 + sum0;
        l1 = l1 * c1 + sum1;
#pragma unroll
        for (int dt = 0; dt < 8; dt++) {
            ctx[dt][0] *= c0; ctx[dt][1] *= c0;
            ctx[dt][2] *= c1; ctx[dt][3] *= c1;
        }

        // ---- ctx += P V  (Ph Vh + Ph Vl + Pl Vh)
        const uint32_t sv = sk + 16384;
#pragma unroll
        for (int j = 0; j < 4; j++) {
            uint32_t vf[8][2];
#pragma unroll
            for (int dp = 0; dp < 4; dp++) {
                uint32_t d = swz((uint32_t)(j * 16 + (lane & 15)) * 128 + dp * 32 + (lane >> 4) * 16);
                asm volatile("ldmatrix.sync.aligned.m8n8.x4.trans.shared.b16 {%0,%1,%2,%3}, [%4];"
                             : "=r"(vf[2*dp][0]), "=r"(vf[2*dp][1]),
                               "=r"(vf[2*dp+1][0]), "=r"(vf[2*dp+1][1]) : "r"(sv + d));
            }
#pragma unroll
            for (int dt = 0; dt < 8; dt++) {
                MMA(ctx[dt], ph[j], vf[dt][0], vf[dt][1]);
                MMA(ctx[dt], pl[j], vf[dt][0], vf[dt][1]);
            }
#pragma unroll
            for (int dp = 0; dp < 4; dp++) {
                uint32_t d = swz((uint32_t)(j * 16 + (lane & 15)) * 128 + dp * 32 + (lane >> 4) * 16);
                asm volatile("ldmatrix.sync.aligned.m8n8.x4.trans.shared.b16 {%0,%1,%2,%3}, [%4];"
                             : "=r"(vf[2*dp][0]), "=r"(vf[2*dp][1]),
                               "=r"(vf[2*dp+1][0]), "=r"(vf[2*dp+1][1]) : "r"(sv + 8192 + d));
            }
#pragma unroll
            for (int dt = 0; dt < 8; dt++)
                MMA(ctx[dt], ph[j], vf[dt][0], vf[dt][1]);
        }
    }

    // ---- finalize: row sums across the 4 lanes sharing a row, then write
    l0 += __shfl_xor_sync(0xffffffffu, l0, 1);
    l0 += __shfl_xor_sync(0xffffffffu, l0, 2);
    l1 += __shfl_xor_sync(0xffffffffu, l1, 1);
    l1 += __shfl_xor_sync(0xffffffffu, l1, 2);
    float rinv0 = 1.f / l0, rinv1 = 1.f / l1;

    int qr = q0 + w * 16 + (lane >> 2);
    size_t row0 = ((size_t)b * SEQ + qr) * KEXP;
    size_t row1 = ((size_t)b * SEQ + qr + 8) * KEXP;
    int cbase = h * HDIM + (lane & 3) * 2;
#pragma unroll
    for (int dt = 0; dt < 8; dt++) {
        int cc = cbase + dt * 8;
        uint32_t hp, lp;
        split_pack(ctx[dt][0] * rinv0, ctx[dt][1] * rinv0, hp, lp);
        *(uint32_t*)&g_actx[row0 + cc]              = hp;
        *(uint32_t*)&g_actx[row0 + DMODEL + cc]     = hp;
        *(uint32_t*)&g_actx[row0 + 2 * DMODEL + cc] = lp;
        split_pack(ctx[dt][2] * rinv1, ctx[dt][3] * rinv1, hp, lp);
        *(uint32_t*)&g_actx[row1 + cc]              = hp;
        *(uint32_t*)&g_actx[row1 + DMODEL + cc]     = hp;
        *(uint32_t*)&g_actx[row1 + 2 * DMODEL + cc] = lp;
    }
}

// ---------------------------------------------------------------------------
// Launch
// ---------------------------------------------------------------------------
extern "C" void kernel_launch(void* const* d_in, const int* in_sizes, int n_in,
                              void* d_out, int out_size)
{
    const float* x  = (const float*)d_in[0];
    const float* wq = (const float*)d_in[1];
    const float* bq = (const float*)d_in[2];
    const float* wk = (const float*)d_in[3];
    const float* bk = (const float*)d_in[4];
    const float* wv = (const float*)d_in[5];
    const float* bv = (const float*)d_in[6];
    const float* wo = (const float*)d_in[7];
    const float* bo = (const float*)d_in[8];
    float* out = (float*)d_out;
    (void)in_sizes; (void)n_in; (void)out_size;

    cudaFuncSetAttribute(qkv_tc_kernel, cudaFuncAttributeMaxDynamicSharedMemorySize, GEMM_SMEM);
    cudaFuncSetAttribute(out_tc_kernel, cudaFuncAttributeMaxDynamicSharedMemorySize, GEMM_SMEM);
    cudaFuncSetAttribute(attn_tc_kernel, cudaFuncAttributeMaxDynamicSharedMemorySize, ATT_SMEM);

    wsplit_kernel<<<dim3(32, 32, 4), 256>>>(wq, wk, wv, wo);
    split_kernel<<<MROWS * (DMODEL / 4) / 256, 256>>>(x);
    qkv_tc_kernel<<<dim3(DMODEL / 128, MROWS / 128, 3), 256, GEMM_SMEM>>>(bq, bk, bv);
    attn_tc_kernel<<<dim3(SEQ / 128, NHEAD, BATCH), 256, ATT_SMEM>>>();
    out_tc_kernel<<<dim3(DMODEL / 128, MROWS / 128), 256, GEMM_SMEM>>>(bo, out);
}

// round 6
// speedup vs baseline: 3.3543x; 1.2250x over previous
#include <cuda_runtime.h>
#include <cuda_bf16.h>
#include <cstdint>

// ---------------------------------------------------------------------------
// Problem constants
// ---------------------------------------------------------------------------
#define BATCH   4
#define SEQ     2048
#define DMODEL  1024
#define NHEAD   16
#define HDIM    64
#define MROWS   (BATCH * SEQ)          // 8192
#define KEXP    (3 * DMODEL)           // 3072: [hi | hi | lo] x [hi | lo | hi]
#define NCHUNK  (KEXP / 64)            // 48 K-chunks of 64
#define QSCALE  0.18033688011112042f   // log2(e) / sqrt(HDIM)

// ---------------------------------------------------------------------------
// Scratch (device globals: allocation-free, graph-capture safe)
// ---------------------------------------------------------------------------
__device__ __nv_bfloat16 g_qh[MROWS * DMODEL];            // [b,h,s,d] Q hi (pre-scaled)
__device__ __nv_bfloat16 g_ql[MROWS * DMODEL];            // Q lo
__device__ __nv_bfloat16 g_kh[MROWS * DMODEL];            // K hi
__device__ __nv_bfloat16 g_kl[MROWS * DMODEL];            // K lo
__device__ __nv_bfloat16 g_vh[MROWS * DMODEL];            // V hi
__device__ __nv_bfloat16 g_vl[MROWS * DMODEL];            // V lo
__device__ __nv_bfloat16 g_ax[(size_t)MROWS * KEXP];      // x split      [M, 3K]
__device__ __nv_bfloat16 g_actx[(size_t)MROWS * KEXP];    // ctx split    [M, 3K]
__device__ __nv_bfloat16 g_bw[(size_t)4 * DMODEL * KEXP]; // weights^T    [4][N, 3K]

// ---------------------------------------------------------------------------
// PTX helpers — arch-agnostic (sm_80-class) only: harness targets sm_103.
// ---------------------------------------------------------------------------
__device__ __forceinline__ uint32_t smem_u32(const void* p) {
    uint32_t a;
    asm("{ .reg .u64 t; cvta.to.shared.u64 t, %1; cvt.u32.u64 %0, t; }" : "=r"(a) : "l"(p));
    return a;
}
__device__ __forceinline__ void cp_async16(uint32_t dst, const void* src) {
    size_t g = __cvta_generic_to_global(src);
    asm volatile("cp.async.cg.shared.global [%0], [%1], 16;" :: "r"(dst), "l"(g) : "memory");
}
__device__ __forceinline__ void cp_commit() {
    asm volatile("cp.async.commit_group;" ::: "memory");
}
template <int N>
__device__ __forceinline__ void cp_wait() {
    asm volatile("cp.async.wait_group %0;" :: "n"(N) : "memory");
}
__device__ __forceinline__ uint32_t swz(uint32_t b) {   // Swizzle<3,4,3> on 128B rows
    return b ^ ((b >> 3) & 0x70);
}
__device__ __forceinline__ float ex2(float x) {
    float y;
    asm("ex2.approx.ftz.f32 %0, %1;" : "=f"(y) : "f"(x));
    return y;
}
__device__ __forceinline__ uint32_t pack2(__nv_bfloat16 a, __nv_bfloat16 b) {
    return ((uint32_t)__bfloat16_as_ushort(b) << 16) | __bfloat16_as_ushort(a);
}
__device__ __forceinline__ void split_pack(float a, float b, uint32_t& hp, uint32_t& lp) {
    __nv_bfloat16 ah = __float2bfloat16(a);
    __nv_bfloat16 bh = __float2bfloat16(b);
    float al = a - __bfloat162float(ah);
    float bl = b - __bfloat162float(bh);
    hp = pack2(ah, bh);
    lp = pack2(__float2bfloat16(al), __float2bfloat16(bl));
}

#define MMA(acc, a, b0, b1)                                                          \
    asm volatile(                                                                    \
        "mma.sync.aligned.m16n8k16.row.col.f32.bf16.bf16.f32 "                       \
        "{%0,%1,%2,%3}, {%4,%5,%6,%7}, {%8,%9}, {%0,%1,%2,%3};"                      \
        : "+f"((acc)[0]), "+f"((acc)[1]), "+f"((acc)[2]), "+f"((acc)[3])             \
        : "r"((a)[0]), "r"((a)[1]), "r"((a)[2]), "r"((a)[3]), "r"(b0), "r"(b1))

#define LDSM4(r, addr)                                                               \
    asm volatile("ldmatrix.sync.aligned.m8n8.x4.shared.b16 {%0,%1,%2,%3}, [%4];"     \
                 : "=r"((r)[0]), "=r"((r)[1]), "=r"((r)[2]), "=r"((r)[3]) : "r"(addr))

// ---------------------------------------------------------------------------
// Split conversions
// ---------------------------------------------------------------------------
__device__ __forceinline__ void split2(float x, __nv_bfloat16& h, __nv_bfloat16& l) {
    h = __float2bfloat16(x);
    l = __float2bfloat16(x - __bfloat162float(h));
}

__global__ void split_kernel(const float* __restrict__ in)   // x -> g_ax
{
    int idx = blockIdx.x * 256 + threadIdx.x;
    int m   = idx >> 8;
    int k4  = (idx & 255) * 4;
    float4 v = *(const float4*)&in[(size_t)m * DMODEL + k4];
    __nv_bfloat16 h[4], l[4];
    split2(v.x, h[0], l[0]); split2(v.y, h[1], l[1]);
    split2(v.z, h[2], l[2]); split2(v.w, h[3], l[3]);
    size_t ro = (size_t)m * KEXP;
    uint2 hp, lp;
    hp.x = pack2(h[0], h[1]); hp.y = pack2(h[2], h[3]);
    lp.x = pack2(l[0], l[1]); lp.y = pack2(l[2], l[3]);
    *(uint2*)&g_ax[ro + k4]              = hp;
    *(uint2*)&g_ax[ro + DMODEL + k4]     = hp;
    *(uint2*)&g_ax[ro + 2 * DMODEL + k4] = lp;
}

__global__ void wsplit_kernel(const float* __restrict__ wq, const float* __restrict__ wk,
                              const float* __restrict__ wv, const float* __restrict__ wo)
{
    const float* W;
    switch (blockIdx.z) {
        case 0: W = wq; break; case 1: W = wk; break;
        case 2: W = wv; break; default: W = wo; break;
    }
    __nv_bfloat16* out = g_bw + (size_t)blockIdx.z * DMODEL * KEXP;

    __shared__ float t[32][33];
    int k0 = blockIdx.x * 32, n0 = blockIdx.y * 32;
    int tx = threadIdx.x & 31, ty = threadIdx.x >> 5;
#pragma unroll
    for (int i = 0; i < 4; i++)
        t[ty + i * 8][tx] = W[(size_t)(k0 + ty + i * 8) * DMODEL + n0 + tx];
    __syncthreads();
#pragma unroll
    for (int i = 0; i < 4; i++) {
        int nl = ty + i * 8;
        float v = t[tx][nl];
        __nv_bfloat16 h, l;
        split2(v, h, l);
        size_t ro = (size_t)(n0 + nl) * KEXP + k0 + tx;
        out[ro]              = h;
        out[ro + DMODEL]     = l;
        out[ro + 2 * DMODEL] = h;
    }
}

// ---------------------------------------------------------------------------
// mma.sync bf16 GEMM, 128x128 CTA tile, BK=64, 3-stage cp.async pipeline.
// 2 CTAs/SM (96KB x 2 = 192KB smem, regs clamped to 128).
// ---------------------------------------------------------------------------
#define STAGES 3
#define CHUNK_BYTES 32768
#define GEMM_SMEM (STAGES * CHUNK_BYTES)

template <int MODE>
__device__ __forceinline__ void gemm_mma_body(const __nv_bfloat16* __restrict__ A,
                                              const __nv_bfloat16* __restrict__ B,
                                              const float* __restrict__ bias,
                                              float* __restrict__ C,
                                              __nv_bfloat16* __restrict__ Oh,
                                              __nv_bfloat16* __restrict__ Ol,
                                              float scale)
{
    extern __shared__ char smem[];
    const uint32_t sbase = smem_u32(smem);
    const int tid  = threadIdx.x;
    const int lane = tid & 31;
    const int w    = tid >> 5;
    const int wm   = w & 1;
    const int wn   = w >> 1;
    const int m0   = blockIdx.y * 128;
    const int n0   = blockIdx.x * 128;

    const __nv_bfloat16* Abase = A + (size_t)m0 * KEXP;
    const __nv_bfloat16* Bbase = B + (size_t)n0 * KEXP;

    const int r0 = tid >> 3;
    const int u  = tid & 7;

    auto load_chunk = [&](int c) {
        uint32_t so = sbase + (uint32_t)(c % STAGES) * CHUNK_BYTES;
        const __nv_bfloat16* as = Abase + (size_t)r0 * KEXP + c * 64 + u * 8;
        const __nv_bfloat16* bs = Bbase + (size_t)r0 * KEXP + c * 64 + u * 8;
#pragma unroll
        for (int i = 0; i < 4; i++) {
            uint32_t d = swz((uint32_t)(i * 32 + r0) * 128 + u * 16);
            cp_async16(so + d,         as + (size_t)i * 32 * KEXP);
            cp_async16(so + 16384 + d, bs + (size_t)i * 32 * KEXP);
        }
        cp_commit();
    };

    float acc[4][4][4];
#pragma unroll
    for (int mi = 0; mi < 4; mi++)
#pragma unroll
        for (int ni = 0; ni < 4; ni++)
#pragma unroll
            for (int r = 0; r < 4; r++) acc[mi][ni][r] = 0.f;

    load_chunk(0);
    load_chunk(1);

    for (int c = 0; c < NCHUNK; c++) {
        cp_wait<1>();
        __syncthreads();
        if (c + 2 < NCHUNK) load_chunk(c + 2);

        uint32_t sa = sbase + (uint32_t)(c % STAGES) * CHUNK_BYTES;
        uint32_t sb = sa + 16384;

#pragma unroll
        for (int ks = 0; ks < 4; ks++) {
            uint32_t a[4][4], b[4][2];
#pragma unroll
            for (int mi = 0; mi < 4; mi++) {
                int r = wm * 64 + mi * 16 + (lane & 15);
                uint32_t addr = sa + swz((uint32_t)r * 128 + ks * 32 + (lane >> 4) * 16);
                LDSM4(a[mi], addr);
            }
#pragma unroll
            for (int nj = 0; nj < 2; nj++) {
                int n = wn * 32 + nj * 16 + (lane >> 4) * 8 + (lane & 7);
                uint32_t addr = sb + swz((uint32_t)n * 128 + ks * 32 + ((lane >> 3) & 1) * 16);
                asm volatile("ldmatrix.sync.aligned.m8n8.x4.shared.b16 {%0,%1,%2,%3}, [%4];"
                             : "=r"(b[nj * 2][0]), "=r"(b[nj * 2][1]),
                               "=r"(b[nj * 2 + 1][0]), "=r"(b[nj * 2 + 1][1])
                             : "r"(addr));
            }
#pragma unroll
            for (int mi = 0; mi < 4; mi++)
#pragma unroll
                for (int ni = 0; ni < 4; ni++)
                    MMA(acc[mi][ni], a[mi], b[ni][0], b[ni][1]);
        }
    }

    const int mrow = m0 + wm * 64 + (lane >> 2);
    const int ncol = n0 + wn * 32 + (lane & 3) * 2;
#pragma unroll
    for (int mi = 0; mi < 4; mi++) {
        int r = mrow + mi * 16;
#pragma unroll
        for (int ni = 0; ni < 4; ni++) {
            int cc = ncol + ni * 8;
            float b0 = bias[cc], b1 = bias[cc + 1];
            float v0 = acc[mi][ni][0] + b0, v1 = acc[mi][ni][1] + b1;
            float v2 = acc[mi][ni][2] + b0, v3 = acc[mi][ni][3] + b1;
            if (MODE == 0) {
                *(float2*)&C[(size_t)r * DMODEL + cc]       = make_float2(v0, v1);
                *(float2*)&C[(size_t)(r + 8) * DMODEL + cc] = make_float2(v2, v3);
            } else {
                v0 *= scale; v1 *= scale; v2 *= scale; v3 *= scale;
                int bb = r >> 11, hh = cc >> 6, dd = cc & 63;
                size_t off0 = (((size_t)bb * NHEAD + hh) * SEQ + (r & 2047)) * HDIM + dd;
                size_t off1 = off0 + 8 * HDIM;
                uint32_t hp, lp;
                split_pack(v0, v1, hp, lp);
                *(uint32_t*)&Oh[off0] = hp;
                *(uint32_t*)&Ol[off0] = lp;
                split_pack(v2, v3, hp, lp);
                *(uint32_t*)&Oh[off1] = hp;
                *(uint32_t*)&Ol[off1] = lp;
            }
        }
    }
}

__global__ __launch_bounds__(256, 2) void qkv_tc_kernel(
    const float* __restrict__ bq, const float* __restrict__ bk, const float* __restrict__ bv)
{
    if (blockIdx.z == 0)
        gemm_mma_body<1>(g_ax, g_bw, bq, nullptr, g_qh, g_ql, QSCALE);
    else if (blockIdx.z == 1)
        gemm_mma_body<1>(g_ax, g_bw + (size_t)DMODEL * KEXP, bk, nullptr, g_kh, g_kl, 1.f);
    else
        gemm_mma_body<1>(g_ax, g_bw + (size_t)2 * DMODEL * KEXP, bv, nullptr, g_vh, g_vl, 1.f);
}

__global__ __launch_bounds__(256, 2) void out_tc_kernel(
    const float* __restrict__ bo, float* __restrict__ out)
{
    gemm_mma_body<0>(g_actx, g_bw + (size_t)3 * DMODEL * KEXP, bo, out, nullptr, nullptr, 1.f);
}

// ---------------------------------------------------------------------------
// Tensor-core causal flash attention. 2 CTAs/SM target.
// CTA: 256 thr (8 warps), q-tile 128, k-tile 64, Dh=64.
// Register diet: P hi/lo packs live only within each PV j-iteration.
// ---------------------------------------------------------------------------
#define ATT_SMEM 98304

__global__ __launch_bounds__(256, 2) void attn_tc_kernel()
{
    extern __shared__ char smem[];
    const uint32_t sb = smem_u32(smem);
    const int tid  = threadIdx.x;
    const int lane = tid & 31;
    const int w    = tid >> 5;
    const int qt   = (int)(gridDim.x - 1 - blockIdx.x);   // heavy tiles first
    const int h    = blockIdx.y, b = blockIdx.z;
    const int q0   = qt * 128;
    const int nkt  = 2 * qt + 2;
    const size_t bh = ((size_t)b * NHEAD + h) * SEQ * HDIM;
    const __nv_bfloat16 *Qhp = g_qh + bh, *Qlp = g_ql + bh;
    const __nv_bfloat16 *Khp = g_kh + bh, *Klp = g_kl + bh;
    const __nv_bfloat16 *Vhp = g_vh + bh, *Vlp = g_vl + bh;

    const int u  = tid & 7;
    const int r8 = tid >> 3;

    // ---- stage Q (q0..q0+127, hi+lo)
#pragma unroll
    for (int i = 0; i < 4; i++) {
        int row = r8 + 32 * i;
        uint32_t d = swz((uint32_t)row * 128 + u * 16);
        cp_async16(sb + d,         Qhp + (size_t)(q0 + row) * HDIM + u * 8);
        cp_async16(sb + 16384 + d, Qlp + (size_t)(q0 + row) * HDIM + u * 8);
    }
    cp_commit();

    auto load_kv = [&](int kt) {
        uint32_t so = sb + 32768 + (uint32_t)(kt & 1) * 32768;
        int kbase = kt * 64;
#pragma unroll
        for (int i = 0; i < 2; i++) {
            int row = r8 + 32 * i;
            uint32_t d = swz((uint32_t)row * 128 + u * 16);
            size_t g = (size_t)(kbase + row) * HDIM + u * 8;
            cp_async16(so + d,         Khp + g);
            cp_async16(so + 8192 + d,  Klp + g);
            cp_async16(so + 16384 + d, Vhp + g);
            cp_async16(so + 24576 + d, Vlp + g);
        }
        cp_commit();
    };
    load_kv(0);
    cp_wait<0>();
    __syncthreads();

    // ---- resident Q fragments
    uint32_t qh[4][4], ql[4][4];
#pragma unroll
    for (int ks = 0; ks < 4; ks++) {
        uint32_t d = swz((uint32_t)(w * 16 + (lane & 15)) * 128 + ks * 32 + (lane >> 4) * 16);
        LDSM4(qh[ks], sb + d);
        LDSM4(ql[ks], sb + 16384 + d);
    }

    float ctx[8][4];
#pragma unroll
    for (int dt = 0; dt < 8; dt++)
#pragma unroll
        for (int r = 0; r < 4; r++) ctx[dt][r] = 0.f;
    float m0 = -1e30f, m1 = -1e30f, l0 = 0.f, l1 = 0.f;

    for (int kt = 0; kt < nkt; kt++) {
        cp_wait<0>();
        __syncthreads();
        if (kt + 1 < nkt) load_kv(kt + 1);
        const uint32_t sk = sb + 32768 + (uint32_t)(kt & 1) * 32768;

        // ---- S = Q K^T  (Qh Kh + Qh Kl + Ql Kh)
        float s[8][4];
#pragma unroll
        for (int nt = 0; nt < 8; nt++) {
            s[nt][0] = s[nt][1] = s[nt][2] = s[nt][3] = 0.f;
            uint32_t kh[4][2], kl[4][2];
#pragma unroll
            for (int hf = 0; hf < 2; hf++) {
                uint32_t d = swz((uint32_t)(nt * 8 + (lane & 7)) * 128 + hf * 64 + (lane >> 3) * 16);
                asm volatile("ldmatrix.sync.aligned.m8n8.x4.shared.b16 {%0,%1,%2,%3}, [%4];"
                             : "=r"(kh[2*hf][0]), "=r"(kh[2*hf][1]),
                               "=r"(kh[2*hf+1][0]), "=r"(kh[2*hf+1][1]) : "r"(sk + d));
                asm volatile("ldmatrix.sync.aligned.m8n8.x4.shared.b16 {%0,%1,%2,%3}, [%4];"
                             : "=r"(kl[2*hf][0]), "=r"(kl[2*hf][1]),
                               "=r"(kl[2*hf+1][0]), "=r"(kl[2*hf+1][1]) : "r"(sk + 8192 + d));
            }
#pragma unroll
            for (int ks = 0; ks < 4; ks++) {
                MMA(s[nt], qh[ks], kh[ks][0], kh[ks][1]);
                MMA(s[nt], qh[ks], kl[ks][0], kl[ks][1]);
                MMA(s[nt], ql[ks], kh[ks][0], kh[ks][1]);
            }
        }

        // ---- causal mask
        if (kt >= nkt - 2) {
            int qr = q0 + w * 16 + (lane >> 2);
#pragma unroll
            for (int nt = 0; nt < 8; nt++) {
                int kc = kt * 64 + nt * 8 + (lane & 3) * 2;
                if (kc     > qr)     s[nt][0] = -1e30f;
                if (kc + 1 > qr)     s[nt][1] = -1e30f;
                if (kc     > qr + 8) s[nt][2] = -1e30f;
                if (kc + 1 > qr + 8) s[nt][3] = -1e30f;
            }
        }

        // ---- online softmax (exp2 domain)
        float mx0 = -1e30f, mx1 = -1e30f;
#pragma unroll
        for (int nt = 0; nt < 8; nt++) {
            mx0 = fmaxf(mx0, fmaxf(s[nt][0], s[nt][1]));
            mx1 = fmaxf(mx1, fmaxf(s[nt][2], s[nt][3]));
        }
        mx0 = fmaxf(mx0, __shfl_xor_sync(0xffffffffu, mx0, 1));
        mx0 = fmaxf(mx0, __shfl_xor_sync(0xffffffffu, mx0, 2));
        mx1 = fmaxf(mx1, __shfl_xor_sync(0xffffffffu, mx1, 1));
        mx1 = fmaxf(mx1, __shfl_xor_sync(0xffffffffu, mx1, 2));
        float mn0 = fmaxf(m0, mx0), mn1 = fmaxf(m1, mx1);
        float c0 = ex2(m0 - mn0), c1 = ex2(m1 - mn1);
        m0 = mn0; m1 = mn1;
        l0 *= c0; l1 *= c1;
#pragma unroll
        for (int dt = 0; dt < 8; dt++) {
            ctx[dt][0] *= c0; ctx[dt][1] *= c0;
            ctx[dt][2] *= c1; ctx[dt][3] *= c1;
        }

        // ---- per-j: exp, pack, PV (keeps P packs short-lived)
        const uint32_t sv = sk + 16384;
#pragma unroll
        for (int j = 0; j < 4; j++) {
            float p00 = ex2(s[2*j][0] - mn0),   p01 = ex2(s[2*j][1] - mn0);
            float p02 = ex2(s[2*j][2] - mn1),   p03 = ex2(s[2*j][3] - mn1);
            float p10 = ex2(s[2*j+1][0] - mn0), p11 = ex2(s[2*j+1][1] - mn0);
            float p12 = ex2(s[2*j+1][2] - mn1), p13 = ex2(s[2*j+1][3] - mn1);
            l0 += (p00 + p01) + (p10 + p11);
            l1 += (p02 + p03) + (p12 + p13);
            uint32_t ph[4], pl[4];
            split_pack(p00, p01, ph[0], pl[0]);
            split_pack(p02, p03, ph[1], pl[1]);
            split_pack(p10, p11, ph[2], pl[2]);
            split_pack(p12, p13, ph[3], pl[3]);

            uint32_t vf[8][2];
#pragma unroll
            for (int dp = 0; dp < 4; dp++) {
                uint32_t d = swz((uint32_t)(j * 16 + (lane & 15)) * 128 + dp * 32 + (lane >> 4) * 16);
                asm volatile("ldmatrix.sync.aligned.m8n8.x4.trans.shared.b16 {%0,%1,%2,%3}, [%4];"
                             : "=r"(vf[2*dp][0]), "=r"(vf[2*dp][1]),
                               "=r"(vf[2*dp+1][0]), "=r"(vf[2*dp+1][1]) : "r"(sv + d));
            }
#pragma unroll
            for (int dt = 0; dt < 8; dt++) {
                MMA(ctx[dt], ph, vf[dt][0], vf[dt][1]);
                MMA(ctx[dt], pl, vf[dt][0], vf[dt][1]);
            }
#pragma unroll
            for (int dp = 0; dp < 4; dp++) {
                uint32_t d = swz((uint32_t)(j * 16 + (lane & 15)) * 128 + dp * 32 + (lane >> 4) * 16);
                asm volatile("ldmatrix.sync.aligned.m8n8.x4.trans.shared.b16 {%0,%1,%2,%3}, [%4];"
                             : "=r"(vf[2*dp][0]), "=r"(vf[2*dp][1]),
                               "=r"(vf[2*dp+1][0]), "=r"(vf[2*dp+1][1]) : "r"(sv + 8192 + d));
            }
#pragma unroll
            for (int dt = 0; dt < 8; dt++)
                MMA(ctx[dt], ph, vf[dt][0], vf[dt][1]);
        }
    }

    // ---- finalize
    l0 += __shfl_xor_sync(0xffffffffu, l0, 1);
    l0 += __shfl_xor_sync(0xffffffffu, l0, 2);
    l1 += __shfl_xor_sync(0xffffffffu, l1, 1);
    l1 += __shfl_xor_sync(0xffffffffu, l1, 2);
    float rinv0 = 1.f / l0, rinv1 = 1.f / l1;

    int qr = q0 + w * 16 + (lane >> 2);
    size_t row0 = ((size_t)b * SEQ + qr) * KEXP;
    size_t row1 = ((size_t)b * SEQ + qr + 8) * KEXP;
    int cbase = h * HDIM + (lane & 3) * 2;
#pragma unroll
    for (int dt = 0; dt < 8; dt++) {
        int cc = cbase + dt * 8;
        uint32_t hp, lp;
        split_pack(ctx[dt][0] * rinv0, ctx[dt][1] * rinv0, hp, lp);
        *(uint32_t*)&g_actx[row0 + cc]              = hp;
        *(uint32_t*)&g_actx[row0 + DMODEL + cc]     = hp;
        *(uint32_t*)&g_actx[row0 + 2 * DMODEL + cc] = lp;
        split_pack(ctx[dt][2] * rinv1, ctx[dt][3] * rinv1, hp, lp);
        *(uint32_t*)&g_actx[row1 + cc]              = hp;
        *(uint32_t*)&g_actx[row1 + DMODEL + cc]     = hp;
        *(uint32_t*)&g_actx[row1 + 2 * DMODEL + cc] = lp;
    }
}

// ---------------------------------------------------------------------------
// Launch
// ---------------------------------------------------------------------------
extern "C" void kernel_launch(void* const* d_in, const int* in_sizes, int n_in,
                              void* d_out, int out_size)
{
    const float* x  = (const float*)d_in[0];
    const float* wq = (const float*)d_in[1];
    const float* bq = (const float*)d_in[2];
    const float* wk = (const float*)d_in[3];
    const float* bk = (const float*)d_in[4];
    const float* wv = (const float*)d_in[5];
    const float* bv = (const float*)d_in[6];
    const float* wo = (const float*)d_in[7];
    const float* bo = (const float*)d_in[8];
    float* out = (float*)d_out;
    (void)in_sizes; (void)n_in; (void)out_size;

    cudaFuncSetAttribute(qkv_tc_kernel, cudaFuncAttributeMaxDynamicSharedMemorySize, GEMM_SMEM);
    cudaFuncSetAttribute(out_tc_kernel, cudaFuncAttributeMaxDynamicSharedMemorySize, GEMM_SMEM);
    cudaFuncSetAttribute(attn_tc_kernel, cudaFuncAttributeMaxDynamicSharedMemorySize, ATT_SMEM);

    wsplit_kernel<<<dim3(32, 32, 4), 256>>>(wq, wk, wv, wo);
    split_kernel<<<MROWS * (DMODEL / 4) / 256, 256>>>(x);
    qkv_tc_kernel<<<dim3(DMODEL / 128, MROWS / 128, 3), 256, GEMM_SMEM>>>(bq, bk, bv);
    attn_tc_kernel<<<dim3(SEQ / 128, NHEAD, BATCH), 256, ATT_SMEM>>>();
    out_tc_kernel<<<dim3(DMODEL / 128, MROWS / 128), 256, GEMM_SMEM>>>(bo, out);
}

// round 8
// speedup vs baseline: 3.8502x; 1.1478x over previous
#include <cuda_runtime.h>
#include <cuda_bf16.h>
#include <cuda_fp16.h>
#include <cstdint>

// ---------------------------------------------------------------------------
// Problem constants
// ---------------------------------------------------------------------------
#define BATCH   4
#define SEQ     2048
#define DMODEL  1024
#define NHEAD   16
#define HDIM    64
#define MROWS   (BATCH * SEQ)          // 8192
#define KEXP    (3 * DMODEL)           // 3072: [hi | hi | lo] x [hi | lo | hi]
#define QSCALE  0.18033688011112042f   // log2(e) / sqrt(HDIM)

// ---------------------------------------------------------------------------
// Scratch (device globals: allocation-free, graph-capture safe)
// ---------------------------------------------------------------------------
__device__ __nv_bfloat16 g_qh[MROWS * DMODEL];            // [b,h,s,d] Q hi (pre-scaled)
__device__ __nv_bfloat16 g_ql[MROWS * DMODEL];            // Q lo
__device__ __nv_bfloat16 g_kh[MROWS * DMODEL];            // K hi
__device__ __nv_bfloat16 g_kl[MROWS * DMODEL];            // K lo
__device__ __half        g_vh[MROWS * DMODEL];            // V hi (fp16)
__device__ __half        g_vl[MROWS * DMODEL];            // V lo (fp16)
__device__ __nv_bfloat16 g_ax[(size_t)MROWS * KEXP];      // x split      [M, 3K] bf16
__device__ __half        g_actxh[MROWS * DMODEL];         // ctx, single fp16 [M, K]
__device__ __nv_bfloat16 g_bw[(size_t)3 * DMODEL * KEXP]; // Wq/Wk/Wv^T   [3][N, 3K] bf16
__device__ __half        g_bwo[(size_t)DMODEL * 2 * DMODEL]; // Wo^T [N, 2K] = [hi|lo] fp16

// ---------------------------------------------------------------------------
// PTX helpers — arch-agnostic (sm_80-class) only: harness targets sm_103.
// ---------------------------------------------------------------------------
__device__ __forceinline__ uint32_t smem_u32(const void* p) {
    uint32_t a;
    asm("{ .reg .u64 t; cvta.to.shared.u64 t, %1; cvt.u32.u64 %0, t; }" : "=r"(a) : "l"(p));
    return a;
}
__device__ __forceinline__ void cp_async16(uint32_t dst, const void* src) {
    size_t g = __cvta_generic_to_global(src);
    asm volatile("cp.async.cg.shared.global [%0], [%1], 16;" :: "r"(dst), "l"(g) : "memory");
}
__device__ __forceinline__ void cp_commit() {
    asm volatile("cp.async.commit_group;" ::: "memory");
}
template <int N>
__device__ __forceinline__ void cp_wait() {
    asm volatile("cp.async.wait_group %0;" :: "n"(N) : "memory");
}
__device__ __forceinline__ uint32_t swz(uint32_t b) {   // Swizzle<3,4,3> on 128B rows
    return b ^ ((b >> 3) & 0x70);
}
__device__ __forceinline__ float ex2(float x) {
    float y;
    asm("ex2.approx.ftz.f32 %0, %1;" : "=f"(y) : "f"(x));
    return y;
}
__device__ __forceinline__ uint32_t pack2(__nv_bfloat16 a, __nv_bfloat16 b) {
    return ((uint32_t)__bfloat16_as_ushort(b) << 16) | __bfloat16_as_ushort(a);
}
__device__ __forceinline__ uint32_t h2(float a, float b) {
    __half2 h = __floats2half2_rn(a, b);
    return *reinterpret_cast<uint32_t*>(&h);
}
// bf16 hi/lo pair
__device__ __forceinline__ void split_pack(float a, float b, uint32_t& hp, uint32_t& lp) {
    __nv_bfloat16 ah = __float2bfloat16(a);
    __nv_bfloat16 bh = __float2bfloat16(b);
    float al = a - __bfloat162float(ah);
    float bl = b - __bfloat162float(bh);
    hp = pack2(ah, bh);
    lp = pack2(__float2bfloat16(al), __float2bfloat16(bl));
}
// fp16 hi/lo pair
__device__ __forceinline__ void split_pack_h(float a, float b, uint32_t& hp, uint32_t& lp) {
    __half ah = __float2half_rn(a);
    __half bh = __float2half_rn(b);
    float al = a - __half2float(ah);
    float bl = b - __half2float(bh);
    __half2 hh = __halves2half2(ah, bh);
    hp = *reinterpret_cast<uint32_t*>(&hh);
    lp = h2(al, bl);
}

#define MMAB(acc, a, b0, b1)                                                         \
    asm volatile(                                                                    \
        "mma.sync.aligned.m16n8k16.row.col.f32.bf16.bf16.f32 "                       \
        "{%0,%1,%2,%3}, {%4,%5,%6,%7}, {%8,%9}, {%0,%1,%2,%3};"                      \
        : "+f"((acc)[0]), "+f"((acc)[1]), "+f"((acc)[2]), "+f"((acc)[3])             \
        : "r"((a)[0]), "r"((a)[1]), "r"((a)[2]), "r"((a)[3]), "r"(b0), "r"(b1))

#define MMAH(acc, a, b0, b1)                                                         \
    asm volatile(                                                                    \
        "mma.sync.aligned.m16n8k16.row.col.f32.f16.f16.f32 "                         \
        "{%0,%1,%2,%3}, {%4,%5,%6,%7}, {%8,%9}, {%0,%1,%2,%3};"                      \
        : "+f"((acc)[0]), "+f"((acc)[1]), "+f"((acc)[2]), "+f"((acc)[3])             \
        : "r"((a)[0]), "r"((a)[1]), "r"((a)[2]), "r"((a)[3]), "r"(b0), "r"(b1))

#define LDSM4(r, addr)                                                               \
    asm volatile("ldmatrix.sync.aligned.m8n8.x4.shared.b16 {%0,%1,%2,%3}, [%4];"     \
                 : "=r"((r)[0]), "=r"((r)[1]), "=r"((r)[2]), "=r"((r)[3]) : "r"(addr))

// ---------------------------------------------------------------------------
// Split conversions (host-input preprocessing)
// ---------------------------------------------------------------------------
__device__ __forceinline__ void split2(float x, __nv_bfloat16& h, __nv_bfloat16& l) {
    h = __float2bfloat16(x);
    l = __float2bfloat16(x - __bfloat162float(h));
}

__global__ void split_kernel(const float* __restrict__ in)   // x -> g_ax
{
    int idx = blockIdx.x * 256 + threadIdx.x;
    int m   = idx >> 8;
    int k4  = (idx & 255) * 4;
    float4 v = *(const float4*)&in[(size_t)m * DMODEL + k4];
    __nv_bfloat16 h[4], l[4];
    split2(v.x, h[0], l[0]); split2(v.y, h[1], l[1]);
    split2(v.z, h[2], l[2]); split2(v.w, h[3], l[3]);
    size_t ro = (size_t)m * KEXP;
    uint2 hp, lp;
    hp.x = pack2(h[0], h[1]); hp.y = pack2(h[2], h[3]);
    lp.x = pack2(l[0], l[1]); lp.y = pack2(l[2], l[3]);
    *(uint2*)&g_ax[ro + k4]              = hp;
    *(uint2*)&g_ax[ro + DMODEL + k4]     = hp;
    *(uint2*)&g_ax[ro + 2 * DMODEL + k4] = lp;
}

// Weight transpose + split. z 0..2: bf16 3-seg -> g_bw. z==3: fp16 2-seg -> g_bwo.
__global__ void wsplit_kernel(const float* __restrict__ wq, const float* __restrict__ wk,
                              const float* __restrict__ wv, const float* __restrict__ wo)
{
    const float* W;
    switch (blockIdx.z) {
        case 0: W = wq; break; case 1: W = wk; break;
        case 2: W = wv; break; default: W = wo; break;
    }
    __shared__ float t[32][33];
    int k0 = blockIdx.x * 32, n0 = blockIdx.y * 32;
    int tx = threadIdx.x & 31, ty = threadIdx.x >> 5;
#pragma unroll
    for (int i = 0; i < 4; i++)
        t[ty + i * 8][tx] = W[(size_t)(k0 + ty + i * 8) * DMODEL + n0 + tx];
    __syncthreads();

    if (blockIdx.z < 3) {
        __nv_bfloat16* out = g_bw + (size_t)blockIdx.z * DMODEL * KEXP;
#pragma unroll
        for (int i = 0; i < 4; i++) {
            int nl = ty + i * 8;
            float v = t[tx][nl];
            __nv_bfloat16 h, l;
            split2(v, h, l);
            size_t ro = (size_t)(n0 + nl) * KEXP + k0 + tx;
            out[ro]              = h;
            out[ro + DMODEL]     = l;
            out[ro + 2 * DMODEL] = h;
        }
    } else {
#pragma unroll
        for (int i = 0; i < 4; i++) {
            int nl = ty + i * 8;
            float v = t[tx][nl];
            __half hh = __float2half_rn(v);
            __half hl = __float2half_rn(v - __half2float(hh));
            size_t ro = (size_t)(n0 + nl) * (2 * DMODEL) + k0 + tx;
            g_bwo[ro]          = hh;
            g_bwo[ro + DMODEL] = hl;
        }
    }
}

// ---------------------------------------------------------------------------
// mma.sync GEMM, 128x128 CTA tile, BK=64, 3-stage cp.async pipeline, 2 CTAs/SM.
// DT: 0=bf16, 1=fp16 MMA. KA/KB: element K extents of A/B (A chunk = c % (KA/64)).
// MODE: 0 -> fp32 C+bias. 1 -> bf16 hi/lo pair out. 2 -> fp16 hi/lo pair out.
// ---------------------------------------------------------------------------
#define STAGES 3
#define CHUNK_BYTES 32768
#define GEMM_SMEM (STAGES * CHUNK_BYTES)

template <int MODE, int DT, int KA, int KB>
__device__ __forceinline__ void gemm_mma_body(const uint16_t* __restrict__ A,
                                              const uint16_t* __restrict__ B,
                                              const float* __restrict__ bias,
                                              float* __restrict__ C,
                                              uint16_t* __restrict__ Oh,
                                              uint16_t* __restrict__ Ol,
                                              float scale)
{
    constexpr int NCH = KB / 64;
    constexpr int ACH = KA / 64;
    extern __shared__ char smem[];
    const uint32_t sbase = smem_u32(smem);
    const int tid  = threadIdx.x;
    const int lane = tid & 31;
    const int w    = tid >> 5;
    const int wm   = w & 1;
    const int wn   = w >> 1;
    const int m0   = blockIdx.y * 128;
    const int n0   = blockIdx.x * 128;

    const uint16_t* Abase = A + (size_t)m0 * KA;
    const uint16_t* Bbase = B + (size_t)n0 * KB;

    const int r0 = tid >> 3;
    const int u  = tid & 7;

    auto load_chunk = [&](int c) {
        uint32_t so = sbase + (uint32_t)(c % STAGES) * CHUNK_BYTES;
        const uint16_t* as = Abase + (size_t)r0 * KA + (c % ACH) * 64 + u * 8;
        const uint16_t* bs = Bbase + (size_t)r0 * KB + c * 64 + u * 8;
#pragma unroll
        for (int i = 0; i < 4; i++) {
            uint32_t d = swz((uint32_t)(i * 32 + r0) * 128 + u * 16);
            cp_async16(so + d,         as + (size_t)i * 32 * KA);
            cp_async16(so + 16384 + d, bs + (size_t)i * 32 * KB);
        }
        cp_commit();
    };

    float acc[4][4][4];
#pragma unroll
    for (int mi = 0; mi < 4; mi++)
#pragma unroll
        for (int ni = 0; ni < 4; ni++)
#pragma unroll
            for (int r = 0; r < 4; r++) acc[mi][ni][r] = 0.f;

    load_chunk(0);
    load_chunk(1);

    for (int c = 0; c < NCH; c++) {
        cp_wait<1>();
        __syncthreads();
        if (c + 2 < NCH) load_chunk(c + 2);

        uint32_t sa = sbase + (uint32_t)(c % STAGES) * CHUNK_BYTES;
        uint32_t sb = sa + 16384;

#pragma unroll
        for (int ks = 0; ks < 4; ks++) {
            uint32_t a[4][4], b[4][2];
#pragma unroll
            for (int mi = 0; mi < 4; mi++) {
                int r = wm * 64 + mi * 16 + (lane & 15);
                uint32_t addr = sa + swz((uint32_t)r * 128 + ks * 32 + (lane >> 4) * 16);
                LDSM4(a[mi], addr);
            }
#pragma unroll
            for (int nj = 0; nj < 2; nj++) {
                int n = wn * 32 + nj * 16 + (lane >> 4) * 8 + (lane & 7);
                uint32_t addr = sb + swz((uint32_t)n * 128 + ks * 32 + ((lane >> 3) & 1) * 16);
                asm volatile("ldmatrix.sync.aligned.m8n8.x4.shared.b16 {%0,%1,%2,%3}, [%4];"
                             : "=r"(b[nj * 2][0]), "=r"(b[nj * 2][1]),
                               "=r"(b[nj * 2 + 1][0]), "=r"(b[nj * 2 + 1][1])
                             : "r"(addr));
            }
#pragma unroll
            for (int mi = 0; mi < 4; mi++)
#pragma unroll
                for (int ni = 0; ni < 4; ni++) {
                    if (DT == 0) { MMAB(acc[mi][ni], a[mi], b[ni][0], b[ni][1]); }
                    else         { MMAH(acc[mi][ni], a[mi], b[ni][0], b[ni][1]); }
                }
        }
    }

    const int mrow = m0 + wm * 64 + (lane >> 2);
    const int ncol = n0 + wn * 32 + (lane & 3) * 2;
#pragma unroll
    for (int mi = 0; mi < 4; mi++) {
        int r = mrow + mi * 16;
#pragma unroll
        for (int ni = 0; ni < 4; ni++) {
            int cc = ncol + ni * 8;
            float b0 = bias[cc], b1 = bias[cc + 1];
            float v0 = acc[mi][ni][0] + b0, v1 = acc[mi][ni][1] + b1;
            float v2 = acc[mi][ni][2] + b0, v3 = acc[mi][ni][3] + b1;
            if (MODE == 0) {
                *(float2*)&C[(size_t)r * DMODEL + cc]       = make_float2(v0, v1);
                *(float2*)&C[(size_t)(r + 8) * DMODEL + cc] = make_float2(v2, v3);
            } else {
                v0 *= scale; v1 *= scale; v2 *= scale; v3 *= scale;
                int bb = r >> 11, hh = cc >> 6, dd = cc & 63;
                size_t off0 = (((size_t)bb * NHEAD + hh) * SEQ + (r & 2047)) * HDIM + dd;
                size_t off1 = off0 + 8 * HDIM;
                uint32_t hp, lp;
                if (MODE == 1) split_pack(v0, v1, hp, lp);
                else           split_pack_h(v0, v1, hp, lp);
                *(uint32_t*)&Oh[off0] = hp;
                *(uint32_t*)&Ol[off0] = lp;
                if (MODE == 1) split_pack(v2, v3, hp, lp);
                else           split_pack_h(v2, v3, hp, lp);
                *(uint32_t*)&Oh[off1] = hp;
                *(uint32_t*)&Ol[off1] = lp;
            }
        }
    }
}

__global__ __launch_bounds__(256, 2) void qkv_tc_kernel(
    const float* __restrict__ bq, const float* __restrict__ bk, const float* __restrict__ bv)
{
    if (blockIdx.z == 0)
        gemm_mma_body<1, 0, KEXP, KEXP>((const uint16_t*)g_ax, (const uint16_t*)g_bw,
                                        bq, nullptr, (uint16_t*)g_qh, (uint16_t*)g_ql, QSCALE);
    else if (blockIdx.z == 1)
        gemm_mma_body<1, 0, KEXP, KEXP>((const uint16_t*)g_ax,
                                        (const uint16_t*)(g_bw + (size_t)DMODEL * KEXP),
                                        bk, nullptr, (uint16_t*)g_kh, (uint16_t*)g_kl, 1.f);
    else
        gemm_mma_body<2, 0, KEXP, KEXP>((const uint16_t*)g_ax,
                                        (const uint16_t*)(g_bw + (size_t)2 * DMODEL * KEXP),
                                        bv, nullptr, (uint16_t*)g_vh, (uint16_t*)g_vl, 1.f);
}

__global__ __launch_bounds__(256, 2) void out_tc_kernel(
    const float* __restrict__ bo, float* __restrict__ out)
{
    gemm_mma_body<0, 1, DMODEL, 2 * DMODEL>((const uint16_t*)g_actxh, (const uint16_t*)g_bwo,
                                            bo, out, nullptr, nullptr, 1.f);
}

// ---------------------------------------------------------------------------
// Tensor-core causal flash attention. 2 CTAs/SM.
// QK^T: bf16 3-term (score-sensitive). PV: fp16 P (single) x fp16 V hi/lo (2 MMAs).
// Smem: Qh|Ql (32KB) + 2 x (Kh|Kl|Vh|Vl) (2x32KB) = 96KB.
// ---------------------------------------------------------------------------
#define ATT_SMEM 98304

__global__ __launch_bounds__(256, 2) void attn_tc_kernel()
{
    extern __shared__ char smem[];
    const uint32_t sb = smem_u32(smem);
    const int tid  = threadIdx.x;
    const int lane = tid & 31;
    const int w    = tid >> 5;
    const int qt   = (int)(gridDim.x - 1 - blockIdx.x);   // heavy tiles first
    const int h    = blockIdx.y, b = blockIdx.z;
    const int q0   = qt * 128;
    const int nkt  = 2 * qt + 2;
    const size_t bh = ((size_t)b * NHEAD + h) * SEQ * HDIM;
    const __nv_bfloat16 *Qhp = g_qh + bh, *Qlp = g_ql + bh;
    const __nv_bfloat16 *Khp = g_kh + bh, *Klp = g_kl + bh;
    const __half        *Vhp = g_vh + bh, *Vlp = g_vl + bh;

    const int u  = tid & 7;
    const int r8 = tid >> 3;

    // ---- stage Q (q0..q0+127, hi+lo)
#pragma unroll
    for (int i = 0; i < 4; i++) {
        int row = r8 + 32 * i;
        uint32_t d = swz((uint32_t)row * 128 + u * 16);
        cp_async16(sb + d,         Qhp + (size_t)(q0 + row) * HDIM + u * 8);
        cp_async16(sb + 16384 + d, Qlp + (size_t)(q0 + row) * HDIM + u * 8);
    }
    cp_commit();

    auto load_kv = [&](int kt) {
        uint32_t so = sb + 32768 + (uint32_t)(kt & 1) * 32768;
        int kbase = kt * 64;
#pragma unroll
        for (int i = 0; i < 2; i++) {
            int row = r8 + 32 * i;
            uint32_t d = swz((uint32_t)row * 128 + u * 16);
            size_t g = (size_t)(kbase + row) * HDIM + u * 8;
            cp_async16(so + d,         Khp + g);
            cp_async16(so + 8192 + d,  Klp + g);
            cp_async16(so + 16384 + d, Vhp + g);
            cp_async16(so + 24576 + d, Vlp + g);
        }
        cp_commit();
    };
    load_kv(0);
    cp_wait<0>();
    __syncthreads();

    // ---- resident Q fragments
    uint32_t qh[4][4], ql[4][4];
#pragma unroll
    for (int ks = 0; ks < 4; ks++) {
        uint32_t d = swz((uint32_t)(w * 16 + (lane & 15)) * 128 + ks * 32 + (lane >> 4) * 16);
        LDSM4(qh[ks], sb + d);
        LDSM4(ql[ks], sb + 16384 + d);
    }

    float ctx[8][4];
#pragma unroll
    for (int dt = 0; dt < 8; dt++)
#pragma unroll
        for (int r = 0; r < 4; r++) ctx[dt][r] = 0.f;
    float m0 = -1e30f, m1 = -1e30f, l0 = 0.f, l1 = 0.f;

    for (int kt = 0; kt < nkt; kt++) {
        cp_wait<0>();
        __syncthreads();
        if (kt + 1 < nkt) load_kv(kt + 1);
        const uint32_t sk = sb + 32768 + (uint32_t)(kt & 1) * 32768;

        // ---- S = Q K^T  (Qh Kh + Qh Kl + Ql Kh), bf16 3-term
        float s[8][4];
#pragma unroll
        for (int nt = 0; nt < 8; nt++) {
            s[nt][0] = s[nt][1] = s[nt][2] = s[nt][3] = 0.f;
            uint32_t kh[4][2], kl[4][2];
#pragma unroll
            for (int hf = 0; hf < 2; hf++) {
                uint32_t d = swz((uint32_t)(nt * 8 + (lane & 7)) * 128 + hf * 64 + (lane >> 3) * 16);
                asm volatile("ldmatrix.sync.aligned.m8n8.x4.shared.b16 {%0,%1,%2,%3}, [%4];"
                             : "=r"(kh[2*hf][0]), "=r"(kh[2*hf][1]),
                               "=r"(kh[2*hf+1][0]), "=r"(kh[2*hf+1][1]) : "r"(sk + d));
                asm volatile("ldmatrix.sync.aligned.m8n8.x4.shared.b16 {%0,%1,%2,%3}, [%4];"
                             : "=r"(kl[2*hf][0]), "=r"(kl[2*hf][1]),
                               "=r"(kl[2*hf+1][0]), "=r"(kl[2*hf+1][1]) : "r"(sk + 8192 + d));
            }
#pragma unroll
            for (int ks = 0; ks < 4; ks++) {
                MMAB(s[nt], qh[ks], kh[ks][0], kh[ks][1]);
                MMAB(s[nt], qh[ks], kl[ks][0], kl[ks][1]);
                MMAB(s[nt], ql[ks], kh[ks][0], kh[ks][1]);
            }
        }

        // ---- causal mask
        if (kt >= nkt - 2) {
            int qr = q0 + w * 16 + (lane >> 2);
#pragma unroll
            for (int nt = 0; nt < 8; nt++) {
                int kc = kt * 64 + nt * 8 + (lane & 3) * 2;
                if (kc     > qr)     s[nt][0] = -1e30f;
                if (kc + 1 > qr)     s[nt][1] = -1e30f;
                if (kc     > qr + 8) s[nt][2] = -1e30f;
                if (kc + 1 > qr + 8) s[nt][3] = -1e30f;
            }
        }

        // ---- online softmax (exp2 domain)
        float mx0 = -1e30f, mx1 = -1e30f;
#pragma unroll
        for (int nt = 0; nt < 8; nt++) {
            mx0 = fmaxf(mx0, fmaxf(s[nt][0], s[nt][1]));
            mx1 = fmaxf(mx1, fmaxf(s[nt][2], s[nt][3]));
        }
        mx0 = fmaxf(mx0, __shfl_xor_sync(0xffffffffu, mx0, 1));
        mx0 = fmaxf(mx0, __shfl_xor_sync(0xffffffffu, mx0, 2));
        mx1 = fmaxf(mx1, __shfl_xor_sync(0xffffffffu, mx1, 1));
        mx1 = fmaxf(mx1, __shfl_xor_sync(0xffffffffu, mx1, 2));
        float mn0 = fmaxf(m0, mx0), mn1 = fmaxf(m1, mx1);
        float c0 = ex2(m0 - mn0), c1 = ex2(m1 - mn1);
        m0 = mn0; m1 = mn1;
        l0 *= c0; l1 *= c1;
#pragma unroll
        for (int dt = 0; dt < 8; dt++) {
            ctx[dt][0] *= c0; ctx[dt][1] *= c0;
            ctx[dt][2] *= c1; ctx[dt][3] *= c1;
        }

        // ---- per-j: exp, pack P (single fp16), PV = Ph Vh + Ph Vl
        const uint32_t sv = sk + 16384;
#pragma unroll
        for (int j = 0; j < 4; j++) {
            float p00 = ex2(s[2*j][0] - mn0),   p01 = ex2(s[2*j][1] - mn0);
            float p02 = ex2(s[2*j][2] - mn1),   p03 = ex2(s[2*j][3] - mn1);
            float p10 = ex2(s[2*j+1][0] - mn0), p11 = ex2(s[2*j+1][1] - mn0);
            float p12 = ex2(s[2*j+1][2] - mn1), p13 = ex2(s[2*j+1][3] - mn1);
            l0 += (p00 + p01) + (p10 + p11);
            l1 += (p02 + p03) + (p12 + p13);
            uint32_t ph[4];
            ph[0] = h2(p00, p01);
            ph[1] = h2(p02, p03);
            ph[2] = h2(p10, p11);
            ph[3] = h2(p12, p13);

            uint32_t vf[8][2];
#pragma unroll
            for (int dp = 0; dp < 4; dp++) {
                uint32_t d = swz((uint32_t)(j * 16 + (lane & 15)) * 128 + dp * 32 + (lane >> 4) * 16);
                asm volatile("ldmatrix.sync.aligned.m8n8.x4.trans.shared.b16 {%0,%1,%2,%3}, [%4];"
                             : "=r"(vf[2*dp][0]), "=r"(vf[2*dp][1]),
                               "=r"(vf[2*dp+1][0]), "=r"(vf[2*dp+1][1]) : "r"(sv + d));
            }
#pragma unroll
            for (int dt = 0; dt < 8; dt++)
                MMAH(ctx[dt], ph, vf[dt][0], vf[dt][1]);
#pragma unroll
            for (int dp = 0; dp < 4; dp++) {
                uint32_t d = swz((uint32_t)(j * 16 + (lane & 15)) * 128 + dp * 32 + (lane >> 4) * 16);
                asm volatile("ldmatrix.sync.aligned.m8n8.x4.trans.shared.b16 {%0,%1,%2,%3}, [%4];"
                             : "=r"(vf[2*dp][0]), "=r"(vf[2*dp][1]),
                               "=r"(vf[2*dp+1][0]), "=r"(vf[2*dp+1][1]) : "r"(sv + 8192 + d));
            }
#pragma unroll
            for (int dt = 0; dt < 8; dt++)
                MMAH(ctx[dt], ph, vf[dt][0], vf[dt][1]);
        }
    }

    // ---- finalize: row sums, normalize, store ctx as single fp16 [M, DMODEL]
    l0 += __shfl_xor_sync(0xffffffffu, l0, 1);
    l0 += __shfl_xor_sync(0xffffffffu, l0, 2);
    l1 += __shfl_xor_sync(0xffffffffu, l1, 1);
    l1 += __shfl_xor_sync(0xffffffffu, l1, 2);
    float rinv0 = 1.f / l0, rinv1 = 1.f / l1;

    int qr = q0 + w * 16 + (lane >> 2);
    size_t row0 = ((size_t)b * SEQ + qr) * DMODEL;
    size_t row1 = row0 + 8 * DMODEL;
    int cbase = h * HDIM + (lane & 3) * 2;
#pragma unroll
    for (int dt = 0; dt < 8; dt++) {
        int cc = cbase + dt * 8;
        *(uint32_t*)&g_actxh[row0 + cc] = h2(ctx[dt][0] * rinv0, ctx[dt][1] * rinv0);
        *(uint32_t*)&g_actxh[row1 + cc] = h2(ctx[dt][2] * rinv1, ctx[dt][3] * rinv1);
    }
}

// ---------------------------------------------------------------------------
// Launch
// ---------------------------------------------------------------------------
extern "C" void kernel_launch(void* const* d_in, const int* in_sizes, int n_in,
                              void* d_out, int out_size)
{
    const float* x  = (const float*)d_in[0];
    const float* wq = (const float*)d_in[1];
    const float* bq = (const float*)d_in[2];
    const float* wk = (const float*)d_in[3];
    const float* bk = (const float*)d_in[4];
    const float* wv = (const float*)d_in[5];
    const float* bv = (const float*)d_in[6];
    const float* wo = (const float*)d_in[7];
    const float* bo = (const float*)d_in[8];
    float* out = (float*)d_out;
    (void)in_sizes; (void)n_in; (void)out_size;

    cudaFuncSetAttribute(qkv_tc_kernel, cudaFuncAttributeMaxDynamicSharedMemorySize, GEMM_SMEM);
    cudaFuncSetAttribute(out_tc_kernel, cudaFuncAttributeMaxDynamicSharedMemorySize, GEMM_SMEM);
    cudaFuncSetAttribute(attn_tc_kernel, cudaFuncAttributeMaxDynamicSharedMemorySize, ATT_SMEM);

    wsplit_kernel<<<dim3(32, 32, 4), 256>>>(wq, wk, wv, wo);
    split_kernel<<<MROWS * (DMODEL / 4) / 256, 256>>>(x);
    qkv_tc_kernel<<<dim3(DMODEL / 128, MROWS / 128, 3), 256, GEMM_SMEM>>>(bq, bk, bv);
    attn_tc_kernel<<<dim3(SEQ / 128, NHEAD, BATCH), 256, ATT_SMEM>>>();
    out_tc_kernel<<<dim3(DMODEL / 128, MROWS / 128), 256, GEMM_SMEM>>>(bo, out);
}

// round 9
// speedup vs baseline: 4.9939x; 1.2970x over previous
#include <cuda_runtime.h>
#include <cuda_bf16.h>
#include <cuda_fp16.h>
#include <cstdint>

// ---------------------------------------------------------------------------
// Problem constants
// ---------------------------------------------------------------------------
#define BATCH   4
#define SEQ     2048
#define DMODEL  1024
#define NHEAD   16
#define HDIM    64
#define MROWS   (BATCH * SEQ)          // 8192
#define QSCALE  0.18033688011112042f   // log2(e) / sqrt(HDIM)

// ---------------------------------------------------------------------------
// Scratch (device globals: allocation-free, graph-capture safe)
// All fp16 now: 2-term splits cover fp32 inputs to ~22 mantissa bits.
// ---------------------------------------------------------------------------
__device__ __half g_qh[MROWS * DMODEL];                 // [b,h,s,d] Q hi (pre-scaled)
__device__ __half g_ql[MROWS * DMODEL];                 // Q lo
__device__ __half g_kh[MROWS * DMODEL];                 // K single fp16
__device__ __half g_vh[MROWS * DMODEL];                 // V hi
__device__ __half g_vl[MROWS * DMODEL];                 // V lo
__device__ __half g_ax[(size_t)MROWS * 2 * DMODEL];     // x split [M, 2K] = [Ah|Al]
__device__ __half g_actxh[MROWS * DMODEL];              // ctx, single fp16 [M, K]
__device__ __half g_bw[(size_t)3 * DMODEL * DMODEL];    // Wq/Wk/Wv^T single fp16 [3][N, K]
__device__ __half g_bwo[(size_t)DMODEL * 2 * DMODEL];   // Wo^T [N, 2K] = [hi|lo]

// ---------------------------------------------------------------------------
// PTX helpers — arch-agnostic (sm_80-class) only: harness targets sm_103.
// ---------------------------------------------------------------------------
__device__ __forceinline__ uint32_t smem_u32(const void* p) {
    uint32_t a;
    asm("{ .reg .u64 t; cvta.to.shared.u64 t, %1; cvt.u32.u64 %0, t; }" : "=r"(a) : "l"(p));
    return a;
}
__device__ __forceinline__ void cp_async16(uint32_t dst, const void* src) {
    size_t g = __cvta_generic_to_global(src);
    asm volatile("cp.async.cg.shared.global [%0], [%1], 16;" :: "r"(dst), "l"(g) : "memory");
}
__device__ __forceinline__ void cp_commit() {
    asm volatile("cp.async.commit_group;" ::: "memory");
}
template <int N>
__device__ __forceinline__ void cp_wait() {
    asm volatile("cp.async.wait_group %0;" :: "n"(N) : "memory");
}
__device__ __forceinline__ uint32_t swz(uint32_t b) {   // Swizzle<3,4,3> on 128B rows
    return b ^ ((b >> 3) & 0x70);
}
__device__ __forceinline__ float ex2(float x) {
    float y;
    asm("ex2.approx.ftz.f32 %0, %1;" : "=f"(y) : "f"(x));
    return y;
}
__device__ __forceinline__ uint32_t h2(float a, float b) {
    __half2 h = __floats2half2_rn(a, b);
    return *reinterpret_cast<uint32_t*>(&h);
}
// fp16 hi/lo pair
__device__ __forceinline__ void split_pack_h(float a, float b, uint32_t& hp, uint32_t& lp) {
    __half ah = __float2half_rn(a);
    __half bh = __float2half_rn(b);
    float al = a - __half2float(ah);
    float bl = b - __half2float(bh);
    __half2 hh = __halves2half2(ah, bh);
    hp = *reinterpret_cast<uint32_t*>(&hh);
    lp = h2(al, bl);
}

#define MMAH(acc, a, b0, b1)                                                         \
    asm volatile(                                                                    \
        "mma.sync.aligned.m16n8k16.row.col.f32.f16.f16.f32 "                         \
        "{%0,%1,%2,%3}, {%4,%5,%6,%7}, {%8,%9}, {%0,%1,%2,%3};"                      \
        : "+f"((acc)[0]), "+f"((acc)[1]), "+f"((acc)[2]), "+f"((acc)[3])             \
        : "r"((a)[0]), "r"((a)[1]), "r"((a)[2]), "r"((a)[3]), "r"(b0), "r"(b1))

#define LDSM4(r, addr)                                                               \
    asm volatile("ldmatrix.sync.aligned.m8n8.x4.shared.b16 {%0,%1,%2,%3}, [%4];"     \
                 : "=r"((r)[0]), "=r"((r)[1]), "=r"((r)[2]), "=r"((r)[3]) : "r"(addr))

// ---------------------------------------------------------------------------
// Split conversions (host-input preprocessing)
// ---------------------------------------------------------------------------
__global__ void split_kernel(const float* __restrict__ in)   // x -> g_ax [Ah|Al] fp16
{
    int idx = blockIdx.x * 256 + threadIdx.x;
    int m   = idx >> 8;
    int k4  = (idx & 255) * 4;
    float4 v = *(const float4*)&in[(size_t)m * DMODEL + k4];
    uint2 hp, lp;
    split_pack_h(v.x, v.y, hp.x, lp.x);
    split_pack_h(v.z, v.w, hp.y, lp.y);
    size_t ro = (size_t)m * 2 * DMODEL;
    *(uint2*)&g_ax[ro + k4]          = hp;
    *(uint2*)&g_ax[ro + DMODEL + k4] = lp;
}

// Weight transpose + split. z 0..2: single fp16 -> g_bw. z==3: fp16 2-seg -> g_bwo.
__global__ void wsplit_kernel(const float* __restrict__ wq, const float* __restrict__ wk,
                              const float* __restrict__ wv, const float* __restrict__ wo)
{
    const float* W;
    switch (blockIdx.z) {
        case 0: W = wq; break; case 1: W = wk; break;
        case 2: W = wv; break; default: W = wo; break;
    }
    __shared__ float t[32][33];
    int k0 = blockIdx.x * 32, n0 = blockIdx.y * 32;
    int tx = threadIdx.x & 31, ty = threadIdx.x >> 5;
#pragma unroll
    for (int i = 0; i < 4; i++)
        t[ty + i * 8][tx] = W[(size_t)(k0 + ty + i * 8) * DMODEL + n0 + tx];
    __syncthreads();

    if (blockIdx.z < 3) {
        __half* out = g_bw + (size_t)blockIdx.z * DMODEL * DMODEL;
#pragma unroll
        for (int i = 0; i < 4; i++) {
            int nl = ty + i * 8;
            out[(size_t)(n0 + nl) * DMODEL + k0 + tx] = __float2half_rn(t[tx][nl]);
        }
    } else {
#pragma unroll
        for (int i = 0; i < 4; i++) {
            int nl = ty + i * 8;
            float v = t[tx][nl];
            __half hh = __float2half_rn(v);
            __half hl = __float2half_rn(v - __half2float(hh));
            size_t ro = (size_t)(n0 + nl) * (2 * DMODEL) + k0 + tx;
            g_bwo[ro]          = hh;
            g_bwo[ro + DMODEL] = hl;
        }
    }
}

// ---------------------------------------------------------------------------
// mma.sync fp16 GEMM, 128x128 CTA tile, BK=64, 3-stage cp.async, 2 CTAs/SM.
// KA/KB: element K extents; chunk index wraps mod (KA/64) / (KB/64), so a
// short operand is streamed repeatedly against the other's segments.
// MODE: 0 -> fp32 C+bias. 2 -> fp16 hi/lo pair out. 3 -> fp16 single out.
// ---------------------------------------------------------------------------
#define STAGES 3
#define CHUNK_BYTES 32768
#define GEMM_SMEM (STAGES * CHUNK_BYTES)

template <int MODE, int KA, int KB>
__device__ __forceinline__ void gemm_mma_body(const uint16_t* __restrict__ A,
                                              const uint16_t* __restrict__ B,
                                              const float* __restrict__ bias,
                                              float* __restrict__ C,
                                              uint16_t* __restrict__ Oh,
                                              uint16_t* __restrict__ Ol,
                                              float scale)
{
    constexpr int ACH = KA / 64;
    constexpr int BCH = KB / 64;
    constexpr int NCH = (KA > KB ? KA : KB) / 64;
    extern __shared__ char smem[];
    const uint32_t sbase = smem_u32(smem);
    const int tid  = threadIdx.x;
    const int lane = tid & 31;
    const int w    = tid >> 5;
    const int wm   = w & 1;
    const int wn   = w >> 1;
    const int m0   = blockIdx.y * 128;
    const int n0   = blockIdx.x * 128;

    const uint16_t* Abase = A + (size_t)m0 * KA;
    const uint16_t* Bbase = B + (size_t)n0 * KB;

    const int r0 = tid >> 3;
    const int u  = tid & 7;

    auto load_chunk = [&](int c) {
        uint32_t so = sbase + (uint32_t)(c % STAGES) * CHUNK_BYTES;
        const uint16_t* as = Abase + (size_t)r0 * KA + (c % ACH) * 64 + u * 8;
        const uint16_t* bs = Bbase + (size_t)r0 * KB + (c % BCH) * 64 + u * 8;
#pragma unroll
        for (int i = 0; i < 4; i++) {
            uint32_t d = swz((uint32_t)(i * 32 + r0) * 128 + u * 16);
            cp_async16(so + d,         as + (size_t)i * 32 * KA);
            cp_async16(so + 16384 + d, bs + (size_t)i * 32 * KB);
        }
        cp_commit();
    };

    float acc[4][4][4];
#pragma unroll
    for (int mi = 0; mi < 4; mi++)
#pragma unroll
        for (int ni = 0; ni < 4; ni++)
#pragma unroll
            for (int r = 0; r < 4; r++) acc[mi][ni][r] = 0.f;

    load_chunk(0);
    load_chunk(1);

    for (int c = 0; c < NCH; c++) {
        cp_wait<1>();
        __syncthreads();
        if (c + 2 < NCH) load_chunk(c + 2);

        uint32_t sa = sbase + (uint32_t)(c % STAGES) * CHUNK_BYTES;
        uint32_t sb = sa + 16384;

#pragma unroll
        for (int ks = 0; ks < 4; ks++) {
            uint32_t a[4][4], b[4][2];
#pragma unroll
            for (int mi = 0; mi < 4; mi++) {
                int r = wm * 64 + mi * 16 + (lane & 15);
                uint32_t addr = sa + swz((uint32_t)r * 128 + ks * 32 + (lane >> 4) * 16);
                LDSM4(a[mi], addr);
            }
#pragma unroll
            for (int nj = 0; nj < 2; nj++) {
                int n = wn * 32 + nj * 16 + (lane >> 4) * 8 + (lane & 7);
                uint32_t addr = sb + swz((uint32_t)n * 128 + ks * 32 + ((lane >> 3) & 1) * 16);
                asm volatile("ldmatrix.sync.aligned.m8n8.x4.shared.b16 {%0,%1,%2,%3}, [%4];"
                             : "=r"(b[nj * 2][0]), "=r"(b[nj * 2][1]),
                               "=r"(b[nj * 2 + 1][0]), "=r"(b[nj * 2 + 1][1])
                             : "r"(addr));
            }
#pragma unroll
            for (int mi = 0; mi < 4; mi++)
#pragma unroll
                for (int ni = 0; ni < 4; ni++)
                    MMAH(acc[mi][ni], a[mi], b[ni][0], b[ni][1]);
        }
    }

    const int mrow = m0 + wm * 64 + (lane >> 2);
    const int ncol = n0 + wn * 32 + (lane & 3) * 2;
#pragma unroll
    for (int mi = 0; mi < 4; mi++) {
        int r = mrow + mi * 16;
#pragma unroll
        for (int ni = 0; ni < 4; ni++) {
            int cc = ncol + ni * 8;
            float b0 = bias[cc], b1 = bias[cc + 1];
            float v0 = acc[mi][ni][0] + b0, v1 = acc[mi][ni][1] + b1;
            float v2 = acc[mi][ni][2] + b0, v3 = acc[mi][ni][3] + b1;
            if (MODE == 0) {
                *(float2*)&C[(size_t)r * DMODEL + cc]       = make_float2(v0, v1);
                *(float2*)&C[(size_t)(r + 8) * DMODEL + cc] = make_float2(v2, v3);
            } else {
                v0 *= scale; v1 *= scale; v2 *= scale; v3 *= scale;
                int bb = r >> 11, hh = cc >> 6, dd = cc & 63;
                size_t off0 = (((size_t)bb * NHEAD + hh) * SEQ + (r & 2047)) * HDIM + dd;
                size_t off1 = off0 + 8 * HDIM;
                if (MODE == 2) {
                    uint32_t hp, lp;
                    split_pack_h(v0, v1, hp, lp);
                    *(uint32_t*)&Oh[off0] = hp;
                    *(uint32_t*)&Ol[off0] = lp;
                    split_pack_h(v2, v3, hp, lp);
                    *(uint32_t*)&Oh[off1] = hp;
                    *(uint32_t*)&Ol[off1] = lp;
                } else {   // MODE 3: single fp16
                    *(uint32_t*)&Oh[off0] = h2(v0, v1);
                    *(uint32_t*)&Oh[off1] = h2(v2, v3);
                }
            }
        }
    }
}

__global__ __launch_bounds__(256, 2) void qkv_tc_kernel(
    const float* __restrict__ bq, const float* __restrict__ bk, const float* __restrict__ bv)
{
    if (blockIdx.z == 0)
        gemm_mma_body<2, 2 * DMODEL, DMODEL>((const uint16_t*)g_ax, (const uint16_t*)g_bw,
                                             bq, nullptr, (uint16_t*)g_qh, (uint16_t*)g_ql, QSCALE);
    else if (blockIdx.z == 1)
        gemm_mma_body<3, 2 * DMODEL, DMODEL>((const uint16_t*)g_ax,
                                             (const uint16_t*)(g_bw + (size_t)DMODEL * DMODEL),
                                             bk, nullptr, (uint16_t*)g_kh, nullptr, 1.f);
    else
        gemm_mma_body<2, 2 * DMODEL, DMODEL>((const uint16_t*)g_ax,
                                             (const uint16_t*)(g_bw + (size_t)2 * DMODEL * DMODEL),
                                             bv, nullptr, (uint16_t*)g_vh, (uint16_t*)g_vl, 1.f);
}

__global__ __launch_bounds__(256, 2) void out_tc_kernel(
    const float* __restrict__ bo, float* __restrict__ out)
{
    gemm_mma_body<0, DMODEL, 2 * DMODEL>((const uint16_t*)g_actxh, (const uint16_t*)g_bwo,
                                         bo, out, nullptr, nullptr, 1.f);
}

// ---------------------------------------------------------------------------
// Tensor-core causal flash attention. 2 CTAs/SM.
// QK^T: fp16 2-term (QhKh + QlKh; K single fp16). PV: fp16 P x V hi/lo.
// Smem: Qh|Ql (32KB) + 2 x (Kh|Vh|Vl) (2x24KB) = 80KB.
// ---------------------------------------------------------------------------
#define ATT_SMEM 81920

__global__ __launch_bounds__(256, 2) void attn_tc_kernel()
{
    extern __shared__ char smem[];
    const uint32_t sb = smem_u32(smem);
    const int tid  = threadIdx.x;
    const int lane = tid & 31;
    const int w    = tid >> 5;
    const int qt   = (int)(gridDim.x - 1 - blockIdx.x);   // heavy tiles first
    const int h    = blockIdx.y, b = blockIdx.z;
    const int q0   = qt * 128;
    const int nkt  = 2 * qt + 2;
    const size_t bh = ((size_t)b * NHEAD + h) * SEQ * HDIM;
    const __half *Qhp = g_qh + bh, *Qlp = g_ql + bh;
    const __half *Khp = g_kh + bh;
    const __half *Vhp = g_vh + bh, *Vlp = g_vl + bh;

    const int u  = tid & 7;
    const int r8 = tid >> 3;

    // ---- stage Q (q0..q0+127, hi+lo)
#pragma unroll
    for (int i = 0; i < 4; i++) {
        int row = r8 + 32 * i;
        uint32_t d = swz((uint32_t)row * 128 + u * 16);
        cp_async16(sb + d,         Qhp + (size_t)(q0 + row) * HDIM + u * 8);
        cp_async16(sb + 16384 + d, Qlp + (size_t)(q0 + row) * HDIM + u * 8);
    }
    cp_commit();

    auto load_kv = [&](int kt) {
        uint32_t so = sb + 32768 + (uint32_t)(kt & 1) * 24576;
        int kbase = kt * 64;
#pragma unroll
        for (int i = 0; i < 2; i++) {
            int row = r8 + 32 * i;
            uint32_t d = swz((uint32_t)row * 128 + u * 16);
            size_t g = (size_t)(kbase + row) * HDIM + u * 8;
            cp_async16(so + d,         Khp + g);
            cp_async16(so + 8192 + d,  Vhp + g);
            cp_async16(so + 16384 + d, Vlp + g);
        }
        cp_commit();
    };
    load_kv(0);
    cp_wait<0>();
    __syncthreads();

    // ---- resident Q fragments
    uint32_t qh[4][4], ql[4][4];
#pragma unroll
    for (int ks = 0; ks < 4; ks++) {
        uint32_t d = swz((uint32_t)(w * 16 + (lane & 15)) * 128 + ks * 32 + (lane >> 4) * 16);
        LDSM4(qh[ks], sb + d);
        LDSM4(ql[ks], sb + 16384 + d);
    }

    float ctx[8][4];
#pragma unroll
    for (int dt = 0; dt < 8; dt++)
#pragma unroll
        for (int r = 0; r < 4; r++) ctx[dt][r] = 0.f;
    float m0 = -1e30f, m1 = -1e30f, l0 = 0.f, l1 = 0.f;

    for (int kt = 0; kt < nkt; kt++) {
        cp_wait<0>();
        __syncthreads();
        if (kt + 1 < nkt) load_kv(kt + 1);
        const uint32_t sk = sb + 32768 + (uint32_t)(kt & 1) * 24576;

        // ---- S = Q K^T  (Qh Kh + Ql Kh), fp16 2-term
        float s[8][4];
#pragma unroll
        for (int nt = 0; nt < 8; nt++) {
            s[nt][0] = s[nt][1] = s[nt][2] = s[nt][3] = 0.f;
            uint32_t kh[4][2];
#pragma unroll
            for (int hf = 0; hf < 2; hf++) {
                uint32_t d = swz((uint32_t)(nt * 8 + (lane & 7)) * 128 + hf * 64 + (lane >> 3) * 16);
                asm volatile("ldmatrix.sync.aligned.m8n8.x4.shared.b16 {%0,%1,%2,%3}, [%4];"
                             : "=r"(kh[2*hf][0]), "=r"(kh[2*hf][1]),
                               "=r"(kh[2*hf+1][0]), "=r"(kh[2*hf+1][1]) : "r"(sk + d));
            }
#pragma unroll
            for (int ks = 0; ks < 4; ks++) {
                MMAH(s[nt], qh[ks], kh[ks][0], kh[ks][1]);
                MMAH(s[nt], ql[ks], kh[ks][0], kh[ks][1]);
            }
        }

        // ---- causal mask
        if (kt >= nkt - 2) {
            int qr = q0 + w * 16 + (lane >> 2);
#pragma unroll
            for (int nt = 0; nt < 8; nt++) {
                int kc = kt * 64 + nt * 8 + (lane & 3) * 2;
                if (kc     > qr)     s[nt][0] = -1e30f;
                if (kc + 1 > qr)     s[nt][1] = -1e30f;
                if (kc     > qr + 8) s[nt][2] = -1e30f;
                if (kc + 1 > qr + 8) s[nt][3] = -1e30f;
            }
        }

        // ---- online softmax (exp2 domain)
        float mx0 = -1e30f, mx1 = -1e30f;
#pragma unroll
        for (int nt = 0; nt < 8; nt++) {
            mx0 = fmaxf(mx0, fmaxf(s[nt][0], s[nt][1]));
            mx1 = fmaxf(mx1, fmaxf(s[nt][2], s[nt][3]));
        }
        mx0 = fmaxf(mx0, __shfl_xor_sync(0xffffffffu, mx0, 1));
        mx0 = fmaxf(mx0, __shfl_xor_sync(0xffffffffu, mx0, 2));
        mx1 = fmaxf(mx1, __shfl_xor_sync(0xffffffffu, mx1, 1));
        mx1 = fmaxf(mx1, __shfl_xor_sync(0xffffffffu, mx1, 2));
        float mn0 = fmaxf(m0, mx0), mn1 = fmaxf(m1, mx1);
        float c0 = ex2(m0 - mn0), c1 = ex2(m1 - mn1);
        m0 = mn0; m1 = mn1;
        l0 *= c0; l1 *= c1;
#pragma unroll
        for (int dt = 0; dt < 8; dt++) {
            ctx[dt][0] *= c0; ctx[dt][1] *= c0;
            ctx[dt][2] *= c1; ctx[dt][3] *= c1;
        }

        // ---- per-j: exp, pack P (single fp16), PV = Ph Vh + Ph Vl
        const uint32_t sv = sk + 8192;
#pragma unroll
        for (int j = 0; j < 4; j++) {
            float p00 = ex2(s[2*j][0] - mn0),   p01 = ex2(s[2*j][1] - mn0);
            float p02 = ex2(s[2*j][2] - mn1),   p03 = ex2(s[2*j][3] - mn1);
            float p10 = ex2(s[2*j+1][0] - mn0), p11 = ex2(s[2*j+1][1] - mn0);
            float p12 = ex2(s[2*j+1][2] - mn1), p13 = ex2(s[2*j+1][3] - mn1);
            l0 += (p00 + p01) + (p10 + p11);
            l1 += (p02 + p03) + (p12 + p13);
            uint32_t ph[4];
            ph[0] = h2(p00, p01);
            ph[1] = h2(p02, p03);
            ph[2] = h2(p10, p11);
            ph[3] = h2(p12, p13);

            uint32_t vf[8][2];
#pragma unroll
            for (int dp = 0; dp < 4; dp++) {
                uint32_t d = swz((uint32_t)(j * 16 + (lane & 15)) * 128 + dp * 32 + (lane >> 4) * 16);
                asm volatile("ldmatrix.sync.aligned.m8n8.x4.trans.shared.b16 {%0,%1,%2,%3}, [%4];"
                             : "=r"(vf[2*dp][0]), "=r"(vf[2*dp][1]),
                               "=r"(vf[2*dp+1][0]), "=r"(vf[2*dp+1][1]) : "r"(sv + d));
            }
#pragma unroll
            for (int dt = 0; dt < 8; dt++)
                MMAH(ctx[dt], ph, vf[dt][0], vf[dt][1]);
#pragma unroll
            for (int dp = 0; dp < 4; dp++) {
                uint32_t d = swz((uint32_t)(j * 16 + (lane & 15)) * 128 + dp * 32 + (lane >> 4) * 16);
                asm volatile("ldmatrix.sync.aligned.m8n8.x4.trans.shared.b16 {%0,%1,%2,%3}, [%4];"
                             : "=r"(vf[2*dp][0]), "=r"(vf[2*dp][1]),
                               "=r"(vf[2*dp+1][0]), "=r"(vf[2*dp+1][1]) : "r"(sv + 8192 + d));
            }
#pragma unroll
            for (int dt = 0; dt < 8; dt++)
                MMAH(ctx[dt], ph, vf[dt][0], vf[dt][1]);
        }
    }

    // ---- finalize: row sums, normalize, store ctx as single fp16 [M, DMODEL]
    l0 += __shfl_xor_sync(0xffffffffu, l0, 1);
    l0 += __shfl_xor_sync(0xffffffffu, l0, 2);
    l1 += __shfl_xor_sync(0xffffffffu, l1, 1);
    l1 += __shfl_xor_sync(0xffffffffu, l1, 2);
    float rinv0 = 1.f / l0, rinv1 = 1.f / l1;

    int qr = q0 + w * 16 + (lane >> 2);
    size_t row0 = ((size_t)b * SEQ + qr) * DMODEL;
    size_t row1 = row0 + 8 * DMODEL;
    int cbase = h * HDIM + (lane & 3) * 2;
#pragma unroll
    for (int dt = 0; dt < 8; dt++) {
        int cc = cbase + dt * 8;
        *(uint32_t*)&g_actxh[row0 + cc] = h2(ctx[dt][0] * rinv0, ctx[dt][1] * rinv0);
        *(uint32_t*)&g_actxh[row1 + cc] = h2(ctx[dt][2] * rinv1, ctx[dt][3] * rinv1);
    }
}

// ---------------------------------------------------------------------------
// Launch
// ---------------------------------------------------------------------------
extern "C" void kernel_launch(void* const* d_in, const int* in_sizes, int n_in,
                              void* d_out, int out_size)
{
    const float* x  = (const float*)d_in[0];
    const float* wq = (const float*)d_in[1];
    const float* bq = (const float*)d_in[2];
    const float* wk = (const float*)d_in[3];
    const float* bk = (const float*)d_in[4];
    const float* wv = (const float*)d_in[5];
    const float* bv = (const float*)d_in[6];
    const float* wo = (const float*)d_in[7];
    const float* bo = (const float*)d_in[8];
    float* out = (float*)d_out;
    (void)in_sizes; (void)n_in; (void)out_size;

    cudaFuncSetAttribute(qkv_tc_kernel, cudaFuncAttributeMaxDynamicSharedMemorySize, GEMM_SMEM);
    cudaFuncSetAttribute(out_tc_kernel, cudaFuncAttributeMaxDynamicSharedMemorySize, GEMM_SMEM);
    cudaFuncSetAttribute(attn_tc_kernel, cudaFuncAttributeMaxDynamicSharedMemorySize, ATT_SMEM);

    wsplit_kernel<<<dim3(32, 32, 4), 256>>>(wq, wk, wv, wo);
    split_kernel<<<MROWS * (DMODEL / 4) / 256, 256>>>(x);
    qkv_tc_kernel<<<dim3(DMODEL / 128, MROWS / 128, 3), 256, GEMM_SMEM>>>(bq, bk, bv);
    attn_tc_kernel<<<dim3(SEQ / 128, NHEAD, BATCH), 256, ATT_SMEM>>>();
    out_tc_kernel<<<dim3(DMODEL / 128, MROWS / 128), 256, GEMM_SMEM>>>(bo, out);
}

// round 10
// speedup vs baseline: 5.9201x; 1.1855x over previous
#include <cuda_runtime.h>
#include <cuda_bf16.h>
#include <cuda_fp16.h>
#include <cstdint>

// ---------------------------------------------------------------------------
// Problem constants
// ---------------------------------------------------------------------------
#define BATCH   4
#define SEQ     2048
#define DMODEL  1024
#define NHEAD   16
#define HDIM    64
#define MROWS   (BATCH * SEQ)          // 8192
#define QSCALE  0.18033688011112042f   // log2(e) / sqrt(HDIM)

// ---------------------------------------------------------------------------
// Scratch (device globals: allocation-free, graph-capture safe)
// ---------------------------------------------------------------------------
__device__ __half g_qh[MROWS * DMODEL];                 // [b,h,s,d] Q hi (pre-scaled)
__device__ __half g_ql[MROWS * DMODEL];                 // Q lo
__device__ __half g_kh[MROWS * DMODEL];                 // K single fp16
__device__ __half g_vh[MROWS * DMODEL];                 // V single fp16
__device__ __half g_ax[(size_t)MROWS * 2 * DMODEL];     // x split [M, 2K] = [Ah|Al]
__device__ __half g_actxh[MROWS * DMODEL];              // ctx, single fp16 [M, K]
__device__ __half g_bw[(size_t)3 * DMODEL * DMODEL];    // Wq/Wk/Wv^T single fp16 [3][N, K]
__device__ __half g_bwo[(size_t)DMODEL * DMODEL];       // Wo^T single fp16 [N, K]

// ---------------------------------------------------------------------------
// PTX helpers — arch-agnostic (sm_80-class) only: harness targets sm_103.
// ---------------------------------------------------------------------------
__device__ __forceinline__ uint32_t smem_u32(const void* p) {
    uint32_t a;
    asm("{ .reg .u64 t; cvta.to.shared.u64 t, %1; cvt.u32.u64 %0, t; }" : "=r"(a) : "l"(p));
    return a;
}
__device__ __forceinline__ void cp_async16(uint32_t dst, const void* src) {
    size_t g = __cvta_generic_to_global(src);
    asm volatile("cp.async.cg.shared.global [%0], [%1], 16;" :: "r"(dst), "l"(g) : "memory");
}
__device__ __forceinline__ void cp_commit() {
    asm volatile("cp.async.commit_group;" ::: "memory");
}
template <int N>
__device__ __forceinline__ void cp_wait() {
    asm volatile("cp.async.wait_group %0;" :: "n"(N) : "memory");
}
__device__ __forceinline__ uint32_t swz(uint32_t b) {   // Swizzle<3,4,3> on 128B rows
    return b ^ ((b >> 3) & 0x70);
}
__device__ __forceinline__ float ex2(float x) {
    float y;
    asm("ex2.approx.ftz.f32 %0, %1;" : "=f"(y) : "f"(x));
    return y;
}
__device__ __forceinline__ uint32_t h2(float a, float b) {
    __half2 h = __floats2half2_rn(a, b);
    return *reinterpret_cast<uint32_t*>(&h);
}
// fp16 hi/lo pair
__device__ __forceinline__ void split_pack_h(float a, float b, uint32_t& hp, uint32_t& lp) {
    __half ah = __float2half_rn(a);
    __half bh = __float2half_rn(b);
    float al = a - __half2float(ah);
    float bl = b - __half2float(bh);
    __half2 hh = __halves2half2(ah, bh);
    hp = *reinterpret_cast<uint32_t*>(&hh);
    lp = h2(al, bl);
}

#define MMAH(acc, a, b0, b1)                                                         \
    asm volatile(                                                                    \
        "mma.sync.aligned.m16n8k16.row.col.f32.f16.f16.f32 "                         \
        "{%0,%1,%2,%3}, {%4,%5,%6,%7}, {%8,%9}, {%0,%1,%2,%3};"                      \
        : "+f"((acc)[0]), "+f"((acc)[1]), "+f"((acc)[2]), "+f"((acc)[3])             \
        : "r"((a)[0]), "r"((a)[1]), "r"((a)[2]), "r"((a)[3]), "r"(b0), "r"(b1))

#define LDSM4(r, addr)                                                               \
    asm volatile("ldmatrix.sync.aligned.m8n8.x4.shared.b16 {%0,%1,%2,%3}, [%4];"     \
                 : "=r"((r)[0]), "=r"((r)[1]), "=r"((r)[2]), "=r"((r)[3]) : "r"(addr))

// ---------------------------------------------------------------------------
// Split conversions (host-input preprocessing)
// ---------------------------------------------------------------------------
__global__ void split_kernel(const float* __restrict__ in)   // x -> g_ax [Ah|Al] fp16
{
    int idx = blockIdx.x * 256 + threadIdx.x;
    int m   = idx >> 8;
    int k4  = (idx & 255) * 4;
    float4 v = *(const float4*)&in[(size_t)m * DMODEL + k4];
    uint2 hp, lp;
    split_pack_h(v.x, v.y, hp.x, lp.x);
    split_pack_h(v.z, v.w, hp.y, lp.y);
    size_t ro = (size_t)m * 2 * DMODEL;
    *(uint2*)&g_ax[ro + k4]          = hp;
    *(uint2*)&g_ax[ro + DMODEL + k4] = lp;
}

// Weight transpose + fp16 convert: z 0..2 -> g_bw, z==3 -> g_bwo (all single fp16).
__global__ void wsplit_kernel(const float* __restrict__ wq, const float* __restrict__ wk,
                              const float* __restrict__ wv, const float* __restrict__ wo)
{
    const float* W;
    switch (blockIdx.z) {
        case 0: W = wq; break; case 1: W = wk; break;
        case 2: W = wv; break; default: W = wo; break;
    }
    __shared__ float t[32][33];
    int k0 = blockIdx.x * 32, n0 = blockIdx.y * 32;
    int tx = threadIdx.x & 31, ty = threadIdx.x >> 5;
#pragma unroll
    for (int i = 0; i < 4; i++)
        t[ty + i * 8][tx] = W[(size_t)(k0 + ty + i * 8) * DMODEL + n0 + tx];
    __syncthreads();

    __half* out = (blockIdx.z < 3) ? (g_bw + (size_t)blockIdx.z * DMODEL * DMODEL) : g_bwo;
#pragma unroll
    for (int i = 0; i < 4; i++) {
        int nl = ty + i * 8;
        out[(size_t)(n0 + nl) * DMODEL + k0 + tx] = __float2half_rn(t[tx][nl]);
    }
}

// ---------------------------------------------------------------------------
// mma.sync fp16 GEMM, 128x128 CTA tile, BK=64, 3-stage cp.async, 2 CTAs/SM.
// KA/KB: element K extents; chunk index wraps mod (KA/64) / (KB/64).
// MODE: 0 -> fp32 C+bias. 2 -> fp16 hi/lo pair out. 3 -> fp16 single out.
// ---------------------------------------------------------------------------
#define STAGES 3
#define CHUNK_BYTES 32768
#define GEMM_SMEM (STAGES * CHUNK_BYTES)

template <int MODE, int KA, int KB>
__device__ __forceinline__ void gemm_mma_body(const uint16_t* __restrict__ A,
                                              const uint16_t* __restrict__ B,
                                              const float* __restrict__ bias,
                                              float* __restrict__ C,
                                              uint16_t* __restrict__ Oh,
                                              uint16_t* __restrict__ Ol,
                                              float scale)
{
    constexpr int ACH = KA / 64;
    constexpr int BCH = KB / 64;
    constexpr int NCH = (KA > KB ? KA : KB) / 64;
    extern __shared__ char smem[];
    const uint32_t sbase = smem_u32(smem);
    const int tid  = threadIdx.x;
    const int lane = tid & 31;
    const int w    = tid >> 5;
    const int wm   = w & 1;
    const int wn   = w >> 1;
    const int m0   = blockIdx.y * 128;
    const int n0   = blockIdx.x * 128;

    const uint16_t* Abase = A + (size_t)m0 * KA;
    const uint16_t* Bbase = B + (size_t)n0 * KB;

    const int r0 = tid >> 3;
    const int u  = tid & 7;

    auto load_chunk = [&](int c) {
        uint32_t so = sbase + (uint32_t)(c % STAGES) * CHUNK_BYTES;
        const uint16_t* as = Abase + (size_t)r0 * KA + (c % ACH) * 64 + u * 8;
        const uint16_t* bs = Bbase + (size_t)r0 * KB + (c % BCH) * 64 + u * 8;
#pragma unroll
        for (int i = 0; i < 4; i++) {
            uint32_t d = swz((uint32_t)(i * 32 + r0) * 128 + u * 16);
            cp_async16(so + d,         as + (size_t)i * 32 * KA);
            cp_async16(so + 16384 + d, bs + (size_t)i * 32 * KB);
        }
        cp_commit();
    };

    float acc[4][4][4];
#pragma unroll
    for (int mi = 0; mi < 4; mi++)
#pragma unroll
        for (int ni = 0; ni < 4; ni++)
#pragma unroll
            for (int r = 0; r < 4; r++) acc[mi][ni][r] = 0.f;

    load_chunk(0);
    load_chunk(1);

    for (int c = 0; c < NCH; c++) {
        cp_wait<1>();
        __syncthreads();
        if (c + 2 < NCH) load_chunk(c + 2);

        uint32_t sa = sbase + (uint32_t)(c % STAGES) * CHUNK_BYTES;
        uint32_t sb = sa + 16384;

#pragma unroll
        for (int ks = 0; ks < 4; ks++) {
            uint32_t a[4][4], b[4][2];
#pragma unroll
            for (int mi = 0; mi < 4; mi++) {
                int r = wm * 64 + mi * 16 + (lane & 15);
                uint32_t addr = sa + swz((uint32_t)r * 128 + ks * 32 + (lane >> 4) * 16);
                LDSM4(a[mi], addr);
            }
#pragma unroll
            for (int nj = 0; nj < 2; nj++) {
                int n = wn * 32 + nj * 16 + (lane >> 4) * 8 + (lane & 7);
                uint32_t addr = sb + swz((uint32_t)n * 128 + ks * 32 + ((lane >> 3) & 1) * 16);
                asm volatile("ldmatrix.sync.aligned.m8n8.x4.shared.b16 {%0,%1,%2,%3}, [%4];"
                             : "=r"(b[nj * 2][0]), "=r"(b[nj * 2][1]),
                               "=r"(b[nj * 2 + 1][0]), "=r"(b[nj * 2 + 1][1])
                             : "r"(addr));
            }
#pragma unroll
            for (int mi = 0; mi < 4; mi++)
#pragma unroll
                for (int ni = 0; ni < 4; ni++)
                    MMAH(acc[mi][ni], a[mi], b[ni][0], b[ni][1]);
        }
    }

    const int mrow = m0 + wm * 64 + (lane >> 2);
    const int ncol = n0 + wn * 32 + (lane & 3) * 2;
#pragma unroll
    for (int mi = 0; mi < 4; mi++) {
        int r = mrow + mi * 16;
#pragma unroll
        for (int ni = 0; ni < 4; ni++) {
            int cc = ncol + ni * 8;
            float b0 = bias[cc], b1 = bias[cc + 1];
            float v0 = acc[mi][ni][0] + b0, v1 = acc[mi][ni][1] + b1;
            float v2 = acc[mi][ni][2] + b0, v3 = acc[mi][ni][3] + b1;
            if (MODE == 0) {
                *(float2*)&C[(size_t)r * DMODEL + cc]       = make_float2(v0, v1);
                *(float2*)&C[(size_t)(r + 8) * DMODEL + cc] = make_float2(v2, v3);
            } else {
                v0 *= scale; v1 *= scale; v2 *= scale; v3 *= scale;
                int bb = r >> 11, hh = cc >> 6, dd = cc & 63;
                size_t off0 = (((size_t)bb * NHEAD + hh) * SEQ + (r & 2047)) * HDIM + dd;
                size_t off1 = off0 + 8 * HDIM;
                if (MODE == 2) {
                    uint32_t hp, lp;
                    split_pack_h(v0, v1, hp, lp);
                    *(uint32_t*)&Oh[off0] = hp;
                    *(uint32_t*)&Ol[off0] = lp;
                    split_pack_h(v2, v3, hp, lp);
                    *(uint32_t*)&Oh[off1] = hp;
                    *(uint32_t*)&Ol[off1] = lp;
                } else {   // MODE 3: single fp16
                    *(uint32_t*)&Oh[off0] = h2(v0, v1);
                    *(uint32_t*)&Oh[off1] = h2(v2, v3);
                }
            }
        }
    }
}

__global__ __launch_bounds__(256, 2) void qkv_tc_kernel(
    const float* __restrict__ bq, const float* __restrict__ bk, const float* __restrict__ bv)
{
    if (blockIdx.z == 0)
        gemm_mma_body<2, 2 * DMODEL, DMODEL>((const uint16_t*)g_ax, (const uint16_t*)g_bw,
                                             bq, nullptr, (uint16_t*)g_qh, (uint16_t*)g_ql, QSCALE);
    else if (blockIdx.z == 1)
        gemm_mma_body<3, 2 * DMODEL, DMODEL>((const uint16_t*)g_ax,
                                             (const uint16_t*)(g_bw + (size_t)DMODEL * DMODEL),
                                             bk, nullptr, (uint16_t*)g_kh, nullptr, 1.f);
    else
        gemm_mma_body<3, 2 * DMODEL, DMODEL>((const uint16_t*)g_ax,
                                             (const uint16_t*)(g_bw + (size_t)2 * DMODEL * DMODEL),
                                             bv, nullptr, (uint16_t*)g_vh, nullptr, 1.f);
}

__global__ __launch_bounds__(256, 2) void out_tc_kernel(
    const float* __restrict__ bo, float* __restrict__ out)
{
    gemm_mma_body<0, DMODEL, DMODEL>((const uint16_t*)g_actxh, (const uint16_t*)g_bwo,
                                     bo, out, nullptr, nullptr, 1.f);
}

// ---------------------------------------------------------------------------
// Tensor-core causal flash attention. 2 CTAs/SM.
// QK^T: fp16 2-term (QhKh + QlKh). PV: fp16 single-term (Ph Vh).
// Smem: Qh|Ql (32KB) + 2 x (Kh|Vh) (2x16KB) = 64KB.
// ---------------------------------------------------------------------------
#define ATT_SMEM 65536

__global__ __launch_bounds__(256, 2) void attn_tc_kernel()
{
    extern __shared__ char smem[];
    const uint32_t sb = smem_u32(smem);
    const int tid  = threadIdx.x;
    const int lane = tid & 31;
    const int w    = tid >> 5;
    const int qt   = (int)(gridDim.x - 1 - blockIdx.x);   // heavy tiles first
    const int h    = blockIdx.y, b = blockIdx.z;
    const int q0   = qt * 128;
    const int nkt  = 2 * qt + 2;
    const size_t bh = ((size_t)b * NHEAD + h) * SEQ * HDIM;
    const __half *Qhp = g_qh + bh, *Qlp = g_ql + bh;
    const __half *Khp = g_kh + bh;
    const __half *Vhp = g_vh + bh;

    const int u  = tid & 7;
    const int r8 = tid >> 3;

    // ---- stage Q (q0..q0+127, hi+lo)
#pragma unroll
    for (int i = 0; i < 4; i++) {
        int row = r8 + 32 * i;
        uint32_t d = swz((uint32_t)row * 128 + u * 16);
        cp_async16(sb + d,         Qhp + (size_t)(q0 + row) * HDIM + u * 8);
        cp_async16(sb + 16384 + d, Qlp + (size_t)(q0 + row) * HDIM + u * 8);
    }
    cp_commit();

    auto load_kv = [&](int kt) {
        uint32_t so = sb + 32768 + (uint32_t)(kt & 1) * 16384;
        int kbase = kt * 64;
#pragma unroll
        for (int i = 0; i < 2; i++) {
            int row = r8 + 32 * i;
            uint32_t d = swz((uint32_t)row * 128 + u * 16);
            size_t g = (size_t)(kbase + row) * HDIM + u * 8;
            cp_async16(so + d,        Khp + g);
            cp_async16(so + 8192 + d, Vhp + g);
        }
        cp_commit();
    };
    load_kv(0);
    cp_wait<0>();
    __syncthreads();

    // ---- resident Q fragments
    uint32_t qh[4][4], ql[4][4];
#pragma unroll
    for (int ks = 0; ks < 4; ks++) {
        uint32_t d = swz((uint32_t)(w * 16 + (lane & 15)) * 128 + ks * 32 + (lane >> 4) * 16);
        LDSM4(qh[ks], sb + d);
        LDSM4(ql[ks], sb + 16384 + d);
    }

    float ctx[8][4];
#pragma unroll
    for (int dt = 0; dt < 8; dt++)
#pragma unroll
        for (int r = 0; r < 4; r++) ctx[dt][r] = 0.f;
    float m0 = -1e30f, m1 = -1e30f, l0 = 0.f, l1 = 0.f;

    for (int kt = 0; kt < nkt; kt++) {
        cp_wait<0>();
        __syncthreads();
        if (kt + 1 < nkt) load_kv(kt + 1);
        const uint32_t sk = sb + 32768 + (uint32_t)(kt & 1) * 16384;

        // ---- S = Q K^T  (Qh Kh + Ql Kh), fp16 2-term
        float s[8][4];
#pragma unroll
        for (int nt = 0; nt < 8; nt++) {
            s[nt][0] = s[nt][1] = s[nt][2] = s[nt][3] = 0.f;
            uint32_t kh[4][2];
#pragma unroll
            for (int hf = 0; hf < 2; hf++) {
                uint32_t d = swz((uint32_t)(nt * 8 + (lane & 7)) * 128 + hf * 64 + (lane >> 3) * 16);
                asm volatile("ldmatrix.sync.aligned.m8n8.x4.shared.b16 {%0,%1,%2,%3}, [%4];"
                             : "=r"(kh[2*hf][0]), "=r"(kh[2*hf][1]),
                               "=r"(kh[2*hf+1][0]), "=r"(kh[2*hf+1][1]) : "r"(sk + d));
            }
#pragma unroll
            for (int ks = 0; ks < 4; ks++) {
                MMAH(s[nt], qh[ks], kh[ks][0], kh[ks][1]);
                MMAH(s[nt], ql[ks], kh[ks][0], kh[ks][1]);
            }
        }

        // ---- causal mask
        if (kt >= nkt - 2) {
            int qr = q0 + w * 16 + (lane >> 2);
#pragma unroll
            for (int nt = 0; nt < 8; nt++) {
                int kc = kt * 64 + nt * 8 + (lane & 3) * 2;
                if (kc     > qr)     s[nt][0] = -1e30f;
                if (kc + 1 > qr)     s[nt][1] = -1e30f;
                if (kc     > qr + 8) s[nt][2] = -1e30f;
                if (kc + 1 > qr + 8) s[nt][3] = -1e30f;
            }
        }

        // ---- online softmax (exp2 domain)
        float mx0 = -1e30f, mx1 = -1e30f;
#pragma unroll
        for (int nt = 0; nt < 8; nt++) {
            mx0 = fmaxf(mx0, fmaxf(s[nt][0], s[nt][1]));
            mx1 = fmaxf(mx1, fmaxf(s[nt][2], s[nt][3]));
        }
        mx0 = fmaxf(mx0, __shfl_xor_sync(0xffffffffu, mx0, 1));
        mx0 = fmaxf(mx0, __shfl_xor_sync(0xffffffffu, mx0, 2));
        mx1 = fmaxf(mx1, __shfl_xor_sync(0xffffffffu, mx1, 1));
        mx1 = fmaxf(mx1, __shfl_xor_sync(0xffffffffu, mx1, 2));
        float mn0 = fmaxf(m0, mx0), mn1 = fmaxf(m1, mx1);
        float c0 = ex2(m0 - mn0), c1 = ex2(m1 - mn1);
        m0 = mn0; m1 = mn1;
        l0 *= c0; l1 *= c1;
#pragma unroll
        for (int dt = 0; dt < 8; dt++) {
            ctx[dt][0] *= c0; ctx[dt][1] *= c0;
            ctx[dt][2] *= c1; ctx[dt][3] *= c1;
        }

        // ---- per-j: exp, pack P (single fp16), PV = Ph Vh (single-term)
        const uint32_t sv = sk + 8192;
#pragma unroll
        for (int j = 0; j < 4; j++) {
            float p00 = ex2(s[2*j][0] - mn0),   p01 = ex2(s[2*j][1] - mn0);
            float p02 = ex2(s[2*j][2] - mn1),   p03 = ex2(s[2*j][3] - mn1);
            float p10 = ex2(s[2*j+1][0] - mn0), p11 = ex2(s[2*j+1][1] - mn0);
            float p12 = ex2(s[2*j+1][2] - mn1), p13 = ex2(s[2*j+1][3] - mn1);
            l0 += (p00 + p01) + (p10 + p11);
            l1 += (p02 + p03) + (p12 + p13);
            uint32_t ph[4];
            ph[0] = h2(p00, p01);
            ph[1] = h2(p02, p03);
            ph[2] = h2(p10, p11);
            ph[3] = h2(p12, p13);

            uint32_t vf[8][2];
#pragma unroll
            for (int dp = 0; dp < 4; dp++) {
                uint32_t d = swz((uint32_t)(j * 16 + (lane & 15)) * 128 + dp * 32 + (lane >> 4) * 16);
                asm volatile("ldmatrix.sync.aligned.m8n8.x4.trans.shared.b16 {%0,%1,%2,%3}, [%4];"
                             : "=r"(vf[2*dp][0]), "=r"(vf[2*dp][1]),
                               "=r"(vf[2*dp+1][0]), "=r"(vf[2*dp+1][1]) : "r"(sv + d));
            }
#pragma unroll
            for (int dt = 0; dt < 8; dt++)
                MMAH(ctx[dt], ph, vf[dt][0], vf[dt][1]);
        }
    }

    // ---- finalize: row sums, normalize, store ctx as single fp16 [M, DMODEL]
    l0 += __shfl_xor_sync(0xffffffffu, l0, 1);
    l0 += __shfl_xor_sync(0xffffffffu, l0, 2);
    l1 += __shfl_xor_sync(0xffffffffu, l1, 1);
    l1 += __shfl_xor_sync(0xffffffffu, l1, 2);
    float rinv0 = 1.f / l0, rinv1 = 1.f / l1;

    int qr = q0 + w * 16 + (lane >> 2);
    size_t row0 = ((size_t)b * SEQ + qr) * DMODEL;
    size_t row1 = row0 + 8 * DMODEL;
    int cbase = h * HDIM + (lane & 3) * 2;
#pragma unroll
    for (int dt = 0; dt < 8; dt++) {
        int cc = cbase + dt * 8;
        *(uint32_t*)&g_actxh[row0 + cc] = h2(ctx[dt][0] * rinv0, ctx[dt][1] * rinv0);
        *(uint32_t*)&g_actxh[row1 + cc] = h2(ctx[dt][2] * rinv1, ctx[dt][3] * rinv1);
    }
}

// ---------------------------------------------------------------------------
// Launch
// ---------------------------------------------------------------------------
extern "C" void kernel_launch(void* const* d_in, const int* in_sizes, int n_in,
                              void* d_out, int out_size)
{
    const float* x  = (const float*)d_in[0];
    const float* wq = (const float*)d_in[1];
    const float* bq = (const float*)d_in[2];
    const float* wk = (const float*)d_in[3];
    const float* bk = (const float*)d_in[4];
    const float* wv = (const float*)d_in[5];
    const float* bv = (const float*)d_in[6];
    const float* wo = (const float*)d_in[7];
    const float* bo = (const float*)d_in[8];
    float* out = (float*)d_out;
    (void)in_sizes; (void)n_in; (void)out_size;

    cudaFuncSetAttribute(qkv_tc_kernel, cudaFuncAttributeMaxDynamicSharedMemorySize, GEMM_SMEM);
    cudaFuncSetAttribute(out_tc_kernel, cudaFuncAttributeMaxDynamicSharedMemorySize, GEMM_SMEM);
    cudaFuncSetAttribute(attn_tc_kernel, cudaFuncAttributeMaxDynamicSharedMemorySize, ATT_SMEM);

    wsplit_kernel<<<dim3(32, 32, 4), 256>>>(wq, wk, wv, wo);
    split_kernel<<<MROWS * (DMODEL / 4) / 256, 256>>>(x);
    qkv_tc_kernel<<<dim3(DMODEL / 128, MROWS / 128, 3), 256, GEMM_SMEM>>>(bq, bk, bv);
    attn_tc_kernel<<<dim3(SEQ / 128, NHEAD, BATCH), 256, ATT_SMEM>>>();
    out_tc_kernel<<<dim3(DMODEL / 128, MROWS / 128), 256, GEMM_SMEM>>>(bo, out);
}

// round 11
// speedup vs baseline: 8.4759x; 1.4317x over previous
#include <cuda_runtime.h>
#include <cuda_fp16.h>
#include <cstdint>

// ---------------------------------------------------------------------------
// Problem constants
// ---------------------------------------------------------------------------
#define BATCH   4
#define SEQ     2048
#define DMODEL  1024
#define NHEAD   16
#define HDIM    64
#define MROWS   (BATCH * SEQ)          // 8192
#define QSCALE  0.18033688011112042f   // log2(e) / sqrt(HDIM)

// ---------------------------------------------------------------------------
// Scratch (device globals: allocation-free, graph-capture safe). All fp16.
// ---------------------------------------------------------------------------
__device__ __half g_qh[MROWS * DMODEL];                 // [b,h,s,d] Q (pre-scaled)
__device__ __half g_kh[MROWS * DMODEL];                 // K
__device__ __half g_vh[MROWS * DMODEL];                 // V
__device__ __half g_ax[MROWS * DMODEL];                 // x fp16 [M, K]
__device__ __half g_actxh[MROWS * DMODEL];              // ctx fp16 [M, K]
__device__ __half g_bw[(size_t)3 * DMODEL * DMODEL];    // Wq/Wk/Wv^T fp16 [3][N, K]
__device__ __half g_bwo[(size_t)DMODEL * DMODEL];       // Wo^T fp16 [N, K]

// ---------------------------------------------------------------------------
// PTX helpers — arch-agnostic (sm_80-class) only: harness targets sm_103.
// ---------------------------------------------------------------------------
__device__ __forceinline__ uint32_t smem_u32(const void* p) {
    uint32_t a;
    asm("{ .reg .u64 t; cvta.to.shared.u64 t, %1; cvt.u32.u64 %0, t; }" : "=r"(a) : "l"(p));
    return a;
}
__device__ __forceinline__ void cp_async16(uint32_t dst, const void* src) {
    size_t g = __cvta_generic_to_global(src);
    asm volatile("cp.async.cg.shared.global [%0], [%1], 16;" :: "r"(dst), "l"(g) : "memory");
}
__device__ __forceinline__ void cp_commit() {
    asm volatile("cp.async.commit_group;" ::: "memory");
}
template <int N>
__device__ __forceinline__ void cp_wait() {
    asm volatile("cp.async.wait_group %0;" :: "n"(N) : "memory");
}
__device__ __forceinline__ uint32_t swz(uint32_t b) {   // Swizzle<3,4,3> on 128B rows
    return b ^ ((b >> 3) & 0x70);
}
__device__ __forceinline__ float ex2(float x) {
    float y;
    asm("ex2.approx.ftz.f32 %0, %1;" : "=f"(y) : "f"(x));
    return y;
}
__device__ __forceinline__ uint32_t h2(float a, float b) {
    __half2 h = __floats2half2_rn(a, b);
    return *reinterpret_cast<uint32_t*>(&h);
}

#define MMAH(acc, a, b0, b1)                                                         \
    asm volatile(                                                                    \
        "mma.sync.aligned.m16n8k16.row.col.f32.f16.f16.f32 "                         \
        "{%0,%1,%2,%3}, {%4,%5,%6,%7}, {%8,%9}, {%0,%1,%2,%3};"                      \
        : "+f"((acc)[0]), "+f"((acc)[1]), "+f"((acc)[2]), "+f"((acc)[3])             \
        : "r"((a)[0]), "r"((a)[1]), "r"((a)[2]), "r"((a)[3]), "r"(b0), "r"(b1))

#define LDSM4(r, addr)                                                               \
    asm volatile("ldmatrix.sync.aligned.m8n8.x4.shared.b16 {%0,%1,%2,%3}, [%4];"     \
                 : "=r"((r)[0]), "=r"((r)[1]), "=r"((r)[2]), "=r"((r)[3]) : "r"(addr))

// ---------------------------------------------------------------------------
// Conversions (host-input preprocessing)
// ---------------------------------------------------------------------------
__global__ void split_kernel(const float* __restrict__ in)   // x -> g_ax fp16
{
    int idx = blockIdx.x * 256 + threadIdx.x;     // one float4 per thread
    size_t off = (size_t)idx * 4;
    float4 v = *(const float4*)&in[off];
    uint2 hp;
    hp.x = h2(v.x, v.y);
    hp.y = h2(v.z, v.w);
    *(uint2*)&g_ax[off] = hp;
}

// Weight transpose + fp16 convert: z 0..2 -> g_bw, z==3 -> g_bwo.
__global__ void wsplit_kernel(const float* __restrict__ wq, const float* __restrict__ wk,
                              const float* __restrict__ wv, const float* __restrict__ wo)
{
    const float* W;
    switch (blockIdx.z) {
        case 0: W = wq; break; case 1: W = wk; break;
        case 2: W = wv; break; default: W = wo; break;
    }
    __shared__ float t[32][33];
    int k0 = blockIdx.x * 32, n0 = blockIdx.y * 32;
    int tx = threadIdx.x & 31, ty = threadIdx.x >> 5;
#pragma unroll
    for (int i = 0; i < 4; i++)
        t[ty + i * 8][tx] = W[(size_t)(k0 + ty + i * 8) * DMODEL + n0 + tx];
    __syncthreads();

    __half* out = (blockIdx.z < 3) ? (g_bw + (size_t)blockIdx.z * DMODEL * DMODEL) : g_bwo;
#pragma unroll
    for (int i = 0; i < 4; i++) {
        int nl = ty + i * 8;
        out[(size_t)(n0 + nl) * DMODEL + k0 + tx] = __float2half_rn(t[tx][nl]);
    }
}

// ---------------------------------------------------------------------------
// mma.sync fp16 GEMM, 128x128 CTA tile, BK=64, 3-stage cp.async, 2 CTAs/SM.
// MODE: 0 -> fp32 C+bias. 3 -> fp16 out, head-major [b,h,s,d], scaled.
// ---------------------------------------------------------------------------
#define STAGES 3
#define CHUNK_BYTES 32768
#define GEMM_SMEM (STAGES * CHUNK_BYTES)
#define KDIM DMODEL
#define NCH (KDIM / 64)    // 16

template <int MODE>
__device__ __forceinline__ void gemm_mma_body(const uint16_t* __restrict__ A,
                                              const uint16_t* __restrict__ B,
                                              const float* __restrict__ bias,
                                              float* __restrict__ C,
                                              uint16_t* __restrict__ Oh,
                                              float scale)
{
    extern __shared__ char smem[];
    const uint32_t sbase = smem_u32(smem);
    const int tid  = threadIdx.x;
    const int lane = tid & 31;
    const int w    = tid >> 5;
    const int wm   = w & 1;
    const int wn   = w >> 1;
    const int m0   = blockIdx.y * 128;
    const int n0   = blockIdx.x * 128;

    const uint16_t* Abase = A + (size_t)m0 * KDIM;
    const uint16_t* Bbase = B + (size_t)n0 * KDIM;

    const int r0 = tid >> 3;
    const int u  = tid & 7;

    auto load_chunk = [&](int c) {
        uint32_t so = sbase + (uint32_t)(c % STAGES) * CHUNK_BYTES;
        const uint16_t* as = Abase + (size_t)r0 * KDIM + c * 64 + u * 8;
        const uint16_t* bs = Bbase + (size_t)r0 * KDIM + c * 64 + u * 8;
#pragma unroll
        for (int i = 0; i < 4; i++) {
            uint32_t d = swz((uint32_t)(i * 32 + r0) * 128 + u * 16);
            cp_async16(so + d,         as + (size_t)i * 32 * KDIM);
            cp_async16(so + 16384 + d, bs + (size_t)i * 32 * KDIM);
        }
        cp_commit();
    };

    float acc[4][4][4];
#pragma unroll
    for (int mi = 0; mi < 4; mi++)
#pragma unroll
        for (int ni = 0; ni < 4; ni++)
#pragma unroll
            for (int r = 0; r < 4; r++) acc[mi][ni][r] = 0.f;

    load_chunk(0);
    load_chunk(1);

    for (int c = 0; c < NCH; c++) {
        cp_wait<1>();
        __syncthreads();
        if (c + 2 < NCH) load_chunk(c + 2);

        uint32_t sa = sbase + (uint32_t)(c % STAGES) * CHUNK_BYTES;
        uint32_t sb = sa + 16384;

#pragma unroll
        for (int ks = 0; ks < 4; ks++) {
            uint32_t a[4][4], b[4][2];
#pragma unroll
            for (int mi = 0; mi < 4; mi++) {
                int r = wm * 64 + mi * 16 + (lane & 15);
                uint32_t addr = sa + swz((uint32_t)r * 128 + ks * 32 + (lane >> 4) * 16);
                LDSM4(a[mi], addr);
            }
#pragma unroll
            for (int nj = 0; nj < 2; nj++) {
                int n = wn * 32 + nj * 16 + (lane >> 4) * 8 + (lane & 7);
                uint32_t addr = sb + swz((uint32_t)n * 128 + ks * 32 + ((lane >> 3) & 1) * 16);
                asm volatile("ldmatrix.sync.aligned.m8n8.x4.shared.b16 {%0,%1,%2,%3}, [%4];"
                             : "=r"(b[nj * 2][0]), "=r"(b[nj * 2][1]),
                               "=r"(b[nj * 2 + 1][0]), "=r"(b[nj * 2 + 1][1])
                             : "r"(addr));
            }
#pragma unroll
            for (int mi = 0; mi < 4; mi++)
#pragma unroll
                for (int ni = 0; ni < 4; ni++)
                    MMAH(acc[mi][ni], a[mi], b[ni][0], b[ni][1]);
        }
    }

    const int mrow = m0 + wm * 64 + (lane >> 2);
    const int ncol = n0 + wn * 32 + (lane & 3) * 2;
#pragma unroll
    for (int mi = 0; mi < 4; mi++) {
        int r = mrow + mi * 16;
#pragma unroll
        for (int ni = 0; ni < 4; ni++) {
            int cc = ncol + ni * 8;
            float b0 = bias[cc], b1 = bias[cc + 1];
            float v0 = acc[mi][ni][0] + b0, v1 = acc[mi][ni][1] + b1;
            float v2 = acc[mi][ni][2] + b0, v3 = acc[mi][ni][3] + b1;
            if (MODE == 0) {
                *(float2*)&C[(size_t)r * DMODEL + cc]       = make_float2(v0, v1);
                *(float2*)&C[(size_t)(r + 8) * DMODEL + cc] = make_float2(v2, v3);
            } else {   // MODE 3: fp16, head-major
                v0 *= scale; v1 *= scale; v2 *= scale; v3 *= scale;
                int bb = r >> 11, hh = cc >> 6, dd = cc & 63;
                size_t off0 = (((size_t)bb * NHEAD + hh) * SEQ + (r & 2047)) * HDIM + dd;
                size_t off1 = off0 + 8 * HDIM;
                *(uint32_t*)&Oh[off0] = h2(v0, v1);
                *(uint32_t*)&Oh[off1] = h2(v2, v3);
            }
        }
    }
}

__global__ __launch_bounds__(256, 2) void qkv_tc_kernel(
    const float* __restrict__ bq, const float* __restrict__ bk, const float* __restrict__ bv)
{
    if (blockIdx.z == 0)
        gemm_mma_body<3>((const uint16_t*)g_ax, (const uint16_t*)g_bw,
                         bq, nullptr, (uint16_t*)g_qh, QSCALE);
    else if (blockIdx.z == 1)
        gemm_mma_body<3>((const uint16_t*)g_ax,
                         (const uint16_t*)(g_bw + (size_t)DMODEL * DMODEL),
                         bk, nullptr, (uint16_t*)g_kh, 1.f);
    else
        gemm_mma_body<3>((const uint16_t*)g_ax,
                         (const uint16_t*)(g_bw + (size_t)2 * DMODEL * DMODEL),
                         bv, nullptr, (uint16_t*)g_vh, 1.f);
}

__global__ __launch_bounds__(256, 2) void out_tc_kernel(
    const float* __restrict__ bo, float* __restrict__ out)
{
    gemm_mma_body<0>((const uint16_t*)g_actxh, (const uint16_t*)g_bwo,
                     bo, out, nullptr, 1.f);
}

// ---------------------------------------------------------------------------
// Tensor-core causal flash attention. 2 CTAs/SM.
// QK^T: single fp16 term. PV: single fp16 term. exp2-domain softmax.
// Smem: Q (16KB) + 2 x (Kh|Vh) (2x16KB) = 48KB.
// ---------------------------------------------------------------------------
#define ATT_SMEM 49152

__global__ __launch_bounds__(256, 2) void attn_tc_kernel()
{
    extern __shared__ char smem[];
    const uint32_t sb = smem_u32(smem);
    const int tid  = threadIdx.x;
    const int lane = tid & 31;
    const int w    = tid >> 5;
    const int qt   = (int)(gridDim.x - 1 - blockIdx.x);   // heavy tiles first
    const int h    = blockIdx.y, b = blockIdx.z;
    const int q0   = qt * 128;
    const int nkt  = 2 * qt + 2;
    const size_t bh = ((size_t)b * NHEAD + h) * SEQ * HDIM;
    const __half *Qhp = g_qh + bh;
    const __half *Khp = g_kh + bh;
    const __half *Vhp = g_vh + bh;

    const int u  = tid & 7;
    const int r8 = tid >> 3;

    // ---- stage Q (q0..q0+127)
#pragma unroll
    for (int i = 0; i < 4; i++) {
        int row = r8 + 32 * i;
        uint32_t d = swz((uint32_t)row * 128 + u * 16);
        cp_async16(sb + d, Qhp + (size_t)(q0 + row) * HDIM + u * 8);
    }
    cp_commit();

    auto load_kv = [&](int kt) {
        uint32_t so = sb + 16384 + (uint32_t)(kt & 1) * 16384;
        int kbase = kt * 64;
#pragma unroll
        for (int i = 0; i < 2; i++) {
            int row = r8 + 32 * i;
            uint32_t d = swz((uint32_t)row * 128 + u * 16);
            size_t g = (size_t)(kbase + row) * HDIM + u * 8;
            cp_async16(so + d,        Khp + g);
            cp_async16(so + 8192 + d, Vhp + g);
        }
        cp_commit();
    };
    load_kv(0);
    cp_wait<0>();
    __syncthreads();

    // ---- resident Q fragments
    uint32_t qh[4][4];
#pragma unroll
    for (int ks = 0; ks < 4; ks++) {
        uint32_t d = swz((uint32_t)(w * 16 + (lane & 15)) * 128 + ks * 32 + (lane >> 4) * 16);
        LDSM4(qh[ks], sb + d);
    }

    float ctx[8][4];
#pragma unroll
    for (int dt = 0; dt < 8; dt++)
#pragma unroll
        for (int r = 0; r < 4; r++) ctx[dt][r] = 0.f;
    float m0 = -1e30f, m1 = -1e30f, l0 = 0.f, l1 = 0.f;

    for (int kt = 0; kt < nkt; kt++) {
        cp_wait<0>();
        __syncthreads();
        if (kt + 1 < nkt) load_kv(kt + 1);
        const uint32_t sk = sb + 16384 + (uint32_t)(kt & 1) * 16384;

        // ---- S = Q K^T  (single fp16 term)
        float s[8][4];
#pragma unroll
        for (int nt = 0; nt < 8; nt++) {
            s[nt][0] = s[nt][1] = s[nt][2] = s[nt][3] = 0.f;
            uint32_t kh[4][2];
#pragma unroll
            for (int hf = 0; hf < 2; hf++) {
                uint32_t d = swz((uint32_t)(nt * 8 + (lane & 7)) * 128 + hf * 64 + (lane >> 3) * 16);
                asm volatile("ldmatrix.sync.aligned.m8n8.x4.shared.b16 {%0,%1,%2,%3}, [%4];"
                             : "=r"(kh[2*hf][0]), "=r"(kh[2*hf][1]),
                               "=r"(kh[2*hf+1][0]), "=r"(kh[2*hf+1][1]) : "r"(sk + d));
            }
#pragma unroll
            for (int ks = 0; ks < 4; ks++)
                MMAH(s[nt], qh[ks], kh[ks][0], kh[ks][1]);
        }

        // ---- causal mask
        if (kt >= nkt - 2) {
            int qr = q0 + w * 16 + (lane >> 2);
#pragma unroll
            for (int nt = 0; nt < 8; nt++) {
                int kc = kt * 64 + nt * 8 + (lane & 3) * 2;
                if (kc     > qr)     s[nt][0] = -1e30f;
                if (kc + 1 > qr)     s[nt][1] = -1e30f;
                if (kc     > qr + 8) s[nt][2] = -1e30f;
                if (kc + 1 > qr + 8) s[nt][3] = -1e30f;
            }
        }

        // ---- online softmax (exp2 domain)
        float mx0 = -1e30f, mx1 = -1e30f;
#pragma unroll
        for (int nt = 0; nt < 8; nt++) {
            mx0 = fmaxf(mx0, fmaxf(s[nt][0], s[nt][1]));
            mx1 = fmaxf(mx1, fmaxf(s[nt][2], s[nt][3]));
        }
        mx0 = fmaxf(mx0, __shfl_xor_sync(0xffffffffu, mx0, 1));
        mx0 = fmaxf(mx0, __shfl_xor_sync(0xffffffffu, mx0, 2));
        mx1 = fmaxf(mx1, __shfl_xor_sync(0xffffffffu, mx1, 1));
        mx1 = fmaxf(mx1, __shfl_xor_sync(0xffffffffu, mx1, 2));
        float mn0 = fmaxf(m0, mx0), mn1 = fmaxf(m1, mx1);
        float c0 = ex2(m0 - mn0), c1 = ex2(m1 - mn1);
        m0 = mn0; m1 = mn1;
        l0 *= c0; l1 *= c1;
#pragma unroll
        for (int dt = 0; dt < 8; dt++) {
            ctx[dt][0] *= c0; ctx[dt][1] *= c0;
            ctx[dt][2] *= c1; ctx[dt][3] *= c1;
        }

        // ---- per-j: exp, pack P fp16, PV = P Vh
        const uint32_t sv = sk + 8192;
#pragma unroll
        for (int j = 0; j < 4; j++) {
            float p00 = ex2(s[2*j][0] - mn0),   p01 = ex2(s[2*j][1] - mn0);
            float p02 = ex2(s[2*j][2] - mn1),   p03 = ex2(s[2*j][3] - mn1);
            float p10 = ex2(s[2*j+1][0] - mn0), p11 = ex2(s[2*j+1][1] - mn0);
            float p12 = ex2(s[2*j+1][2] - mn1), p13 = ex2(s[2*j+1][3] - mn1);
            l0 += (p00 + p01) + (p10 + p11);
            l1 += (p02 + p03) + (p12 + p13);
            uint32_t ph[4];
            ph[0] = h2(p00, p01);
            ph[1] = h2(p02, p03);
            ph[2] = h2(p10, p11);
            ph[3] = h2(p12, p13);

            uint32_t vf[8][2];
#pragma unroll
            for (int dp = 0; dp < 4; dp++) {
                uint32_t d = swz((uint32_t)(j * 16 + (lane & 15)) * 128 + dp * 32 + (lane >> 4) * 16);
                asm volatile("ldmatrix.sync.aligned.m8n8.x4.trans.shared.b16 {%0,%1,%2,%3}, [%4];"
                             : "=r"(vf[2*dp][0]), "=r"(vf[2*dp][1]),
                               "=r"(vf[2*dp+1][0]), "=r"(vf[2*dp+1][1]) : "r"(sv + d));
            }
#pragma unroll
            for (int dt = 0; dt < 8; dt++)
                MMAH(ctx[dt], ph, vf[dt][0], vf[dt][1]);
        }
    }

    // ---- finalize: row sums, normalize, store ctx fp16 [M, DMODEL]
    l0 += __shfl_xor_sync(0xffffffffu, l0, 1);
    l0 += __shfl_xor_sync(0xffffffffu, l0, 2);
    l1 += __shfl_xor_sync(0xffffffffu, l1, 1);
    l1 += __shfl_xor_sync(0xffffffffu, l1, 2);
    float rinv0 = 1.f / l0, rinv1 = 1.f / l1;

    int qr = q0 + w * 16 + (lane >> 2);
    size_t row0 = ((size_t)b * SEQ + qr) * DMODEL;
    size_t row1 = row0 + 8 * DMODEL;
    int cbase = h * HDIM + (lane & 3) * 2;
#pragma unroll
    for (int dt = 0; dt < 8; dt++) {
        int cc = cbase + dt * 8;
        *(uint32_t*)&g_actxh[row0 + cc] = h2(ctx[dt][0] * rinv0, ctx[dt][1] * rinv0);
        *(uint32_t*)&g_actxh[row1 + cc] = h2(ctx[dt][2] * rinv1, ctx[dt][3] * rinv1);
    }
}

// ---------------------------------------------------------------------------
// Launch
// ---------------------------------------------------------------------------
extern "C" void kernel_launch(void* const* d_in, const int* in_sizes, int n_in,
                              void* d_out, int out_size)
{
    const float* x  = (const float*)d_in[0];
    const float* wq = (const float*)d_in[1];
    const float* bq = (const float*)d_in[2];
    const float* wk = (const float*)d_in[3];
    const float* bk = (const float*)d_in[4];
    const float* wv = (const float*)d_in[5];
    const float* bv = (const float*)d_in[6];
    const float* wo = (const float*)d_in[7];
    const float* bo = (const float*)d_in[8];
    float* out = (float*)d_out;
    (void)in_sizes; (void)n_in; (void)out_size;

    cudaFuncSetAttribute(qkv_tc_kernel, cudaFuncAttributeMaxDynamicSharedMemorySize, GEMM_SMEM);
    cudaFuncSetAttribute(out_tc_kernel, cudaFuncAttributeMaxDynamicSharedMemorySize, GEMM_SMEM);
    cudaFuncSetAttribute(attn_tc_kernel, cudaFuncAttributeMaxDynamicSharedMemorySize, ATT_SMEM);

    wsplit_kernel<<<dim3(32, 32, 4), 256>>>(wq, wk, wv, wo);
    split_kernel<<<MROWS * DMODEL / 4 / 256, 256>>>(x);
    qkv_tc_kernel<<<dim3(DMODEL / 128, MROWS / 128, 3), 256, GEMM_SMEM>>>(bq, bk, bv);
    attn_tc_kernel<<<dim3(SEQ / 128, NHEAD, BATCH), 256, ATT_SMEM>>>();
    out_tc_kernel<<<dim3(DMODEL / 128, MROWS / 128), 256, GEMM_SMEM>>>(bo, out);
}

// round 12
// speedup vs baseline: 8.7374x; 1.0308x over previous
#include <cuda_runtime.h>
#include <cuda_fp16.h>
#include <cstdint>

// ---------------------------------------------------------------------------
// Problem constants
// ---------------------------------------------------------------------------
#define BATCH   4
#define SEQ     2048
#define DMODEL  1024
#define NHEAD   16
#define HDIM    64
#define MROWS   (BATCH * SEQ)          // 8192
#define QSCALE  0.18033688011112042f   // log2(e) / sqrt(HDIM)

// ---------------------------------------------------------------------------
// Scratch (device globals: allocation-free, graph-capture safe). All fp16.
// ---------------------------------------------------------------------------
__device__ __half g_qh[MROWS * DMODEL];                 // [b,h,s,d] Q (pre-scaled)
__device__ __half g_kh[MROWS * DMODEL];                 // K
__device__ __half g_vh[MROWS * DMODEL];                 // V
__device__ __half g_ax[MROWS * DMODEL];                 // x fp16 [M, K]
__device__ __half g_actxh[MROWS * DMODEL];              // ctx fp16 [M, K]
__device__ __half g_bw[(size_t)3 * DMODEL * DMODEL];    // Wq/Wk/Wv^T fp16 [3][N, K]
__device__ __half g_bwo[(size_t)DMODEL * DMODEL];       // Wo^T fp16 [N, K]

// ---------------------------------------------------------------------------
// PTX helpers — arch-agnostic (sm_80-class) only: harness targets sm_103.
// ---------------------------------------------------------------------------
__device__ __forceinline__ uint32_t smem_u32(const void* p) {
    uint32_t a;
    asm("{ .reg .u64 t; cvta.to.shared.u64 t, %1; cvt.u32.u64 %0, t; }" : "=r"(a) : "l"(p));
    return a;
}
__device__ __forceinline__ void cp_async16(uint32_t dst, const void* src) {
    size_t g = __cvta_generic_to_global(src);
    asm volatile("cp.async.cg.shared.global [%0], [%1], 16;" :: "r"(dst), "l"(g) : "memory");
}
__device__ __forceinline__ void cp_commit() {
    asm volatile("cp.async.commit_group;" ::: "memory");
}
template <int N>
__device__ __forceinline__ void cp_wait() {
    asm volatile("cp.async.wait_group %0;" :: "n"(N) : "memory");
}
__device__ __forceinline__ uint32_t swz(uint32_t b) {   // Swizzle<3,4,3> on 128B rows
    return b ^ ((b >> 3) & 0x70);
}
__device__ __forceinline__ float ex2(float x) {
    float y;
    asm("ex2.approx.ftz.f32 %0, %1;" : "=f"(y) : "f"(x));
    return y;
}
__device__ __forceinline__ uint32_t h2(float a, float b) {
    __half2 h = __floats2half2_rn(a, b);
    return *reinterpret_cast<uint32_t*>(&h);
}

#define MMAH(acc, a, b0, b1)                                                         \
    asm volatile(                                                                    \
        "mma.sync.aligned.m16n8k16.row.col.f32.f16.f16.f32 "                         \
        "{%0,%1,%2,%3}, {%4,%5,%6,%7}, {%8,%9}, {%0,%1,%2,%3};"                      \
        : "+f"((acc)[0]), "+f"((acc)[1]), "+f"((acc)[2]), "+f"((acc)[3])             \
        : "r"((a)[0]), "r"((a)[1]), "r"((a)[2]), "r"((a)[3]), "r"(b0), "r"(b1))

#define LDSM4(r, addr)                                                               \
    asm volatile("ldmatrix.sync.aligned.m8n8.x4.shared.b16 {%0,%1,%2,%3}, [%4];"     \
                 : "=r"((r)[0]), "=r"((r)[1]), "=r"((r)[2]), "=r"((r)[3]) : "r"(addr))

// ---------------------------------------------------------------------------
// Conversions (host-input preprocessing)
// ---------------------------------------------------------------------------
__global__ void split_kernel(const float* __restrict__ in)   // x -> g_ax fp16
{
    int idx = blockIdx.x * 256 + threadIdx.x;     // one float4 per thread
    size_t off = (size_t)idx * 4;
    float4 v = *(const float4*)&in[off];
    uint2 hp;
    hp.x = h2(v.x, v.y);
    hp.y = h2(v.z, v.w);
    *(uint2*)&g_ax[off] = hp;
}

// Weight transpose + fp16 convert: z 0..2 -> g_bw, z==3 -> g_bwo.
__global__ void wsplit_kernel(const float* __restrict__ wq, const float* __restrict__ wk,
                              const float* __restrict__ wv, const float* __restrict__ wo)
{
    const float* W;
    switch (blockIdx.z) {
        case 0: W = wq; break; case 1: W = wk; break;
        case 2: W = wv; break; default: W = wo; break;
    }
    __shared__ float t[32][33];
    int k0 = blockIdx.x * 32, n0 = blockIdx.y * 32;
    int tx = threadIdx.x & 31, ty = threadIdx.x >> 5;
#pragma unroll
    for (int i = 0; i < 4; i++)
        t[ty + i * 8][tx] = W[(size_t)(k0 + ty + i * 8) * DMODEL + n0 + tx];
    __syncthreads();

    __half* out = (blockIdx.z < 3) ? (g_bw + (size_t)blockIdx.z * DMODEL * DMODEL) : g_bwo;
#pragma unroll
    for (int i = 0; i < 4; i++) {
        int nl = ty + i * 8;
        out[(size_t)(n0 + nl) * DMODEL + k0 + tx] = __float2half_rn(t[tx][nl]);
    }
}

// ---------------------------------------------------------------------------
// mma.sync fp16 GEMM, 128x128 CTA tile, BK=64, 3-stage cp.async, 2 CTAs/SM.
// MODE: 0 -> fp32 C+bias. 3 -> fp16 out, head-major [b,h,s,d], scaled.
// ---------------------------------------------------------------------------
#define STAGES 3
#define CHUNK_BYTES 32768
#define GEMM_SMEM (STAGES * CHUNK_BYTES)
#define KDIM DMODEL
#define NCH (KDIM / 64)    // 16

template <int MODE>
__device__ __forceinline__ void gemm_mma_body(const uint16_t* __restrict__ A,
                                              const uint16_t* __restrict__ B,
                                              const float* __restrict__ bias,
                                              float* __restrict__ C,
                                              uint16_t* __restrict__ Oh,
                                              float scale)
{
    extern __shared__ char smem[];
    const uint32_t sbase = smem_u32(smem);
    const int tid  = threadIdx.x;
    const int lane = tid & 31;
    const int w    = tid >> 5;
    const int wm   = w & 1;
    const int wn   = w >> 1;
    const int m0   = blockIdx.y * 128;
    const int n0   = blockIdx.x * 128;

    const uint16_t* Abase = A + (size_t)m0 * KDIM;
    const uint16_t* Bbase = B + (size_t)n0 * KDIM;

    const int r0 = tid >> 3;
    const int u  = tid & 7;

    auto load_chunk = [&](int c) {
        uint32_t so = sbase + (uint32_t)(c % STAGES) * CHUNK_BYTES;
        const uint16_t* as = Abase + (size_t)r0 * KDIM + c * 64 + u * 8;
        const uint16_t* bs = Bbase + (size_t)r0 * KDIM + c * 64 + u * 8;
#pragma unroll
        for (int i = 0; i < 4; i++) {
            uint32_t d = swz((uint32_t)(i * 32 + r0) * 128 + u * 16);
            cp_async16(so + d,         as + (size_t)i * 32 * KDIM);
            cp_async16(so + 16384 + d, bs + (size_t)i * 32 * KDIM);
        }
        cp_commit();
    };

    float acc[4][4][4];
#pragma unroll
    for (int mi = 0; mi < 4; mi++)
#pragma unroll
        for (int ni = 0; ni < 4; ni++)
#pragma unroll
            for (int r = 0; r < 4; r++) acc[mi][ni][r] = 0.f;

    load_chunk(0);
    load_chunk(1);

    for (int c = 0; c < NCH; c++) {
        cp_wait<1>();
        __syncthreads();
        if (c + 2 < NCH) load_chunk(c + 2);

        uint32_t sa = sbase + (uint32_t)(c % STAGES) * CHUNK_BYTES;
        uint32_t sb = sa + 16384;

#pragma unroll
        for (int ks = 0; ks < 4; ks++) {
            uint32_t a[4][4], b[4][2];
#pragma unroll
            for (int mi = 0; mi < 4; mi++) {
                int r = wm * 64 + mi * 16 + (lane & 15);
                uint32_t addr = sa + swz((uint32_t)r * 128 + ks * 32 + (lane >> 4) * 16);
                LDSM4(a[mi], addr);
            }
#pragma unroll
            for (int nj = 0; nj < 2; nj++) {
                int n = wn * 32 + nj * 16 + (lane >> 4) * 8 + (lane & 7);
                uint32_t addr = sb + swz((uint32_t)n * 128 + ks * 32 + ((lane >> 3) & 1) * 16);
                asm volatile("ldmatrix.sync.aligned.m8n8.x4.shared.b16 {%0,%1,%2,%3}, [%4];"
                             : "=r"(b[nj * 2][0]), "=r"(b[nj * 2][1]),
                               "=r"(b[nj * 2 + 1][0]), "=r"(b[nj * 2 + 1][1])
                             : "r"(addr));
            }
#pragma unroll
            for (int mi = 0; mi < 4; mi++)
#pragma unroll
                for (int ni = 0; ni < 4; ni++)
                    MMAH(acc[mi][ni], a[mi], b[ni][0], b[ni][1]);
        }
    }

    const int mrow = m0 + wm * 64 + (lane >> 2);
    const int ncol = n0 + wn * 32 + (lane & 3) * 2;
#pragma unroll
    for (int mi = 0; mi < 4; mi++) {
        int r = mrow + mi * 16;
#pragma unroll
        for (int ni = 0; ni < 4; ni++) {
            int cc = ncol + ni * 8;
            float b0 = bias[cc], b1 = bias[cc + 1];
            float v0 = acc[mi][ni][0] + b0, v1 = acc[mi][ni][1] + b1;
            float v2 = acc[mi][ni][2] + b0, v3 = acc[mi][ni][3] + b1;
            if (MODE == 0) {
                *(float2*)&C[(size_t)r * DMODEL + cc]       = make_float2(v0, v1);
                *(float2*)&C[(size_t)(r + 8) * DMODEL + cc] = make_float2(v2, v3);
            } else {   // MODE 3: fp16, head-major
                v0 *= scale; v1 *= scale; v2 *= scale; v3 *= scale;
                int bb = r >> 11, hh = cc >> 6, dd = cc & 63;
                size_t off0 = (((size_t)bb * NHEAD + hh) * SEQ + (r & 2047)) * HDIM + dd;
                size_t off1 = off0 + 8 * HDIM;
                *(uint32_t*)&Oh[off0] = h2(v0, v1);
                *(uint32_t*)&Oh[off1] = h2(v2, v3);
            }
        }
    }
}

__global__ __launch_bounds__(256, 2) void qkv_tc_kernel(
    const float* __restrict__ bq, const float* __restrict__ bk, const float* __restrict__ bv)
{
    if (blockIdx.z == 0)
        gemm_mma_body<3>((const uint16_t*)g_ax, (const uint16_t*)g_bw,
                         bq, nullptr, (uint16_t*)g_qh, QSCALE);
    else if (blockIdx.z == 1)
        gemm_mma_body<3>((const uint16_t*)g_ax,
                         (const uint16_t*)(g_bw + (size_t)DMODEL * DMODEL),
                         bk, nullptr, (uint16_t*)g_kh, 1.f);
    else
        gemm_mma_body<3>((const uint16_t*)g_ax,
                         (const uint16_t*)(g_bw + (size_t)2 * DMODEL * DMODEL),
                         bv, nullptr, (uint16_t*)g_vh, 1.f);
}

__global__ __launch_bounds__(256, 2) void out_tc_kernel(
    const float* __restrict__ bo, float* __restrict__ out)
{
    gemm_mma_body<0>((const uint16_t*)g_actxh, (const uint16_t*)g_bwo,
                     bo, out, nullptr, 1.f);
}

// ---------------------------------------------------------------------------
// Tensor-core causal flash attention. 128 threads (4 warps), q-tile 64,
// k-tile 64, 4 CTAs/SM for latency hiding.
// Smem: Q (8KB) + 2 x (Kh|Vh) (2x16KB) = 40KB.
// ---------------------------------------------------------------------------
#define ATT_SMEM 40960

__global__ __launch_bounds__(128, 4) void attn_tc_kernel()
{
    extern __shared__ char smem[];
    const uint32_t sb = smem_u32(smem);
    const int tid  = threadIdx.x;
    const int lane = tid & 31;
    const int w    = tid >> 5;                            // 0..3
    const int qt   = (int)(gridDim.x - 1 - blockIdx.x);   // heavy tiles first
    const int h    = blockIdx.y, b = blockIdx.z;
    const int q0   = qt * 64;
    const int nkt  = qt + 1;
    const size_t bh = ((size_t)b * NHEAD + h) * SEQ * HDIM;
    const __half *Qhp = g_qh + bh;
    const __half *Khp = g_kh + bh;
    const __half *Vhp = g_vh + bh;

    const int u   = tid & 7;
    const int r16 = tid >> 3;        // 0..15

    // ---- stage Q (q0..q0+63): 64 rows x 8 units / 128 thr = 4 per thread
#pragma unroll
    for (int i = 0; i < 4; i++) {
        int row = r16 + 16 * i;
        uint32_t d = swz((uint32_t)row * 128 + u * 16);
        cp_async16(sb + d, Qhp + (size_t)(q0 + row) * HDIM + u * 8);
    }
    cp_commit();

    auto load_kv = [&](int kt) {
        uint32_t so = sb + 8192 + (uint32_t)(kt & 1) * 16384;
        int kbase = kt * 64;
#pragma unroll
        for (int i = 0; i < 4; i++) {
            int row = r16 + 16 * i;
            uint32_t d = swz((uint32_t)row * 128 + u * 16);
            size_t g = (size_t)(kbase + row) * HDIM + u * 8;
            cp_async16(so + d,        Khp + g);
            cp_async16(so + 8192 + d, Vhp + g);
        }
        cp_commit();
    };
    load_kv(0);
    cp_wait<0>();
    __syncthreads();

    // ---- resident Q fragments (warp w owns rows w*16..w*16+15)
    uint32_t qh[4][4];
#pragma unroll
    for (int ks = 0; ks < 4; ks++) {
        uint32_t d = swz((uint32_t)(w * 16 + (lane & 15)) * 128 + ks * 32 + (lane >> 4) * 16);
        LDSM4(qh[ks], sb + d);
    }

    float ctx[8][4];
#pragma unroll
    for (int dt = 0; dt < 8; dt++)
#pragma unroll
        for (int r = 0; r < 4; r++) ctx[dt][r] = 0.f;
    float m0 = -1e30f, m1 = -1e30f, l0 = 0.f, l1 = 0.f;

    for (int kt = 0; kt < nkt; kt++) {
        cp_wait<0>();
        __syncthreads();
        if (kt + 1 < nkt) load_kv(kt + 1);
        const uint32_t sk = sb + 8192 + (uint32_t)(kt & 1) * 16384;

        // ---- S = Q K^T  (single fp16 term)
        float s[8][4];
#pragma unroll
        for (int nt = 0; nt < 8; nt++) {
            s[nt][0] = s[nt][1] = s[nt][2] = s[nt][3] = 0.f;
            uint32_t kh[4][2];
#pragma unroll
            for (int hf = 0; hf < 2; hf++) {
                uint32_t d = swz((uint32_t)(nt * 8 + (lane & 7)) * 128 + hf * 64 + (lane >> 3) * 16);
                asm volatile("ldmatrix.sync.aligned.m8n8.x4.shared.b16 {%0,%1,%2,%3}, [%4];"
                             : "=r"(kh[2*hf][0]), "=r"(kh[2*hf][1]),
                               "=r"(kh[2*hf+1][0]), "=r"(kh[2*hf+1][1]) : "r"(sk + d));
            }
#pragma unroll
            for (int ks = 0; ks < 4; ks++)
                MMAH(s[nt], qh[ks], kh[ks][0], kh[ks][1]);
        }

        // ---- causal mask (only the final k-tile crosses the diagonal)
        if (kt == nkt - 1) {
            int qr = q0 + w * 16 + (lane >> 2);
#pragma unroll
            for (int nt = 0; nt < 8; nt++) {
                int kc = kt * 64 + nt * 8 + (lane & 3) * 2;
                if (kc     > qr)     s[nt][0] = -1e30f;
                if (kc + 1 > qr)     s[nt][1] = -1e30f;
                if (kc     > qr + 8) s[nt][2] = -1e30f;
                if (kc + 1 > qr + 8) s[nt][3] = -1e30f;
            }
        }

        // ---- online softmax (exp2 domain)
        float mx0 = -1e30f, mx1 = -1e30f;
#pragma unroll
        for (int nt = 0; nt < 8; nt++) {
            mx0 = fmaxf(mx0, fmaxf(s[nt][0], s[nt][1]));
            mx1 = fmaxf(mx1, fmaxf(s[nt][2], s[nt][3]));
        }
        mx0 = fmaxf(mx0, __shfl_xor_sync(0xffffffffu, mx0, 1));
        mx0 = fmaxf(mx0, __shfl_xor_sync(0xffffffffu, mx0, 2));
        mx1 = fmaxf(mx1, __shfl_xor_sync(0xffffffffu, mx1, 1));
        mx1 = fmaxf(mx1, __shfl_xor_sync(0xffffffffu, mx1, 2));
        float mn0 = fmaxf(m0, mx0), mn1 = fmaxf(m1, mx1);
        float c0 = ex2(m0 - mn0), c1 = ex2(m1 - mn1);
        m0 = mn0; m1 = mn1;
        l0 *= c0; l1 *= c1;
#pragma unroll
        for (int dt = 0; dt < 8; dt++) {
            ctx[dt][0] *= c0; ctx[dt][1] *= c0;
            ctx[dt][2] *= c1; ctx[dt][3] *= c1;
        }

        // ---- per-j: exp, pack P fp16, PV = P Vh
        const uint32_t sv = sk + 8192;
#pragma unroll
        for (int j = 0; j < 4; j++) {
            float p00 = ex2(s[2*j][0] - mn0),   p01 = ex2(s[2*j][1] - mn0);
            float p02 = ex2(s[2*j][2] - mn1),   p03 = ex2(s[2*j][3] - mn1);
            float p10 = ex2(s[2*j+1][0] - mn0), p11 = ex2(s[2*j+1][1] - mn0);
            float p12 = ex2(s[2*j+1][2] - mn1), p13 = ex2(s[2*j+1][3] - mn1);
            l0 += (p00 + p01) + (p10 + p11);
            l1 += (p02 + p03) + (p12 + p13);
            uint32_t ph[4];
            ph[0] = h2(p00, p01);
            ph[1] = h2(p02, p03);
            ph[2] = h2(p10, p11);
            ph[3] = h2(p12, p13);

            uint32_t vf[8][2];
#pragma unroll
            for (int dp = 0; dp < 4; dp++) {
                uint32_t d = swz((uint32_t)(j * 16 + (lane & 15)) * 128 + dp * 32 + (lane >> 4) * 16);
                asm volatile("ldmatrix.sync.aligned.m8n8.x4.trans.shared.b16 {%0,%1,%2,%3}, [%4];"
                             : "=r"(vf[2*dp][0]), "=r"(vf[2*dp][1]),
                               "=r"(vf[2*dp+1][0]), "=r"(vf[2*dp+1][1]) : "r"(sv + d));
            }
#pragma unroll
            for (int dt = 0; dt < 8; dt++)
                MMAH(ctx[dt], ph, vf[dt][0], vf[dt][1]);
        }
    }

    // ---- finalize: row sums, normalize, store ctx fp16 [M, DMODEL]
    l0 += __shfl_xor_sync(0xffffffffu, l0, 1);
    l0 += __shfl_xor_sync(0xffffffffu, l0, 2);
    l1 += __shfl_xor_sync(0xffffffffu, l1, 1);
    l1 += __shfl_xor_sync(0xffffffffu, l1, 2);
    float rinv0 = 1.f / l0, rinv1 = 1.f / l1;

    int qr = q0 + w * 16 + (lane >> 2);
    size_t row0 = ((size_t)b * SEQ + qr) * DMODEL;
    size_t row1 = row0 + 8 * DMODEL;
    int cbase = h * HDIM + (lane & 3) * 2;
#pragma unroll
    for (int dt = 0; dt < 8; dt++) {
        int cc = cbase + dt * 8;
        *(uint32_t*)&g_actxh[row0 + cc] = h2(ctx[dt][0] * rinv0, ctx[dt][1] * rinv0);
        *(uint32_t*)&g_actxh[row1 + cc] = h2(ctx[dt][2] * rinv1, ctx[dt][3] * rinv1);
    }
}

// ---------------------------------------------------------------------------
// Launch
// ---------------------------------------------------------------------------
extern "C" void kernel_launch(void* const* d_in, const int* in_sizes, int n_in,
                              void* d_out, int out_size)
{
    const float* x  = (const float*)d_in[0];
    const float* wq = (const float*)d_in[1];
    const float* bq = (const float*)d_in[2];
    const float* wk = (const float*)d_in[3];
    const float* bk = (const float*)d_in[4];
    const float* wv = (const float*)d_in[5];
    const float* bv = (const float*)d_in[6];
    const float* wo = (const float*)d_in[7];
    const float* bo = (const float*)d_in[8];
    float* out = (float*)d_out;
    (void)in_sizes; (void)n_in; (void)out_size;

    cudaFuncSetAttribute(qkv_tc_kernel, cudaFuncAttributeMaxDynamicSharedMemorySize, GEMM_SMEM);
    cudaFuncSetAttribute(out_tc_kernel, cudaFuncAttributeMaxDynamicSharedMemorySize, GEMM_SMEM);
    cudaFuncSetAttribute(attn_tc_kernel, cudaFuncAttributeMaxDynamicSharedMemorySize, ATT_SMEM);

    wsplit_kernel<<<dim3(32, 32, 4), 256>>>(wq, wk, wv, wo);
    split_kernel<<<MROWS * DMODEL / 4 / 256, 256>>>(x);
    qkv_tc_kernel<<<dim3(DMODEL / 128, MROWS / 128, 3), 256, GEMM_SMEM>>>(bq, bk, bv);
    attn_tc_kernel<<<dim3(SEQ / 64, NHEAD, BATCH), 128, ATT_SMEM>>>();
    out_tc_kernel<<<dim3(DMODEL / 128, MROWS / 128), 256, GEMM_SMEM>>>(bo, out);
}